// round 4
// baseline (speedup 1.0000x reference)
#include <cuda_runtime.h>
#include <math.h>

#define BB 32
#define TT 512
#define DD 1024
#define VOCAB 50257
#define SS 16
#define BT (BB*TT)
#define H2 2048

// ---------------- scratch (static device globals; no allocation) ----------------
__device__ float g_act[(size_t)BT * H2];      // relu(h@W1+b1)       128 MB
__device__ float g_x[(size_t)BT * DD];        // h + ff               64 MB
__device__ float g_hidden[(size_t)BT * DD];   // LN output            64 MB
__device__ float g_slot[BT];                  // slot importance
__device__ float g_wbar[DD];                  // mean_s wg_w
__device__ float g_query[BB * DD];            // hiddens[:, -1]
__device__ float g_mem[BB * SS * DD];         // assembled memory
__device__ float g_dl[(size_t)BB * VOCAB];    // direct logits
__device__ float g_use[BB];                   // use_mem flag (0/1)
__device__ float g_q[BB * DD];                // query @ rp_w + rp_b
__device__ float g_ctx[BB * DD];              // blended context

__device__ __forceinline__ float warp_sum(float v) {
#pragma unroll
    for (int o = 16; o > 0; o >>= 1) v += __shfl_xor_sync(0xffffffffu, v, o);
    return v;
}

// ---------------- K0: wbar = mean_s wg_w ----------------
__global__ void wbar_kernel(const float* __restrict__ wg_w) {
    int d = blockIdx.x * blockDim.x + threadIdx.x;
    if (d < DD) {
        float s = 0.f;
#pragma unroll
        for (int j = 0; j < SS; j++) s += wg_w[d * SS + j];
        g_wbar[d] = s * (1.f / 16.f);
    }
}

// ---------------- K1: act = relu(embed[seq] @ W1 + b1)  M=16384 N=2048 K=1024 ----------------
__global__ __launch_bounds__(256) void gemm1_kernel(
    const int* __restrict__ seq, const float* __restrict__ embed,
    const float* __restrict__ W1, const float* __restrict__ b1) {
    __shared__ float As[16][132];
    __shared__ float Bs[16][128];
    __shared__ int srow[128];
    const int tid = threadIdx.x;
    const int n0 = blockIdx.x * 128;
    const int row0 = blockIdx.y * 128;
    if (tid < 128) srow[tid] = seq[row0 + tid] * DD;
    __syncthreads();
    const int tx = tid & 15, ty = tid >> 4;
    float acc[8][8];
#pragma unroll
    for (int i = 0; i < 8; i++)
#pragma unroll
        for (int j = 0; j < 8; j++) acc[i][j] = 0.f;

    for (int k0 = 0; k0 < DD; k0 += 16) {
#pragma unroll
        for (int l = 0; l < 2; l++) {
            int f4 = tid + l * 256;
            int r = f4 >> 2, kq = f4 & 3;
            float4 v = *(const float4*)(embed + (size_t)srow[r] + k0 + kq * 4);
            As[kq * 4 + 0][r] = v.x; As[kq * 4 + 1][r] = v.y;
            As[kq * 4 + 2][r] = v.z; As[kq * 4 + 3][r] = v.w;
        }
#pragma unroll
        for (int l = 0; l < 2; l++) {
            int f4 = tid + l * 256;
            int kr = f4 >> 5, c4 = (f4 & 31) * 4;
            *(float4*)&Bs[kr][c4] =
                *(const float4*)(W1 + (size_t)(k0 + kr) * H2 + n0 + c4);
        }
        __syncthreads();
#pragma unroll
        for (int k = 0; k < 16; k++) {
            float a[8], bv[8];
#pragma unroll
            for (int i = 0; i < 8; i++) a[i] = As[k][ty * 8 + i];
#pragma unroll
            for (int j = 0; j < 8; j++) bv[j] = Bs[k][tx * 8 + j];
#pragma unroll
            for (int i = 0; i < 8; i++)
#pragma unroll
                for (int j = 0; j < 8; j++) acc[i][j] += a[i] * bv[j];
        }
        __syncthreads();
    }
    float bias[8];
#pragma unroll
    for (int j = 0; j < 8; j++) bias[j] = b1[n0 + tx * 8 + j];
#pragma unroll
    for (int i = 0; i < 8; i++) {
        size_t r = (size_t)(row0 + ty * 8 + i);
        float* op = g_act + r * H2 + n0 + tx * 8;
        float4 o0, o1;
        o0.x = fmaxf(acc[i][0] + bias[0], 0.f);
        o0.y = fmaxf(acc[i][1] + bias[1], 0.f);
        o0.z = fmaxf(acc[i][2] + bias[2], 0.f);
        o0.w = fmaxf(acc[i][3] + bias[3], 0.f);
        o1.x = fmaxf(acc[i][4] + bias[4], 0.f);
        o1.y = fmaxf(acc[i][5] + bias[5], 0.f);
        o1.z = fmaxf(acc[i][6] + bias[6], 0.f);
        o1.w = fmaxf(acc[i][7] + bias[7], 0.f);
        *(float4*)op = o0;
        *(float4*)(op + 4) = o1;
    }
}

// ---------------- K2: x = act @ W2 + b2 + h   M=16384 N=1024 K=2048 ----------------
__global__ __launch_bounds__(256) void gemm2_kernel(
    const int* __restrict__ seq, const float* __restrict__ embed,
    const float* __restrict__ W2, const float* __restrict__ b2) {
    __shared__ float As[16][132];
    __shared__ float Bs[16][128];
    __shared__ int srow[128];
    const int tid = threadIdx.x;
    const int n0 = blockIdx.x * 128;
    const int row0 = blockIdx.y * 128;
    if (tid < 128) srow[tid] = seq[row0 + tid] * DD;
    __syncthreads();
    const int tx = tid & 15, ty = tid >> 4;
    float acc[8][8];
#pragma unroll
    for (int i = 0; i < 8; i++)
#pragma unroll
        for (int j = 0; j < 8; j++) acc[i][j] = 0.f;

    for (int k0 = 0; k0 < H2; k0 += 16) {
#pragma unroll
        for (int l = 0; l < 2; l++) {
            int f4 = tid + l * 256;
            int r = f4 >> 2, kq = f4 & 3;
            float4 v = *(const float4*)(g_act + (size_t)(row0 + r) * H2 + k0 + kq * 4);
            As[kq * 4 + 0][r] = v.x; As[kq * 4 + 1][r] = v.y;
            As[kq * 4 + 2][r] = v.z; As[kq * 4 + 3][r] = v.w;
        }
#pragma unroll
        for (int l = 0; l < 2; l++) {
            int f4 = tid + l * 256;
            int kr = f4 >> 5, c4 = (f4 & 31) * 4;
            *(float4*)&Bs[kr][c4] =
                *(const float4*)(W2 + (size_t)(k0 + kr) * DD + n0 + c4);
        }
        __syncthreads();
#pragma unroll
        for (int k = 0; k < 16; k++) {
            float a[8], bv[8];
#pragma unroll
            for (int i = 0; i < 8; i++) a[i] = As[k][ty * 8 + i];
#pragma unroll
            for (int j = 0; j < 8; j++) bv[j] = Bs[k][tx * 8 + j];
#pragma unroll
            for (int i = 0; i < 8; i++)
#pragma unroll
                for (int j = 0; j < 8; j++) acc[i][j] += a[i] * bv[j];
        }
        __syncthreads();
    }
    float bias[8];
#pragma unroll
    for (int j = 0; j < 8; j++) bias[j] = b2[n0 + tx * 8 + j];
#pragma unroll
    for (int i = 0; i < 8; i++) {
        int lr = ty * 8 + i;
        size_t r = (size_t)(row0 + lr);
        const float* hp = embed + (size_t)srow[lr] + n0 + tx * 8;
        float* op = g_x + r * DD + n0 + tx * 8;
        float4 h0 = *(const float4*)hp;
        float4 h1 = *(const float4*)(hp + 4);
        float4 o0, o1;
        o0.x = acc[i][0] + bias[0] + h0.x;
        o0.y = acc[i][1] + bias[1] + h0.y;
        o0.z = acc[i][2] + bias[2] + h0.z;
        o0.w = acc[i][3] + bias[3] + h0.w;
        o1.x = acc[i][4] + bias[4] + h1.x;
        o1.y = acc[i][5] + bias[5] + h1.y;
        o1.z = acc[i][6] + bias[6] + h1.z;
        o1.w = acc[i][7] + bias[7] + h1.w;
        *(float4*)op = o0;
        *(float4*)(op + 4) = o1;
    }
}

// ---------------- K3: LayerNorm + slot_imp + query extraction ----------------
__global__ __launch_bounds__(256) void ln_kernel(
    const float* __restrict__ ln_g, const float* __restrict__ ln_b) {
    const int token = blockIdx.x;
    const int tid = threadIdx.x;
    const float4 x4 = *(const float4*)(g_x + (size_t)token * DD + tid * 4);
    float s = x4.x + x4.y + x4.z + x4.w;
    float sq = x4.x * x4.x + x4.y * x4.y + x4.z * x4.z + x4.w * x4.w;
    __shared__ float sh1[8], sh2[8];
    const int w = tid >> 5, l = tid & 31;
    s = warp_sum(s);
    sq = warp_sum(sq);
    if (l == 0) { sh1[w] = s; sh2[w] = sq; }
    __syncthreads();
    float ts = 0.f, tq = 0.f;
#pragma unroll
    for (int i = 0; i < 8; i++) { ts += sh1[i]; tq += sh2[i]; }
    const float mu = ts * (1.f / 1024.f);
    const float var = tq * (1.f / 1024.f) - mu * mu;
    const float rstd = rsqrtf(var + 1e-5f);
    const float4 g4 = *(const float4*)(ln_g + tid * 4);
    const float4 b4 = *(const float4*)(ln_b + tid * 4);
    float4 h4;
    h4.x = (x4.x - mu) * rstd * g4.x + b4.x;
    h4.y = (x4.y - mu) * rstd * g4.y + b4.y;
    h4.z = (x4.z - mu) * rstd * g4.z + b4.z;
    h4.w = (x4.w - mu) * rstd * g4.w + b4.w;
    *(float4*)(g_hidden + (size_t)token * DD + tid * 4) = h4;
    const float4 wb = *(const float4*)(g_wbar + tid * 4);
    float wd = h4.x * wb.x + h4.y * wb.y + h4.z * wb.z + h4.w * wb.w;
    wd = warp_sum(wd);
    __syncthreads();
    if (l == 0) sh1[w] = wd;
    __syncthreads();
    if (tid == 0) {
        float t2 = 0.f;
#pragma unroll
        for (int i = 0; i < 8; i++) t2 += sh1[i];
        g_slot[token] = t2;   // constant offset (mean wg_b) omitted: rank-invariant
    }
    if ((token & (TT - 1)) == TT - 1) {
        int bidx = token >> 9;
        *(float4*)(g_query + bidx * DD + tid * 4) = h4;
    }
}

// ---------------- K4: top-k selection + memory assembly ----------------
__global__ __launch_bounds__(256) void select_kernel(const float* __restrict__ memory) {
    const int b = blockIdx.x, tid = threadIdx.x;
    __shared__ float imp[512];
    __shared__ int idx[6];
    for (int t = tid; t < TT - 1; t += 256) imp[t] = g_slot[b * TT + t];
    __syncthreads();
    if (tid == 0) {
#pragma unroll
        for (int r = 0; r < 4; r++) {       // fwd top-4 (desc, stable)
            float best = -1e30f; int bi = 0;
            for (int t = 0; t < TT - 1; t++)
                if (imp[t] > best) { best = imp[t]; bi = t; }
            idx[r] = bi;
            imp[bi] = -3.0e38f;
        }
#pragma unroll
        for (int r = 0; r < 2; r++) {       // rev top-2 over first 8, masked
            float best = -1e30f; int bi = 0;
            for (int t = 0; t < 8; t++)
                if (imp[t] > best) { best = imp[t]; bi = t; }
            idx[4 + r] = bi;
            imp[bi] = -3.0e38f;
        }
    }
    __syncthreads();
    for (int s = 0; s < SS; s++) {
        const float* src = (s < 6)
            ? (g_hidden + (size_t)(b * TT + idx[s]) * DD)
            : (memory + (size_t)s * DD);
        *(float4*)(g_mem + (size_t)(b * SS + s) * DD + tid * 4) =
            *(const float4*)(src + tid * 4);
    }
}

// ---------------- K5/K9: vocab GEMM  out[b][v] = Q[b]·W[:,v] + bias[v] ----------------
// mode 0: Q=g_query -> g_dl ; mode 1: Q=g_ctx -> extout
__global__ __launch_bounds__(256) void logits_kernel(
    const float* __restrict__ W, const float* __restrict__ bias,
    float* __restrict__ extout, int mode) {
    const float* __restrict__ Q = mode ? g_ctx : g_query;
    float* __restrict__ out = mode ? extout : g_dl;
    const int tid = threadIdx.x;
    const int tv = tid & 31, bg = tid >> 5;
    const int v0 = blockIdx.x * 128 + tv * 4;
    __shared__ float Qs[32][128];
    float acc[4][4];
#pragma unroll
    for (int u = 0; u < 4; u++)
#pragma unroll
        for (int j = 0; j < 4; j++) acc[u][j] = 0.f;
    const bool full = (v0 + 4 <= VOCAB);

    for (int k0 = 0; k0 < DD; k0 += 128) {
#pragma unroll
        for (int l2 = 0; l2 < 4; l2++) {
            int f4 = tid + l2 * 256;
            int bb = f4 >> 5, dq = f4 & 31;
            *(float4*)&Qs[bb][dq * 4] =
                *(const float4*)(Q + bb * DD + k0 + dq * 4);
        }
        __syncthreads();
        if (full) {
            const float* wp = W + (size_t)k0 * VOCAB + v0;
#pragma unroll 2
            for (int d = 0; d < 128; d++) {
                const float w0 = wp[0], w1 = wp[1], w2 = wp[2], w3 = wp[3];
#pragma unroll
                for (int u = 0; u < 4; u++) {
                    const float q = Qs[bg * 4 + u][d];
                    acc[u][0] += q * w0; acc[u][1] += q * w1;
                    acc[u][2] += q * w2; acc[u][3] += q * w3;
                }
                wp += VOCAB;
            }
        } else if (v0 < VOCAB) {
            for (int d = 0; d < 128; d++) {
                const float* wp = W + (size_t)(k0 + d) * VOCAB;
#pragma unroll
                for (int j = 0; j < 4; j++) {
                    int v = v0 + j;
                    if (v < VOCAB) {
                        const float wv = wp[v];
#pragma unroll
                        for (int u = 0; u < 4; u++)
                            acc[u][j] += Qs[bg * 4 + u][d] * wv;
                    }
                }
            }
        }
        __syncthreads();
    }
#pragma unroll
    for (int u = 0; u < 4; u++) {
        const int bidx = bg * 4 + u;
#pragma unroll
        for (int j = 0; j < 4; j++) {
            int v = v0 + j;
            if (v < VOCAB) out[(size_t)bidx * VOCAB + v] = acc[u][j] + bias[v];
        }
    }
}

// ---------------- K6: conf = 1/sumexp(direct_logits - max) -> use_mem flag ----------------
__global__ __launch_bounds__(256) void conf_kernel() {
    const int b = blockIdx.x, tid = threadIdx.x;
    const float* row = g_dl + (size_t)b * VOCAB;
    float m = -3.0e38f;
    for (int v = tid; v < VOCAB; v += 256) m = fmaxf(m, row[v]);
    __shared__ float sh[8];
#pragma unroll
    for (int o = 16; o > 0; o >>= 1) m = fmaxf(m, __shfl_xor_sync(0xffffffffu, m, o));
    if ((tid & 31) == 0) sh[tid >> 5] = m;
    __syncthreads();
    float bm = sh[0];
#pragma unroll
    for (int i = 1; i < 8; i++) bm = fmaxf(bm, sh[i]);
    float ssum = 0.f;
    for (int v = tid; v < VOCAB; v += 256) ssum += expf(row[v] - bm);
    ssum = warp_sum(ssum);
    __syncthreads();
    if ((tid & 31) == 0) sh[tid >> 5] = ssum;
    __syncthreads();
    if (tid == 0) {
        float t = 0.f;
#pragma unroll
        for (int i = 0; i < 8; i++) t += sh[i];
        const float conf = 1.f / t;
        g_use[b] = (conf < 0.8f) ? 1.f : 0.f;
    }
}

// ---------------- K7: q = query @ rp_w + rp_b ----------------
__global__ __launch_bounds__(256) void rp_kernel(
    const float* __restrict__ rp_w, const float* __restrict__ rp_b) {
    const int b = blockIdx.x, tid = threadIdx.x;
    __shared__ __align__(16) float qs[DD];
    *(float4*)&qs[tid * 4] = *(const float4*)(g_query + b * DD + tid * 4);
    __syncthreads();
    float acc0 = 0.f, acc1 = 0.f, acc2 = 0.f, acc3 = 0.f;
    for (int d = 0; d < DD; d++) {
        const float q = qs[d];
        const float* wr = rp_w + (size_t)d * DD + tid;
        acc0 += q * wr[0];
        acc1 += q * wr[256];
        acc2 += q * wr[512];
        acc3 += q * wr[768];
    }
    g_q[b * DD + tid +   0] = acc0 + rp_b[tid +   0];
    g_q[b * DD + tid + 256] = acc1 + rp_b[tid + 256];
    g_q[b * DD + tid + 512] = acc2 + rp_b[tid + 512];
    g_q[b * DD + tid + 768] = acc3 + rp_b[tid + 768];
}

// ---------------- K8: scores -> softmax -> ctx -> blend ----------------
__global__ __launch_bounds__(256) void attn_kernel() {
    const int b = blockIdx.x, tid = threadIdx.x;
    __shared__ __align__(16) float qs[DD];
    __shared__ float sh[8];
    __shared__ float scores[SS];
    __shared__ float attn[SS];
    *(float4*)&qs[tid * 4] = *(const float4*)(g_q + b * DD + tid * 4);
    __syncthreads();
    for (int s = 0; s < SS; s++) {
        const float4 m4 = *(const float4*)(g_mem + (size_t)(b * SS + s) * DD + tid * 4);
        const float4 q4 = *(const float4*)&qs[tid * 4];
        float p = m4.x * q4.x + m4.y * q4.y + m4.z * q4.z + m4.w * q4.w;
        p = warp_sum(p);
        if ((tid & 31) == 0) sh[tid >> 5] = p;
        __syncthreads();
        if (tid == 0) {
            float t = 0.f;
#pragma unroll
            for (int i = 0; i < 8; i++) t += sh[i];
            scores[s] = t;
        }
        __syncthreads();
    }
    if (tid == 0) {
        float m = scores[0];
        for (int s = 1; s < SS; s++) m = fmaxf(m, scores[s]);
        float sum = 0.f;
        for (int s = 0; s < SS; s++) { float e = expf(scores[s] - m); attn[s] = e; sum += e; }
        const float inv = 1.f / sum;
        for (int s = 0; s < SS; s++) attn[s] *= inv;
    }
    __syncthreads();
    float c0 = 0.f, c1 = 0.f, c2 = 0.f, c3 = 0.f;
#pragma unroll
    for (int s = 0; s < SS; s++) {
        const float a = attn[s];
        const float4 m4 = *(const float4*)(g_mem + (size_t)(b * SS + s) * DD + tid * 4);
        c0 += a * m4.x; c1 += a * m4.y; c2 += a * m4.z; c3 += a * m4.w;
    }
    const float use = g_use[b];
    const float4 qv = *(const float4*)(g_query + b * DD + tid * 4);
    float4 o;
    o.x = c0 * use + qv.x * (1.f - use);
    o.y = c1 * use + qv.y * (1.f - use);
    o.z = c2 * use + qv.z * (1.f - use);
    o.w = c3 * use + qv.w * (1.f - use);
    *(float4*)(g_ctx + b * DD + tid * 4) = o;
}

// ---------------- launch ----------------
extern "C" void kernel_launch(void* const* d_in, const int* in_sizes, int n_in,
                              void* d_out, int out_size) {
    const int*   seq    = (const int*)  d_in[0];
    const float* embed  = (const float*)d_in[1];
    const float* ff_w1  = (const float*)d_in[2];
    const float* ff_b1  = (const float*)d_in[3];
    const float* ff_w2  = (const float*)d_in[4];
    const float* ff_b2  = (const float*)d_in[5];
    const float* ln_g   = (const float*)d_in[6];
    const float* ln_b   = (const float*)d_in[7];
    const float* wg_w   = (const float*)d_in[8];
    // d_in[9] = wg_b: constant shift of slot_imp, rank-invariant -> unused
    const float* rp_w   = (const float*)d_in[10];
    const float* rp_b   = (const float*)d_in[11];
    const float* out_w  = (const float*)d_in[12];
    const float* out_b  = (const float*)d_in[13];
    const float* memory = (const float*)d_in[14];
    float* out = (float*)d_out;

    wbar_kernel<<<4, 256>>>(wg_w);
    gemm1_kernel<<<dim3(16, 128), 256>>>(seq, embed, ff_w1, ff_b1);
    gemm2_kernel<<<dim3(8, 128), 256>>>(seq, embed, ff_w2, ff_b2);
    ln_kernel<<<BT, 256>>>(ln_g, ln_b);
    select_kernel<<<BB, 256>>>(memory);
    logits_kernel<<<(VOCAB + 127) / 128, 256>>>(out_w, out_b, nullptr, 0);
    conf_kernel<<<BB, 256>>>();
    rp_kernel<<<BB, 256>>>(rp_w, rp_b);
    attn_kernel<<<BB, 256>>>();
    logits_kernel<<<(VOCAB + 127) / 128, 256>>>(out_w, out_b, out, 1);
}

// round 5
// speedup vs baseline: 1.6528x; 1.6528x over previous
#include <cuda_runtime.h>
#include <math.h>

#define BB 32
#define TT 512
#define DD 1024
#define VOCAB 50257
#define SS 16
#define BT (BB*TT)
#define H2 2048

// ---------------- scratch (static device globals; no allocation) ----------------
__device__ float g_act[(size_t)BT * H2];      // relu(h@W1+b1)       128 MB
__device__ float g_x[(size_t)BT * DD];        // h + ff               64 MB
__device__ float g_hidden[(size_t)BT * DD];   // LN output            64 MB
__device__ float g_slot[BT];                  // slot importance
__device__ float g_wbar[DD];                  // mean_s wg_w
__device__ float g_query[BB * DD];            // hiddens[:, -1]
__device__ float g_mem[BB * SS * DD];         // assembled memory
__device__ float g_dl[(size_t)BB * VOCAB];    // direct logits
__device__ float g_use[BB];                   // use_mem flag (0/1)
__device__ float g_q[BB * DD];                // query @ rp_w + rp_b
__device__ float g_ctx[BB * DD];              // blended context

__device__ __forceinline__ float warp_sum(float v) {
#pragma unroll
    for (int o = 16; o > 0; o >>= 1) v += __shfl_xor_sync(0xffffffffu, v, o);
    return v;
}

__device__ __forceinline__ unsigned f2tf(float x) {
    unsigned u;
    asm("cvt.rna.tf32.f32 %0, %1;" : "=r"(u) : "f"(x));
    return u;
}

__device__ __forceinline__ void mma_tf32(float* c,
    unsigned a0, unsigned a1, unsigned a2, unsigned a3,
    unsigned b0, unsigned b1) {
    asm volatile(
        "mma.sync.aligned.m16n8k8.row.col.f32.tf32.tf32.f32 "
        "{%0,%1,%2,%3}, {%4,%5,%6,%7}, {%8,%9}, {%0,%1,%2,%3};"
        : "+f"(c[0]), "+f"(c[1]), "+f"(c[2]), "+f"(c[3])
        : "r"(a0), "r"(a1), "r"(a2), "r"(a3), "r"(b0), "r"(b1));
}

// ---------------- K0: wbar = mean_s wg_w ----------------
__global__ void wbar_kernel(const float* __restrict__ wg_w) {
    int d = blockIdx.x * blockDim.x + threadIdx.x;
    if (d < DD) {
        float s = 0.f;
#pragma unroll
        for (int j = 0; j < SS; j++) s += wg_w[d * SS + j];
        g_wbar[d] = s * (1.f / 16.f);
    }
}

// A smem: [128 rows][36 words]  (pad 36 ≡ 4 mod 32 -> conflict-free STS.128 + frag LDS)
// B smem: [32 k][136 words]     (pad 136 ≡ 8 mod 32 -> conflict-free)
#define APAD 36
#define BPAD 136

// ---------------- K1: act = relu(embed[seq] @ W1 + b1)  M=16384 N=2048 K=1024 (tf32 MMA) ----------------
__global__ __launch_bounds__(256) void gemm1_kernel(
    const int* __restrict__ seq, const float* __restrict__ embed,
    const float* __restrict__ W1, const float* __restrict__ b1) {
    __shared__ unsigned As[128 * APAD];
    __shared__ unsigned Bs[32 * BPAD];
    __shared__ int srow[128];
    const int tid = threadIdx.x;
    const int n0 = blockIdx.x * 128;
    const int row0 = blockIdx.y * 128;
    if (tid < 128) srow[tid] = seq[row0 + tid] * DD;
    __syncthreads();
    const int lane = tid & 31, warp = tid >> 5;
    const int wm = (warp & 1) * 64, wn = (warp >> 1) * 32;
    const int gid = lane >> 2, tg = lane & 3;

    float acc[4][4][4];
#pragma unroll
    for (int mi = 0; mi < 4; mi++)
#pragma unroll
        for (int ni = 0; ni < 4; ni++)
#pragma unroll
            for (int r = 0; r < 4; r++) acc[mi][ni][r] = 0.f;

    for (int k0 = 0; k0 < DD; k0 += 32) {
        // A: 128 rows x 32 k = 1024 float4 loads, transposed-free layout [m][k]
#pragma unroll
        for (int l = 0; l < 4; l++) {
            int f4 = tid + l * 256;
            int r = f4 >> 3, kq = f4 & 7;
            float4 v = *(const float4*)(embed + (size_t)srow[r] + k0 + kq * 4);
            unsigned* p = &As[r * APAD + kq * 4];
            p[0] = f2tf(v.x); p[1] = f2tf(v.y); p[2] = f2tf(v.z); p[3] = f2tf(v.w);
        }
        // B: 32 k x 128 n
#pragma unroll
        for (int l = 0; l < 4; l++) {
            int f4 = tid + l * 256;
            int kr = f4 >> 5, c4 = (f4 & 31) * 4;
            float4 v = *(const float4*)(W1 + (size_t)(k0 + kr) * H2 + n0 + c4);
            unsigned* p = &Bs[kr * BPAD + c4];
            p[0] = f2tf(v.x); p[1] = f2tf(v.y); p[2] = f2tf(v.z); p[3] = f2tf(v.w);
        }
        __syncthreads();
#pragma unroll
        for (int kt = 0; kt < 32; kt += 8) {
            unsigned a[4][4], b[4][2];
#pragma unroll
            for (int mi = 0; mi < 4; mi++) {
                int mb = (wm + mi * 16 + gid) * APAD;
                a[mi][0] = As[mb + kt + tg];
                a[mi][1] = As[mb + 8 * APAD + kt + tg];
                a[mi][2] = As[mb + kt + tg + 4];
                a[mi][3] = As[mb + 8 * APAD + kt + tg + 4];
            }
#pragma unroll
            for (int ni = 0; ni < 4; ni++) {
                int c = wn + ni * 8 + gid;
                b[ni][0] = Bs[(kt + tg) * BPAD + c];
                b[ni][1] = Bs[(kt + tg + 4) * BPAD + c];
            }
#pragma unroll
            for (int mi = 0; mi < 4; mi++)
#pragma unroll
                for (int ni = 0; ni < 4; ni++)
                    mma_tf32(acc[mi][ni], a[mi][0], a[mi][1], a[mi][2], a[mi][3],
                             b[ni][0], b[ni][1]);
        }
        __syncthreads();
    }
    // epilogue: bias + relu
#pragma unroll
    for (int mi = 0; mi < 4; mi++) {
        size_t r0 = (size_t)(row0 + wm + mi * 16 + gid);
        size_t r1 = r0 + 8;
#pragma unroll
        for (int ni = 0; ni < 4; ni++) {
            int col = n0 + wn + ni * 8 + 2 * tg;
            float bi0 = b1[col], bi1 = b1[col + 1];
            float2 o0, o1;
            o0.x = fmaxf(acc[mi][ni][0] + bi0, 0.f);
            o0.y = fmaxf(acc[mi][ni][1] + bi1, 0.f);
            o1.x = fmaxf(acc[mi][ni][2] + bi0, 0.f);
            o1.y = fmaxf(acc[mi][ni][3] + bi1, 0.f);
            *(float2*)(g_act + r0 * H2 + col) = o0;
            *(float2*)(g_act + r1 * H2 + col) = o1;
        }
    }
}

// ---------------- K2: x = act @ W2 + b2 + h   M=16384 N=1024 K=2048 (tf32 MMA) ----------------
__global__ __launch_bounds__(256) void gemm2_kernel(
    const int* __restrict__ seq, const float* __restrict__ embed,
    const float* __restrict__ W2, const float* __restrict__ b2) {
    __shared__ unsigned As[128 * APAD];
    __shared__ unsigned Bs[32 * BPAD];
    __shared__ int srow[128];
    const int tid = threadIdx.x;
    const int n0 = blockIdx.x * 128;
    const int row0 = blockIdx.y * 128;
    if (tid < 128) srow[tid] = seq[row0 + tid] * DD;
    __syncthreads();
    const int lane = tid & 31, warp = tid >> 5;
    const int wm = (warp & 1) * 64, wn = (warp >> 1) * 32;
    const int gid = lane >> 2, tg = lane & 3;

    float acc[4][4][4];
#pragma unroll
    for (int mi = 0; mi < 4; mi++)
#pragma unroll
        for (int ni = 0; ni < 4; ni++)
#pragma unroll
            for (int r = 0; r < 4; r++) acc[mi][ni][r] = 0.f;

    for (int k0 = 0; k0 < H2; k0 += 32) {
#pragma unroll
        for (int l = 0; l < 4; l++) {
            int f4 = tid + l * 256;
            int r = f4 >> 3, kq = f4 & 7;
            float4 v = *(const float4*)(g_act + (size_t)(row0 + r) * H2 + k0 + kq * 4);
            unsigned* p = &As[r * APAD + kq * 4];
            p[0] = f2tf(v.x); p[1] = f2tf(v.y); p[2] = f2tf(v.z); p[3] = f2tf(v.w);
        }
#pragma unroll
        for (int l = 0; l < 4; l++) {
            int f4 = tid + l * 256;
            int kr = f4 >> 5, c4 = (f4 & 31) * 4;
            float4 v = *(const float4*)(W2 + (size_t)(k0 + kr) * DD + n0 + c4);
            unsigned* p = &Bs[kr * BPAD + c4];
            p[0] = f2tf(v.x); p[1] = f2tf(v.y); p[2] = f2tf(v.z); p[3] = f2tf(v.w);
        }
        __syncthreads();
#pragma unroll
        for (int kt = 0; kt < 32; kt += 8) {
            unsigned a[4][4], b[4][2];
#pragma unroll
            for (int mi = 0; mi < 4; mi++) {
                int mb = (wm + mi * 16 + gid) * APAD;
                a[mi][0] = As[mb + kt + tg];
                a[mi][1] = As[mb + 8 * APAD + kt + tg];
                a[mi][2] = As[mb + kt + tg + 4];
                a[mi][3] = As[mb + 8 * APAD + kt + tg + 4];
            }
#pragma unroll
            for (int ni = 0; ni < 4; ni++) {
                int c = wn + ni * 8 + gid;
                b[ni][0] = Bs[(kt + tg) * BPAD + c];
                b[ni][1] = Bs[(kt + tg + 4) * BPAD + c];
            }
#pragma unroll
            for (int mi = 0; mi < 4; mi++)
#pragma unroll
                for (int ni = 0; ni < 4; ni++)
                    mma_tf32(acc[mi][ni], a[mi][0], a[mi][1], a[mi][2], a[mi][3],
                             b[ni][0], b[ni][1]);
        }
        __syncthreads();
    }
    // epilogue: bias + gathered embedding residual
#pragma unroll
    for (int mi = 0; mi < 4; mi++) {
        int lr0 = wm + mi * 16 + gid;
        int lr1 = lr0 + 8;
        size_t r0 = (size_t)(row0 + lr0);
        size_t r1 = (size_t)(row0 + lr1);
#pragma unroll
        for (int ni = 0; ni < 4; ni++) {
            int col = n0 + wn + ni * 8 + 2 * tg;
            float bi0 = b2[col], bi1 = b2[col + 1];
            float2 h0 = *(const float2*)(embed + (size_t)srow[lr0] + col);
            float2 h1 = *(const float2*)(embed + (size_t)srow[lr1] + col);
            float2 o0, o1;
            o0.x = acc[mi][ni][0] + bi0 + h0.x;
            o0.y = acc[mi][ni][1] + bi1 + h0.y;
            o1.x = acc[mi][ni][2] + bi0 + h1.x;
            o1.y = acc[mi][ni][3] + bi1 + h1.y;
            *(float2*)(g_x + r0 * DD + col) = o0;
            *(float2*)(g_x + r1 * DD + col) = o1;
        }
    }
}

// ---------------- K3: LayerNorm + slot_imp + query extraction ----------------
__global__ __launch_bounds__(256) void ln_kernel(
    const float* __restrict__ ln_g, const float* __restrict__ ln_b) {
    const int token = blockIdx.x;
    const int tid = threadIdx.x;
    const float4 x4 = *(const float4*)(g_x + (size_t)token * DD + tid * 4);
    float s = x4.x + x4.y + x4.z + x4.w;
    float sq = x4.x * x4.x + x4.y * x4.y + x4.z * x4.z + x4.w * x4.w;
    __shared__ float sh1[8], sh2[8];
    const int w = tid >> 5, l = tid & 31;
    s = warp_sum(s);
    sq = warp_sum(sq);
    if (l == 0) { sh1[w] = s; sh2[w] = sq; }
    __syncthreads();
    float ts = 0.f, tq = 0.f;
#pragma unroll
    for (int i = 0; i < 8; i++) { ts += sh1[i]; tq += sh2[i]; }
    const float mu = ts * (1.f / 1024.f);
    const float var = tq * (1.f / 1024.f) - mu * mu;
    const float rstd = rsqrtf(var + 1e-5f);
    const float4 g4 = *(const float4*)(ln_g + tid * 4);
    const float4 b4 = *(const float4*)(ln_b + tid * 4);
    float4 h4;
    h4.x = (x4.x - mu) * rstd * g4.x + b4.x;
    h4.y = (x4.y - mu) * rstd * g4.y + b4.y;
    h4.z = (x4.z - mu) * rstd * g4.z + b4.z;
    h4.w = (x4.w - mu) * rstd * g4.w + b4.w;
    *(float4*)(g_hidden + (size_t)token * DD + tid * 4) = h4;
    const float4 wb = *(const float4*)(g_wbar + tid * 4);
    float wd = h4.x * wb.x + h4.y * wb.y + h4.z * wb.z + h4.w * wb.w;
    wd = warp_sum(wd);
    __syncthreads();
    if (l == 0) sh1[w] = wd;
    __syncthreads();
    if (tid == 0) {
        float t2 = 0.f;
#pragma unroll
        for (int i = 0; i < 8; i++) t2 += sh1[i];
        g_slot[token] = t2;   // constant offset (mean wg_b) omitted: rank-invariant
    }
    if ((token & (TT - 1)) == TT - 1) {
        int bidx = token >> 9;
        *(float4*)(g_query + bidx * DD + tid * 4) = h4;
    }
}

// ---------------- K4: top-k selection + memory assembly ----------------
__global__ __launch_bounds__(256) void select_kernel(const float* __restrict__ memory) {
    const int b = blockIdx.x, tid = threadIdx.x;
    __shared__ float imp[512];
    __shared__ int idx[6];
    for (int t = tid; t < TT - 1; t += 256) imp[t] = g_slot[b * TT + t];
    __syncthreads();
    if (tid == 0) {
#pragma unroll
        for (int r = 0; r < 4; r++) {       // fwd top-4 (desc, stable)
            float best = -1e30f; int bi = 0;
            for (int t = 0; t < TT - 1; t++)
                if (imp[t] > best) { best = imp[t]; bi = t; }
            idx[r] = bi;
            imp[bi] = -3.0e38f;
        }
#pragma unroll
        for (int r = 0; r < 2; r++) {       // rev top-2 over first 8, masked
            float best = -1e30f; int bi = 0;
            for (int t = 0; t < 8; t++)
                if (imp[t] > best) { best = imp[t]; bi = t; }
            idx[4 + r] = bi;
            imp[bi] = -3.0e38f;
        }
    }
    __syncthreads();
    for (int s = 0; s < SS; s++) {
        const float* src = (s < 6)
            ? (g_hidden + (size_t)(b * TT + idx[s]) * DD)
            : (memory + (size_t)s * DD);
        *(float4*)(g_mem + (size_t)(b * SS + s) * DD + tid * 4) =
            *(const float4*)(src + tid * 4);
    }
}

// ---------------- K5/K9: vocab GEMM  out[b][v] = Q[b]·W[:,v] + bias[v] ----------------
__global__ __launch_bounds__(256) void logits_kernel(
    const float* __restrict__ W, const float* __restrict__ bias,
    float* __restrict__ extout, int mode) {
    const float* __restrict__ Q = mode ? g_ctx : g_query;
    float* __restrict__ out = mode ? extout : g_dl;
    const int tid = threadIdx.x;
    const int tv = tid & 31, bg = tid >> 5;
    const int v0 = blockIdx.x * 128 + tv * 4;
    __shared__ float Qs[32][128];
    float acc[4][4];
#pragma unroll
    for (int u = 0; u < 4; u++)
#pragma unroll
        for (int j = 0; j < 4; j++) acc[u][j] = 0.f;
    const bool full = (v0 + 4 <= VOCAB);

    for (int k0 = 0; k0 < DD; k0 += 128) {
#pragma unroll
        for (int l2 = 0; l2 < 4; l2++) {
            int f4 = tid + l2 * 256;
            int bb = f4 >> 5, dq = f4 & 31;
            *(float4*)&Qs[bb][dq * 4] =
                *(const float4*)(Q + bb * DD + k0 + dq * 4);
        }
        __syncthreads();
        if (full) {
            const float* wp = W + (size_t)k0 * VOCAB + v0;
#pragma unroll 2
            for (int d = 0; d < 128; d++) {
                const float w0 = wp[0], w1 = wp[1], w2 = wp[2], w3 = wp[3];
#pragma unroll
                for (int u = 0; u < 4; u++) {
                    const float q = Qs[bg * 4 + u][d];
                    acc[u][0] += q * w0; acc[u][1] += q * w1;
                    acc[u][2] += q * w2; acc[u][3] += q * w3;
                }
                wp += VOCAB;
            }
        } else if (v0 < VOCAB) {
            for (int d = 0; d < 128; d++) {
                const float* wp = W + (size_t)(k0 + d) * VOCAB;
#pragma unroll
                for (int j = 0; j < 4; j++) {
                    int v = v0 + j;
                    if (v < VOCAB) {
                        const float wv = wp[v];
#pragma unroll
                        for (int u = 0; u < 4; u++)
                            acc[u][j] += Qs[bg * 4 + u][d] * wv;
                    }
                }
            }
        }
        __syncthreads();
    }
#pragma unroll
    for (int u = 0; u < 4; u++) {
        const int bidx = bg * 4 + u;
#pragma unroll
        for (int j = 0; j < 4; j++) {
            int v = v0 + j;
            if (v < VOCAB) out[(size_t)bidx * VOCAB + v] = acc[u][j] + bias[v];
        }
    }
}

// ---------------- K6: conf = 1/sumexp(direct_logits - max) -> use_mem flag ----------------
__global__ __launch_bounds__(256) void conf_kernel() {
    const int b = blockIdx.x, tid = threadIdx.x;
    const float* row = g_dl + (size_t)b * VOCAB;
    float m = -3.0e38f;
    for (int v = tid; v < VOCAB; v += 256) m = fmaxf(m, row[v]);
    __shared__ float sh[8];
#pragma unroll
    for (int o = 16; o > 0; o >>= 1) m = fmaxf(m, __shfl_xor_sync(0xffffffffu, m, o));
    if ((tid & 31) == 0) sh[tid >> 5] = m;
    __syncthreads();
    float bm = sh[0];
#pragma unroll
    for (int i = 1; i < 8; i++) bm = fmaxf(bm, sh[i]);
    float ssum = 0.f;
    for (int v = tid; v < VOCAB; v += 256) ssum += expf(row[v] - bm);
    ssum = warp_sum(ssum);
    __syncthreads();
    if ((tid & 31) == 0) sh[tid >> 5] = ssum;
    __syncthreads();
    if (tid == 0) {
        float t = 0.f;
#pragma unroll
        for (int i = 0; i < 8; i++) t += sh[i];
        const float conf = 1.f / t;
        g_use[b] = (conf < 0.8f) ? 1.f : 0.f;
    }
}

// ---------------- K7: q = query @ rp_w + rp_b ----------------
__global__ __launch_bounds__(256) void rp_kernel(
    const float* __restrict__ rp_w, const float* __restrict__ rp_b) {
    const int b = blockIdx.x, tid = threadIdx.x;
    __shared__ __align__(16) float qs[DD];
    *(float4*)&qs[tid * 4] = *(const float4*)(g_query + b * DD + tid * 4);
    __syncthreads();
    float acc0 = 0.f, acc1 = 0.f, acc2 = 0.f, acc3 = 0.f;
    for (int d = 0; d < DD; d++) {
        const float q = qs[d];
        const float* wr = rp_w + (size_t)d * DD + tid;
        acc0 += q * wr[0];
        acc1 += q * wr[256];
        acc2 += q * wr[512];
        acc3 += q * wr[768];
    }
    g_q[b * DD + tid +   0] = acc0 + rp_b[tid +   0];
    g_q[b * DD + tid + 256] = acc1 + rp_b[tid + 256];
    g_q[b * DD + tid + 512] = acc2 + rp_b[tid + 512];
    g_q[b * DD + tid + 768] = acc3 + rp_b[tid + 768];
}

// ---------------- K8: scores -> softmax -> ctx -> blend ----------------
__global__ __launch_bounds__(256) void attn_kernel() {
    const int b = blockIdx.x, tid = threadIdx.x;
    __shared__ __align__(16) float qs[DD];
    __shared__ float sh[8];
    __shared__ float scores[SS];
    __shared__ float attn[SS];
    *(float4*)&qs[tid * 4] = *(const float4*)(g_q + b * DD + tid * 4);
    __syncthreads();
    for (int s = 0; s < SS; s++) {
        const float4 m4 = *(const float4*)(g_mem + (size_t)(b * SS + s) * DD + tid * 4);
        const float4 q4 = *(const float4*)&qs[tid * 4];
        float p = m4.x * q4.x + m4.y * q4.y + m4.z * q4.z + m4.w * q4.w;
        p = warp_sum(p);
        if ((tid & 31) == 0) sh[tid >> 5] = p;
        __syncthreads();
        if (tid == 0) {
            float t = 0.f;
#pragma unroll
            for (int i = 0; i < 8; i++) t += sh[i];
            scores[s] = t;
        }
        __syncthreads();
    }
    if (tid == 0) {
        float m = scores[0];
        for (int s = 1; s < SS; s++) m = fmaxf(m, scores[s]);
        float sum = 0.f;
        for (int s = 0; s < SS; s++) { float e = expf(scores[s] - m); attn[s] = e; sum += e; }
        const float inv = 1.f / sum;
        for (int s = 0; s < SS; s++) attn[s] *= inv;
    }
    __syncthreads();
    float c0 = 0.f, c1 = 0.f, c2 = 0.f, c3 = 0.f;
#pragma unroll
    for (int s = 0; s < SS; s++) {
        const float a = attn[s];
        const float4 m4 = *(const float4*)(g_mem + (size_t)(b * SS + s) * DD + tid * 4);
        c0 += a * m4.x; c1 += a * m4.y; c2 += a * m4.z; c3 += a * m4.w;
    }
    const float use = g_use[b];
    const float4 qv = *(const float4*)(g_query + b * DD + tid * 4);
    float4 o;
    o.x = c0 * use + qv.x * (1.f - use);
    o.y = c1 * use + qv.y * (1.f - use);
    o.z = c2 * use + qv.z * (1.f - use);
    o.w = c3 * use + qv.w * (1.f - use);
    *(float4*)(g_ctx + b * DD + tid * 4) = o;
}

// ---------------- launch ----------------
extern "C" void kernel_launch(void* const* d_in, const int* in_sizes, int n_in,
                              void* d_out, int out_size) {
    const int*   seq    = (const int*)  d_in[0];
    const float* embed  = (const float*)d_in[1];
    const float* ff_w1  = (const float*)d_in[2];
    const float* ff_b1  = (const float*)d_in[3];
    const float* ff_w2  = (const float*)d_in[4];
    const float* ff_b2  = (const float*)d_in[5];
    const float* ln_g   = (const float*)d_in[6];
    const float* ln_b   = (const float*)d_in[7];
    const float* wg_w   = (const float*)d_in[8];
    // d_in[9] = wg_b: constant shift of slot_imp, rank-invariant -> unused
    const float* rp_w   = (const float*)d_in[10];
    const float* rp_b   = (const float*)d_in[11];
    const float* out_w  = (const float*)d_in[12];
    const float* out_b  = (const float*)d_in[13];
    const float* memory = (const float*)d_in[14];
    float* out = (float*)d_out;

    wbar_kernel<<<4, 256>>>(wg_w);
    gemm1_kernel<<<dim3(16, 128), 256>>>(seq, embed, ff_w1, ff_b1);
    gemm2_kernel<<<dim3(8, 128), 256>>>(seq, embed, ff_w2, ff_b2);
    ln_kernel<<<BT, 256>>>(ln_g, ln_b);
    select_kernel<<<BB, 256>>>(memory);
    logits_kernel<<<(VOCAB + 127) / 128, 256>>>(out_w, out_b, nullptr, 0);
    conf_kernel<<<BB, 256>>>();
    rp_kernel<<<BB, 256>>>(rp_w, rp_b);
    attn_kernel<<<BB, 256>>>();
    logits_kernel<<<(VOCAB + 127) / 128, 256>>>(out_w, out_b, out, 1);
}

// round 7
// speedup vs baseline: 1.9794x; 1.1976x over previous
#include <cuda_runtime.h>
#include <math.h>

#define BB 32
#define TT 512
#define DD 1024
#define VOCAB 50257
#define SS 16
#define BT (BB*TT)
#define H2 2048

// ---------------- scratch (static device globals; no allocation) ----------------
__device__ float g_act[(size_t)BT * H2];      // relu(h@W1+b1)       128 MB
__device__ float g_x[(size_t)BT * DD];        // h + ff               64 MB
__device__ float g_hidden[(size_t)BT * DD];   // LN output            64 MB
__device__ float g_slot[BT];                  // slot importance
__device__ float g_wbar[DD];                  // mean_s wg_w
__device__ float g_query[BB * DD];            // hiddens[:, -1]
__device__ float g_mem[BB * SS * DD];         // assembled memory
__device__ float g_dl[(size_t)BB * VOCAB];    // direct logits
__device__ float g_use[BB];                   // use_mem flag (0/1)
__device__ float g_q[BB * DD];                // query @ rp_w + rp_b
__device__ float g_ctx[BB * DD];              // blended context

__device__ __forceinline__ float warp_sum(float v) {
#pragma unroll
    for (int o = 16; o > 0; o >>= 1) v += __shfl_xor_sync(0xffffffffu, v, o);
    return v;
}

__device__ __forceinline__ unsigned f2tf(float x) {
    unsigned u;
    asm("cvt.rna.tf32.f32 %0, %1;" : "=r"(u) : "f"(x));
    return u;
}
__device__ __forceinline__ unsigned u2tf(unsigned raw) {
    return f2tf(__uint_as_float(raw));
}

__device__ __forceinline__ void mma_tf32(float* c,
    unsigned a0, unsigned a1, unsigned a2, unsigned a3,
    unsigned b0, unsigned b1) {
    asm volatile(
        "mma.sync.aligned.m16n8k8.row.col.f32.tf32.tf32.f32 "
        "{%0,%1,%2,%3}, {%4,%5,%6,%7}, {%8,%9}, {%0,%1,%2,%3};"
        : "+f"(c[0]), "+f"(c[1]), "+f"(c[2]), "+f"(c[3])
        : "r"(a0), "r"(a1), "r"(a2), "r"(a3), "r"(b0), "r"(b1));
}

__device__ __forceinline__ unsigned sptr(const void* p) {
    return (unsigned)__cvta_generic_to_shared(p);
}
#define CPA16(dst_u32, src_ptr) \
    asm volatile("cp.async.cg.shared.global [%0], [%1], 16;" :: "r"(dst_u32), "l"(src_ptr))
#define CPA_COMMIT() asm volatile("cp.async.commit_group;")
#define CPA_WAIT1()  asm volatile("cp.async.wait_group 1;")
#define CPA_WAIT0()  asm volatile("cp.async.wait_group 0;")

// ---------------- K0: wbar = mean_s wg_w ----------------
__global__ void wbar_kernel(const float* __restrict__ wg_w) {
    int d = blockIdx.x * blockDim.x + threadIdx.x;
    if (d < DD) {
        float s = 0.f;
#pragma unroll
        for (int j = 0; j < SS; j++) s += wg_w[d * SS + j];
        g_wbar[d] = s * (1.f / 16.f);
    }
}

// A smem: [128 rows][36 words]  (pad 36 ≡ 4 mod 32 -> conflict-free, 16B-aligned rows)
// B smem: [32 k][136 words]     (pad 136 ≡ 8 mod 32 -> conflict-free, 16B-aligned rows)
#define APAD 36
#define BPAD 136
#define ASZ (128 * APAD)
#define BSZ (32 * BPAD)
#define NSTAGE 3
#define GEMM_SMEM (NSTAGE * (ASZ + BSZ) * 4)

// ---------------- K1: act = relu(embed[seq] @ W1 + b1)  M=16384 N=2048 K=1024 ----------------
__global__ __launch_bounds__(256) void gemm1_kernel(
    const int* __restrict__ seq, const float* __restrict__ embed,
    const float* __restrict__ W1, const float* __restrict__ b1) {
    extern __shared__ unsigned dsm[];
    unsigned* Asm = dsm;                    // [NSTAGE][ASZ]
    unsigned* Bsm = dsm + NSTAGE * ASZ;     // [NSTAGE][BSZ]
    __shared__ int srow[128];
    const int tid = threadIdx.x;
    const int n0 = blockIdx.x * 128;
    const int row0 = blockIdx.y * 128;
    if (tid < 128) srow[tid] = seq[row0 + tid] * DD;
    __syncthreads();
    const int lane = tid & 31, warp = tid >> 5;
    const int wm = (warp & 1) * 64, wn = (warp >> 1) * 32;
    const int gid = lane >> 2, tg = lane & 3;
    const int NT = DD / 32;   // 32 k-tiles

#define G1_ISSUE(kt, st) do {                                                   \
        const int k0 = (kt) * 32;                                               \
        unsigned* Ad = Asm + (st) * ASZ;                                        \
        unsigned* Bd = Bsm + (st) * BSZ;                                        \
        _Pragma("unroll")                                                       \
        for (int l = 0; l < 4; l++) {                                           \
            int f4 = tid + l * 256;                                             \
            int r = f4 >> 3, kq = f4 & 7;                                       \
            CPA16(sptr(Ad + r * APAD + kq * 4),                                 \
                  embed + (size_t)srow[r] + k0 + kq * 4);                       \
        }                                                                       \
        _Pragma("unroll")                                                       \
        for (int l = 0; l < 4; l++) {                                           \
            int f4 = tid + l * 256;                                             \
            int kr = f4 >> 5, c4 = (f4 & 31) * 4;                               \
            CPA16(sptr(Bd + kr * BPAD + c4),                                    \
                  W1 + (size_t)(k0 + kr) * H2 + n0 + c4);                       \
        }                                                                       \
        CPA_COMMIT();                                                           \
    } while (0)

    float acc[4][4][4];
#pragma unroll
    for (int mi = 0; mi < 4; mi++)
#pragma unroll
        for (int ni = 0; ni < 4; ni++)
#pragma unroll
            for (int r = 0; r < 4; r++) acc[mi][ni][r] = 0.f;

    G1_ISSUE(0, 0);
    G1_ISSUE(1, 1);

    for (int kt = 0; kt < NT; kt++) {
        if (kt + 2 < NT) { CPA_WAIT1(); } else { CPA_WAIT0(); }
        __syncthreads();
        if (kt + 2 < NT) G1_ISSUE(kt + 2, (kt + 2) % NSTAGE);
        const unsigned* Ab = Asm + (kt % NSTAGE) * ASZ;
        const unsigned* Bb = Bsm + (kt % NSTAGE) * BSZ;
#pragma unroll
        for (int ks = 0; ks < 32; ks += 8) {
            unsigned a[4][4], b[4][2];
#pragma unroll
            for (int mi = 0; mi < 4; mi++) {
                int mb = (wm + mi * 16 + gid) * APAD;
                a[mi][0] = u2tf(Ab[mb + ks + tg]);
                a[mi][1] = u2tf(Ab[mb + 8 * APAD + ks + tg]);
                a[mi][2] = u2tf(Ab[mb + ks + tg + 4]);
                a[mi][3] = u2tf(Ab[mb + 8 * APAD + ks + tg + 4]);
            }
#pragma unroll
            for (int ni = 0; ni < 4; ni++) {
                int c = wn + ni * 8 + gid;
                b[ni][0] = u2tf(Bb[(ks + tg) * BPAD + c]);
                b[ni][1] = u2tf(Bb[(ks + tg + 4) * BPAD + c]);
            }
#pragma unroll
            for (int mi = 0; mi < 4; mi++)
#pragma unroll
                for (int ni = 0; ni < 4; ni++)
                    mma_tf32(acc[mi][ni], a[mi][0], a[mi][1], a[mi][2], a[mi][3],
                             b[ni][0], b[ni][1]);
        }
    }
    // epilogue: bias + relu
#pragma unroll
    for (int mi = 0; mi < 4; mi++) {
        size_t r0 = (size_t)(row0 + wm + mi * 16 + gid);
        size_t r1 = r0 + 8;
#pragma unroll
        for (int ni = 0; ni < 4; ni++) {
            int col = n0 + wn + ni * 8 + 2 * tg;
            float bi0 = b1[col], bi1 = b1[col + 1];
            float2 o0, o1;
            o0.x = fmaxf(acc[mi][ni][0] + bi0, 0.f);
            o0.y = fmaxf(acc[mi][ni][1] + bi1, 0.f);
            o1.x = fmaxf(acc[mi][ni][2] + bi0, 0.f);
            o1.y = fmaxf(acc[mi][ni][3] + bi1, 0.f);
            *(float2*)(g_act + r0 * H2 + col) = o0;
            *(float2*)(g_act + r1 * H2 + col) = o1;
        }
    }
#undef G1_ISSUE
}

// ---------------- K2: x = act @ W2 + b2 + h   M=16384 N=1024 K=2048 ----------------
__global__ __launch_bounds__(256) void gemm2_kernel(
    const int* __restrict__ seq, const float* __restrict__ embed,
    const float* __restrict__ W2, const float* __restrict__ b2) {
    extern __shared__ unsigned dsm[];
    unsigned* Asm = dsm;
    unsigned* Bsm = dsm + NSTAGE * ASZ;
    __shared__ int srow[128];
    const int tid = threadIdx.x;
    const int n0 = blockIdx.x * 128;
    const int row0 = blockIdx.y * 128;
    if (tid < 128) srow[tid] = seq[row0 + tid] * DD;
    __syncthreads();
    const int lane = tid & 31, warp = tid >> 5;
    const int wm = (warp & 1) * 64, wn = (warp >> 1) * 32;
    const int gid = lane >> 2, tg = lane & 3;
    const int NT = H2 / 32;   // 64 k-tiles

#define G2_ISSUE(kt, st) do {                                                   \
        const int k0 = (kt) * 32;                                               \
        unsigned* Ad = Asm + (st) * ASZ;                                        \
        unsigned* Bd = Bsm + (st) * BSZ;                                        \
        _Pragma("unroll")                                                       \
        for (int l = 0; l < 4; l++) {                                           \
            int f4 = tid + l * 256;                                             \
            int r = f4 >> 3, kq = f4 & 7;                                       \
            CPA16(sptr(Ad + r * APAD + kq * 4),                                 \
                  g_act + (size_t)(row0 + r) * H2 + k0 + kq * 4);               \
        }                                                                       \
        _Pragma("unroll")                                                       \
        for (int l = 0; l < 4; l++) {                                           \
            int f4 = tid + l * 256;                                             \
            int kr = f4 >> 5, c4 = (f4 & 31) * 4;                               \
            CPA16(sptr(Bd + kr * BPAD + c4),                                    \
                  W2 + (size_t)(k0 + kr) * DD + n0 + c4);                       \
        }                                                                       \
        CPA_COMMIT();                                                           \
    } while (0)

    float acc[4][4][4];
#pragma unroll
    for (int mi = 0; mi < 4; mi++)
#pragma unroll
        for (int ni = 0; ni < 4; ni++)
#pragma unroll
            for (int r = 0; r < 4; r++) acc[mi][ni][r] = 0.f;

    G2_ISSUE(0, 0);
    G2_ISSUE(1, 1);

    for (int kt = 0; kt < NT; kt++) {
        if (kt + 2 < NT) { CPA_WAIT1(); } else { CPA_WAIT0(); }
        __syncthreads();
        if (kt + 2 < NT) G2_ISSUE(kt + 2, (kt + 2) % NSTAGE);
        const unsigned* Ab = Asm + (kt % NSTAGE) * ASZ;
        const unsigned* Bb = Bsm + (kt % NSTAGE) * BSZ;
#pragma unroll
        for (int ks = 0; ks < 32; ks += 8) {
            unsigned a[4][4], b[4][2];
#pragma unroll
            for (int mi = 0; mi < 4; mi++) {
                int mb = (wm + mi * 16 + gid) * APAD;
                a[mi][0] = u2tf(Ab[mb + ks + tg]);
                a[mi][1] = u2tf(Ab[mb + 8 * APAD + ks + tg]);
                a[mi][2] = u2tf(Ab[mb + ks + tg + 4]);
                a[mi][3] = u2tf(Ab[mb + 8 * APAD + ks + tg + 4]);
            }
#pragma unroll
            for (int ni = 0; ni < 4; ni++) {
                int c = wn + ni * 8 + gid;
                b[ni][0] = u2tf(Bb[(ks + tg) * BPAD + c]);
                b[ni][1] = u2tf(Bb[(ks + tg + 4) * BPAD + c]);
            }
#pragma unroll
            for (int mi = 0; mi < 4; mi++)
#pragma unroll
                for (int ni = 0; ni < 4; ni++)
                    mma_tf32(acc[mi][ni], a[mi][0], a[mi][1], a[mi][2], a[mi][3],
                             b[ni][0], b[ni][1]);
        }
    }
    // epilogue: bias + gathered embedding residual
#pragma unroll
    for (int mi = 0; mi < 4; mi++) {
        int lr0 = wm + mi * 16 + gid;
        int lr1 = lr0 + 8;
        size_t r0 = (size_t)(row0 + lr0);
        size_t r1 = (size_t)(row0 + lr1);
#pragma unroll
        for (int ni = 0; ni < 4; ni++) {
            int col = n0 + wn + ni * 8 + 2 * tg;
            float bi0 = b2[col], bi1 = b2[col + 1];
            float2 h0 = *(const float2*)(embed + (size_t)srow[lr0] + col);
            float2 h1 = *(const float2*)(embed + (size_t)srow[lr1] + col);
            float2 o0, o1;
            o0.x = acc[mi][ni][0] + bi0 + h0.x;
            o0.y = acc[mi][ni][1] + bi1 + h0.y;
            o1.x = acc[mi][ni][2] + bi0 + h1.x;
            o1.y = acc[mi][ni][3] + bi1 + h1.y;
            *(float2*)(g_x + r0 * DD + col) = o0;
            *(float2*)(g_x + r1 * DD + col) = o1;
        }
    }
#undef G2_ISSUE
}

// ---------------- K3: LayerNorm + slot_imp + query extraction ----------------
__global__ __launch_bounds__(256) void ln_kernel(
    const float* __restrict__ ln_g, const float* __restrict__ ln_b) {
    const int token = blockIdx.x;
    const int tid = threadIdx.x;
    const float4 x4 = *(const float4*)(g_x + (size_t)token * DD + tid * 4);
    float s = x4.x + x4.y + x4.z + x4.w;
    float sq = x4.x * x4.x + x4.y * x4.y + x4.z * x4.z + x4.w * x4.w;
    __shared__ float sh1[8], sh2[8];
    const int w = tid >> 5, l = tid & 31;
    s = warp_sum(s);
    sq = warp_sum(sq);
    if (l == 0) { sh1[w] = s; sh2[w] = sq; }
    __syncthreads();
    float ts = 0.f, tq = 0.f;
#pragma unroll
    for (int i = 0; i < 8; i++) { ts += sh1[i]; tq += sh2[i]; }
    const float mu = ts * (1.f / 1024.f);
    const float var = tq * (1.f / 1024.f) - mu * mu;
    const float rstd = rsqrtf(var + 1e-5f);
    const float4 g4 = *(const float4*)(ln_g + tid * 4);
    const float4 b4 = *(const float4*)(ln_b + tid * 4);
    float4 h4;
    h4.x = (x4.x - mu) * rstd * g4.x + b4.x;
    h4.y = (x4.y - mu) * rstd * g4.y + b4.y;
    h4.z = (x4.z - mu) * rstd * g4.z + b4.z;
    h4.w = (x4.w - mu) * rstd * g4.w + b4.w;
    *(float4*)(g_hidden + (size_t)token * DD + tid * 4) = h4;
    const float4 wb = *(const float4*)(g_wbar + tid * 4);
    float wd = h4.x * wb.x + h4.y * wb.y + h4.z * wb.z + h4.w * wb.w;
    wd = warp_sum(wd);
    __syncthreads();
    if (l == 0) sh1[w] = wd;
    __syncthreads();
    if (tid == 0) {
        float t2 = 0.f;
#pragma unroll
        for (int i = 0; i < 8; i++) t2 += sh1[i];
        g_slot[token] = t2;   // constant offset (mean wg_b) omitted: rank-invariant
    }
    if ((token & (TT - 1)) == TT - 1) {
        int bidx = token >> 9;
        *(float4*)(g_query + bidx * DD + tid * 4) = h4;
    }
}

// ---------------- K4: top-k selection + memory assembly ----------------
__global__ __launch_bounds__(256) void select_kernel(const float* __restrict__ memory) {
    const int b = blockIdx.x, tid = threadIdx.x;
    __shared__ float imp[512];
    __shared__ int idx[6];
    for (int t = tid; t < TT - 1; t += 256) imp[t] = g_slot[b * TT + t];
    __syncthreads();
    if (tid == 0) {
#pragma unroll
        for (int r = 0; r < 4; r++) {       // fwd top-4 (desc, stable)
            float best = -1e30f; int bi = 0;
            for (int t = 0; t < TT - 1; t++)
                if (imp[t] > best) { best = imp[t]; bi = t; }
            idx[r] = bi;
            imp[bi] = -3.0e38f;
        }
#pragma unroll
        for (int r = 0; r < 2; r++) {       // rev top-2 over first 8, masked
            float best = -1e30f; int bi = 0;
            for (int t = 0; t < 8; t++)
                if (imp[t] > best) { best = imp[t]; bi = t; }
            idx[4 + r] = bi;
            imp[bi] = -3.0e38f;
        }
    }
    __syncthreads();
    for (int s = 0; s < SS; s++) {
        const float* src = (s < 6)
            ? (g_hidden + (size_t)(b * TT + idx[s]) * DD)
            : (memory + (size_t)s * DD);
        *(float4*)(g_mem + (size_t)(b * SS + s) * DD + tid * 4) =
            *(const float4*)(src + tid * 4);
    }
}

// ---------------- K5/K9: vocab GEMM  out[b][v] = Q[b]·W[:,v] + bias[v] ----------------
__global__ __launch_bounds__(256) void logits_kernel(
    const float* __restrict__ W, const float* __restrict__ bias,
    float* __restrict__ extout, int mode) {
    const float* __restrict__ Q = mode ? g_ctx : g_query;
    float* __restrict__ out = mode ? extout : g_dl;
    const int tid = threadIdx.x;
    const int tv = tid & 31, bg = tid >> 5;
    const int v0 = blockIdx.x * 128 + tv * 4;
    __shared__ float Qs[32][128];
    float acc[4][4];
#pragma unroll
    for (int u = 0; u < 4; u++)
#pragma unroll
        for (int j = 0; j < 4; j++) acc[u][j] = 0.f;
    const bool full = (v0 + 4 <= VOCAB);

    for (int k0 = 0; k0 < DD; k0 += 128) {
#pragma unroll
        for (int l2 = 0; l2 < 4; l2++) {
            int f4 = tid + l2 * 256;
            int bb = f4 >> 5, dq = f4 & 31;
            *(float4*)&Qs[bb][dq * 4] =
                *(const float4*)(Q + bb * DD + k0 + dq * 4);
        }
        __syncthreads();
        if (full) {
            const float* wp = W + (size_t)k0 * VOCAB + v0;
#pragma unroll 2
            for (int d = 0; d < 128; d++) {
                const float w0 = wp[0], w1 = wp[1], w2 = wp[2], w3 = wp[3];
#pragma unroll
                for (int u = 0; u < 4; u++) {
                    const float q = Qs[bg * 4 + u][d];
                    acc[u][0] += q * w0; acc[u][1] += q * w1;
                    acc[u][2] += q * w2; acc[u][3] += q * w3;
                }
                wp += VOCAB;
            }
        } else if (v0 < VOCAB) {
            for (int d = 0; d < 128; d++) {
                const float* wp = W + (size_t)(k0 + d) * VOCAB;
#pragma unroll
                for (int j = 0; j < 4; j++) {
                    int v = v0 + j;
                    if (v < VOCAB) {
                        const float wv = wp[v];
#pragma unroll
                        for (int u = 0; u < 4; u++)
                            acc[u][j] += Qs[bg * 4 + u][d] * wv;
                    }
                }
            }
        }
        __syncthreads();
    }
#pragma unroll
    for (int u = 0; u < 4; u++) {
        const int bidx = bg * 4 + u;
#pragma unroll
        for (int j = 0; j < 4; j++) {
            int v = v0 + j;
            if (v < VOCAB) out[(size_t)bidx * VOCAB + v] = acc[u][j] + bias[v];
        }
    }
}

// ---------------- K6: conf = 1/sumexp(direct_logits - max) -> use_mem flag ----------------
__global__ __launch_bounds__(256) void conf_kernel() {
    const int b = blockIdx.x, tid = threadIdx.x;
    const float* row = g_dl + (size_t)b * VOCAB;
    float m = -3.0e38f;
    for (int v = tid; v < VOCAB; v += 256) m = fmaxf(m, row[v]);
    __shared__ float sh[8];
#pragma unroll
    for (int o = 16; o > 0; o >>= 1) m = fmaxf(m, __shfl_xor_sync(0xffffffffu, m, o));
    if ((tid & 31) == 0) sh[tid >> 5] = m;
    __syncthreads();
    float bm = sh[0];
#pragma unroll
    for (int i = 1; i < 8; i++) bm = fmaxf(bm, sh[i]);
    float ssum = 0.f;
    for (int v = tid; v < VOCAB; v += 256) ssum += expf(row[v] - bm);
    ssum = warp_sum(ssum);
    __syncthreads();
    if ((tid & 31) == 0) sh[tid >> 5] = ssum;
    __syncthreads();
    if (tid == 0) {
        float t = 0.f;
#pragma unroll
        for (int i = 0; i < 8; i++) t += sh[i];
        const float conf = 1.f / t;
        g_use[b] = (conf < 0.8f) ? 1.f : 0.f;
    }
}

// ---------------- K7: q = query @ rp_w + rp_b ----------------
__global__ __launch_bounds__(256) void rp_kernel(
    const float* __restrict__ rp_w, const float* __restrict__ rp_b) {
    const int b = blockIdx.x, tid = threadIdx.x;
    __shared__ __align__(16) float qs[DD];
    *(float4*)&qs[tid * 4] = *(const float4*)(g_query + b * DD + tid * 4);
    __syncthreads();
    float acc0 = 0.f, acc1 = 0.f, acc2 = 0.f, acc3 = 0.f;
    for (int d = 0; d < DD; d++) {
        const float q = qs[d];
        const float* wr = rp_w + (size_t)d * DD + tid;
        acc0 += q * wr[0];
        acc1 += q * wr[256];
        acc2 += q * wr[512];
        acc3 += q * wr[768];
    }
    g_q[b * DD + tid +   0] = acc0 + rp_b[tid +   0];
    g_q[b * DD + tid + 256] = acc1 + rp_b[tid + 256];
    g_q[b * DD + tid + 512] = acc2 + rp_b[tid + 512];
    g_q[b * DD + tid + 768] = acc3 + rp_b[tid + 768];
}

// ---------------- K8: scores -> softmax -> ctx -> blend ----------------
__global__ __launch_bounds__(256) void attn_kernel() {
    const int b = blockIdx.x, tid = threadIdx.x;
    __shared__ __align__(16) float qs[DD];
    __shared__ float sh[8];
    __shared__ float scores[SS];
    __shared__ float attn[SS];
    *(float4*)&qs[tid * 4] = *(const float4*)(g_q + b * DD + tid * 4);
    __syncthreads();
    for (int s = 0; s < SS; s++) {
        const float4 m4 = *(const float4*)(g_mem + (size_t)(b * SS + s) * DD + tid * 4);
        const float4 q4 = *(const float4*)&qs[tid * 4];
        float p = m4.x * q4.x + m4.y * q4.y + m4.z * q4.z + m4.w * q4.w;
        p = warp_sum(p);
        if ((tid & 31) == 0) sh[tid >> 5] = p;
        __syncthreads();
        if (tid == 0) {
            float t = 0.f;
#pragma unroll
            for (int i = 0; i < 8; i++) t += sh[i];
            scores[s] = t;
        }
        __syncthreads();
    }
    if (tid == 0) {
        float m = scores[0];
        for (int s = 1; s < SS; s++) m = fmaxf(m, scores[s]);
        float sum = 0.f;
        for (int s = 0; s < SS; s++) { float e = expf(scores[s] - m); attn[s] = e; sum += e; }
        const float inv = 1.f / sum;
        for (int s = 0; s < SS; s++) attn[s] *= inv;
    }
    __syncthreads();
    float c0 = 0.f, c1 = 0.f, c2 = 0.f, c3 = 0.f;
#pragma unroll
    for (int s = 0; s < SS; s++) {
        const float a = attn[s];
        const float4 m4 = *(const float4*)(g_mem + (size_t)(b * SS + s) * DD + tid * 4);
        c0 += a * m4.x; c1 += a * m4.y; c2 += a * m4.z; c3 += a * m4.w;
    }
    const float use = g_use[b];
    const float4 qv = *(const float4*)(g_query + b * DD + tid * 4);
    float4 o;
    o.x = c0 * use + qv.x * (1.f - use);
    o.y = c1 * use + qv.y * (1.f - use);
    o.z = c2 * use + qv.z * (1.f - use);
    o.w = c3 * use + qv.w * (1.f - use);
    *(float4*)(g_ctx + b * DD + tid * 4) = o;
}

// ---------------- launch ----------------
extern "C" void kernel_launch(void* const* d_in, const int* in_sizes, int n_in,
                              void* d_out, int out_size) {
    const int*   seq    = (const int*)  d_in[0];
    const float* embed  = (const float*)d_in[1];
    const float* ff_w1  = (const float*)d_in[2];
    const float* ff_b1  = (const float*)d_in[3];
    const float* ff_w2  = (const float*)d_in[4];
    const float* ff_b2  = (const float*)d_in[5];
    const float* ln_g   = (const float*)d_in[6];
    const float* ln_b   = (const float*)d_in[7];
    const float* wg_w   = (const float*)d_in[8];
    // d_in[9] = wg_b: constant shift of slot_imp, rank-invariant -> unused
    const float* rp_w   = (const float*)d_in[10];
    const float* rp_b   = (const float*)d_in[11];
    const float* out_w  = (const float*)d_in[12];
    const float* out_b  = (const float*)d_in[13];
    const float* memory = (const float*)d_in[14];
    float* out = (float*)d_out;

    // opt-in dynamic smem (immediate attribute set, not a stream op; idempotent)
    cudaFuncSetAttribute(gemm1_kernel, cudaFuncAttributeMaxDynamicSharedMemorySize, GEMM_SMEM);
    cudaFuncSetAttribute(gemm2_kernel, cudaFuncAttributeMaxDynamicSharedMemorySize, GEMM_SMEM);

    wbar_kernel<<<4, 256>>>(wg_w);
    gemm1_kernel<<<dim3(16, 128), 256, GEMM_SMEM>>>(seq, embed, ff_w1, ff_b1);
    gemm2_kernel<<<dim3(8, 128), 256, GEMM_SMEM>>>(seq, embed, ff_w2, ff_b2);
    ln_kernel<<<BT, 256>>>(ln_g, ln_b);
    select_kernel<<<BB, 256>>>(memory);
    logits_kernel<<<(VOCAB + 127) / 128, 256>>>(out_w, out_b, nullptr, 0);
    conf_kernel<<<BB, 256>>>();
    rp_kernel<<<BB, 256>>>(rp_w, rp_b);
    attn_kernel<<<BB, 256>>>();
    logits_kernel<<<(VOCAB + 127) / 128, 256>>>(out_w, out_b, out, 1);
}

// round 11
// speedup vs baseline: 2.4934x; 1.2597x over previous
#include <cuda_runtime.h>
#include <math.h>

#define BB 32
#define TT 512
#define DD 1024
#define VOCAB 50257
#define SS 16
#define BT (BB*TT)
#define H2 2048

// ---------------- scratch (static device globals; no allocation) ----------------
// NOTE: device globals are ONLY referenced inside device code (never passed as
// kernel arguments from host — host shadow address + GB300 ATS silently breaks that).
__device__ unsigned g_act[(size_t)BT * H2];    // relu(h@W1+b1) tf32 bits 128 MB
__device__ unsigned g_htf[(size_t)BT * DD];    // rna(embed[seq]) bits     64 MB
__device__ unsigned g_w1r[(size_t)DD * H2];    // rna(W1) bits              8 MB
__device__ unsigned g_w2r[(size_t)H2 * DD];    // rna(W2) bits              8 MB
__device__ float g_x[(size_t)BT * DD];         // h + ff                   64 MB
__device__ float g_hidden[(size_t)BT * DD];    // LN output                64 MB
__device__ float g_slot[BT];
__device__ float g_wbar[DD];
__device__ float g_query[BB * DD];
__device__ float g_mem[BB * SS * DD];
__device__ float g_dl[(size_t)BB * VOCAB];
__device__ float g_use[BB];
__device__ float g_q[BB * DD];
__device__ float g_ctx[BB * DD];

__device__ __forceinline__ float warp_sum(float v) {
#pragma unroll
    for (int o = 16; o > 0; o >>= 1) v += __shfl_xor_sync(0xffffffffu, v, o);
    return v;
}
__device__ __forceinline__ unsigned f2tf(float x) {
    unsigned u;
    asm("cvt.rna.tf32.f32 %0, %1;" : "=r"(u) : "f"(x));
    return u;
}
__device__ __forceinline__ void mma_tf32(float* c,
    unsigned a0, unsigned a1, unsigned a2, unsigned a3,
    unsigned b0, unsigned b1) {
    asm volatile(
        "mma.sync.aligned.m16n8k8.row.col.f32.tf32.tf32.f32 "
        "{%0,%1,%2,%3}, {%4,%5,%6,%7}, {%8,%9}, {%0,%1,%2,%3};"
        : "+f"(c[0]), "+f"(c[1]), "+f"(c[2]), "+f"(c[3])
        : "r"(a0), "r"(a1), "r"(a2), "r"(a3), "r"(b0), "r"(b1));
}
__device__ __forceinline__ unsigned sptr(const void* p) {
    return (unsigned)__cvta_generic_to_shared(p);
}
#define CPA16(dst_u32, src_ptr) \
    asm volatile("cp.async.cg.shared.global [%0], [%1], 16;" :: "r"(dst_u32), "l"(src_ptr))
#define CPA_COMMIT() asm volatile("cp.async.commit_group;")
#define CPA_WAIT1()  asm volatile("cp.async.wait_group 1;")
#define CPA_WAIT0()  asm volatile("cp.async.wait_group 0;")

// A smem: [128 rows][36 words]  (pad 36 ≡ 4 mod 32 -> conflict-free, 16B rows)
// B smem: [32 k][136 words]     (pad 136 ≡ 8 mod 32 -> conflict-free, 16B rows)
#define APAD 36
#define BPAD 136
#define ASZ (128 * APAD)
#define BSZ (32 * BPAD)
#define NSTAGE 3
#define GEMM_SMEM (NSTAGE * (ASZ + BSZ) * 4)

// ---------------- K0: wbar = mean_s wg_w ----------------
__global__ void wbar_kernel(const float* __restrict__ wg_w) {
    int d = blockIdx.x * blockDim.x + threadIdx.x;
    if (d < DD) {
        float s = 0.f;
#pragma unroll
        for (int j = 0; j < SS; j++) s += wg_w[d * SS + j];
        g_wbar[d] = s * (1.f / 16.f);
    }
}

// ---------------- prep: RNA round weights to tf32 bits (dst = device global, internal) ----------------
__global__ __launch_bounds__(256) void round_w1(const float* __restrict__ src) {
    size_t i = ((size_t)blockIdx.x * 256 + threadIdx.x) * 4;
    float4 v = *(const float4*)(src + i);
    uint4 o;
    o.x = f2tf(v.x); o.y = f2tf(v.y); o.z = f2tf(v.z); o.w = f2tf(v.w);
    *(uint4*)(g_w1r + i) = o;
}
__global__ __launch_bounds__(256) void round_w2(const float* __restrict__ src) {
    size_t i = ((size_t)blockIdx.x * 256 + threadIdx.x) * 4;
    float4 v = *(const float4*)(src + i);
    uint4 o;
    o.x = f2tf(v.x); o.y = f2tf(v.y); o.z = f2tf(v.z); o.w = f2tf(v.w);
    *(uint4*)(g_w2r + i) = o;
}

// ---------------- prep: g_htf = rna(embed[seq]) ----------------
__global__ __launch_bounds__(256) void htf_kernel(const int* __restrict__ seq,
                                                  const float* __restrict__ embed) {
    const int t = blockIdx.x;
    const int off = threadIdx.x * 4;
    const size_t erow = (size_t)seq[t] * DD;
    float4 v = *(const float4*)(embed + erow + off);
    uint4 o;
    o.x = f2tf(v.x); o.y = f2tf(v.y); o.z = f2tf(v.z); o.w = f2tf(v.w);
    *(uint4*)(g_htf + (size_t)t * DD + off) = o;
}

// ---------------- K1: g_act = tf32bits(relu(h @ W1 + b1))  M=16384 N=2048 K=1024 ----------------
__global__ __launch_bounds__(256) void gemm1_kernel(const float* __restrict__ b1) {
    extern __shared__ unsigned dsm[];
    unsigned* Asm = dsm;                    // [NSTAGE][ASZ]
    unsigned* Bsm = dsm + NSTAGE * ASZ;     // [NSTAGE][BSZ]
    const int tid = threadIdx.x;
    const int n0 = blockIdx.x * 128;
    const size_t row0 = (size_t)blockIdx.y * 128;
    const int lane = tid & 31, warp = tid >> 5;
    const int wm = (warp & 1) * 64, wn = (warp >> 1) * 32;
    const int gid = lane >> 2, tg = lane & 3;
    const int NT = DD / 32;

#define G1_ISSUE(kt, st) do {                                                   \
        const int k0 = (kt) * 32;                                               \
        unsigned* Ad = Asm + (st) * ASZ;                                        \
        unsigned* Bd = Bsm + (st) * BSZ;                                        \
        _Pragma("unroll")                                                       \
        for (int l = 0; l < 4; l++) {                                           \
            int f4 = tid + l * 256;                                             \
            int r = f4 >> 3, kq = f4 & 7;                                       \
            CPA16(sptr(Ad + r * APAD + kq * 4),                                 \
                  g_htf + (row0 + r) * DD + k0 + kq * 4);                       \
        }                                                                       \
        _Pragma("unroll")                                                       \
        for (int l = 0; l < 4; l++) {                                           \
            int f4 = tid + l * 256;                                             \
            int kr = f4 >> 5, c4 = (f4 & 31) * 4;                               \
            CPA16(sptr(Bd + kr * BPAD + c4),                                    \
                  g_w1r + (size_t)(k0 + kr) * H2 + n0 + c4);                    \
        }                                                                       \
        CPA_COMMIT();                                                           \
    } while (0)

    float acc[4][4][4];
#pragma unroll
    for (int mi = 0; mi < 4; mi++)
#pragma unroll
        for (int ni = 0; ni < 4; ni++)
#pragma unroll
            for (int r = 0; r < 4; r++) acc[mi][ni][r] = 0.f;

    G1_ISSUE(0, 0);
    G1_ISSUE(1, 1);

    for (int kt = 0; kt < NT; kt++) {
        if (kt + 1 < NT) { CPA_WAIT1(); } else { CPA_WAIT0(); }
        __syncthreads();
        if (kt + 2 < NT) G1_ISSUE(kt + 2, (kt + 2) % NSTAGE);
        const unsigned* Ab = Asm + (kt % NSTAGE) * ASZ;
        const unsigned* Bb = Bsm + (kt % NSTAGE) * BSZ;
#pragma unroll
        for (int ks = 0; ks < 32; ks += 8) {
            unsigned a[4][4], b[4][2];
#pragma unroll
            for (int mi = 0; mi < 4; mi++) {
                int mb = (wm + mi * 16 + gid) * APAD;
                a[mi][0] = Ab[mb + ks + tg];
                a[mi][1] = Ab[mb + 8 * APAD + ks + tg];
                a[mi][2] = Ab[mb + ks + tg + 4];
                a[mi][3] = Ab[mb + 8 * APAD + ks + tg + 4];
            }
#pragma unroll
            for (int ni = 0; ni < 4; ni++) {
                int c = wn + ni * 8 + gid;
                b[ni][0] = Bb[(ks + tg) * BPAD + c];
                b[ni][1] = Bb[(ks + tg + 4) * BPAD + c];
            }
#pragma unroll
            for (int mi = 0; mi < 4; mi++)
#pragma unroll
                for (int ni = 0; ni < 4; ni++)
                    mma_tf32(acc[mi][ni], a[mi][0], a[mi][1], a[mi][2], a[mi][3],
                             b[ni][0], b[ni][1]);
        }
        __syncthreads();
    }
    // epilogue: bias + relu -> tf32 bits (gemm2's A path then needs no CVT)
#pragma unroll
    for (int mi = 0; mi < 4; mi++) {
        size_t r0 = row0 + wm + mi * 16 + gid;
        size_t r1 = r0 + 8;
#pragma unroll
        for (int ni = 0; ni < 4; ni++) {
            int col = n0 + wn + ni * 8 + 2 * tg;
            float bi0 = b1[col], bi1 = b1[col + 1];
            uint2 o0, o1;
            o0.x = f2tf(fmaxf(acc[mi][ni][0] + bi0, 0.f));
            o0.y = f2tf(fmaxf(acc[mi][ni][1] + bi1, 0.f));
            o1.x = f2tf(fmaxf(acc[mi][ni][2] + bi0, 0.f));
            o1.y = f2tf(fmaxf(acc[mi][ni][3] + bi1, 0.f));
            *(uint2*)(g_act + r0 * H2 + col) = o0;
            *(uint2*)(g_act + r1 * H2 + col) = o1;
        }
    }
#undef G1_ISSUE
}

// ---------------- K2: x = act @ W2 + b2 + embed[seq]   M=16384 N=1024 K=2048 ----------------
__global__ __launch_bounds__(256) void gemm2_kernel(const int* __restrict__ seq,
                                                    const float* __restrict__ embed,
                                                    const float* __restrict__ b2) {
    extern __shared__ unsigned dsm[];
    unsigned* Asm = dsm;
    unsigned* Bsm = dsm + NSTAGE * ASZ;
    __shared__ int srow[128];
    const int tid = threadIdx.x;
    const int n0 = blockIdx.x * 128;
    const int row0 = blockIdx.y * 128;
    if (tid < 128) srow[tid] = seq[row0 + tid] * DD;
    __syncthreads();
    const int lane = tid & 31, warp = tid >> 5;
    const int wm = (warp & 1) * 64, wn = (warp >> 1) * 32;
    const int gid = lane >> 2, tg = lane & 3;
    const int NT = H2 / 32;

#define G2_ISSUE(kt, st) do {                                                   \
        const int k0 = (kt) * 32;                                               \
        unsigned* Ad = Asm + (st) * ASZ;                                        \
        unsigned* Bd = Bsm + (st) * BSZ;                                        \
        _Pragma("unroll")                                                       \
        for (int l = 0; l < 4; l++) {                                           \
            int f4 = tid + l * 256;                                             \
            int r = f4 >> 3, kq = f4 & 7;                                       \
            CPA16(sptr(Ad + r * APAD + kq * 4),                                 \
                  g_act + (size_t)(row0 + r) * H2 + k0 + kq * 4);               \
        }                                                                       \
        _Pragma("unroll")                                                       \
        for (int l = 0; l < 4; l++) {                                           \
            int f4 = tid + l * 256;                                             \
            int kr = f4 >> 5, c4 = (f4 & 31) * 4;                               \
            CPA16(sptr(Bd + kr * BPAD + c4),                                    \
                  g_w2r + (size_t)(k0 + kr) * DD + n0 + c4);                    \
        }                                                                       \
        CPA_COMMIT();                                                           \
    } while (0)

    float acc[4][4][4];
#pragma unroll
    for (int mi = 0; mi < 4; mi++)
#pragma unroll
        for (int ni = 0; ni < 4; ni++)
#pragma unroll
            for (int r = 0; r < 4; r++) acc[mi][ni][r] = 0.f;

    G2_ISSUE(0, 0);
    G2_ISSUE(1, 1);

    for (int kt = 0; kt < NT; kt++) {
        if (kt + 1 < NT) { CPA_WAIT1(); } else { CPA_WAIT0(); }
        __syncthreads();
        if (kt + 2 < NT) G2_ISSUE(kt + 2, (kt + 2) % NSTAGE);
        const unsigned* Ab = Asm + (kt % NSTAGE) * ASZ;
        const unsigned* Bb = Bsm + (kt % NSTAGE) * BSZ;
#pragma unroll
        for (int ks = 0; ks < 32; ks += 8) {
            unsigned a[4][4], b[4][2];
#pragma unroll
            for (int mi = 0; mi < 4; mi++) {
                int mb = (wm + mi * 16 + gid) * APAD;
                a[mi][0] = Ab[mb + ks + tg];
                a[mi][1] = Ab[mb + 8 * APAD + ks + tg];
                a[mi][2] = Ab[mb + ks + tg + 4];
                a[mi][3] = Ab[mb + 8 * APAD + ks + tg + 4];
            }
#pragma unroll
            for (int ni = 0; ni < 4; ni++) {
                int c = wn + ni * 8 + gid;
                b[ni][0] = Bb[(ks + tg) * BPAD + c];
                b[ni][1] = Bb[(ks + tg + 4) * BPAD + c];
            }
#pragma unroll
            for (int mi = 0; mi < 4; mi++)
#pragma unroll
                for (int ni = 0; ni < 4; ni++)
                    mma_tf32(acc[mi][ni], a[mi][0], a[mi][1], a[mi][2], a[mi][3],
                             b[ni][0], b[ni][1]);
        }
        __syncthreads();
    }
    // epilogue: bias + gathered embedding residual (fp32)
#pragma unroll
    for (int mi = 0; mi < 4; mi++) {
        int lr0 = wm + mi * 16 + gid;
        int lr1 = lr0 + 8;
        size_t r0 = (size_t)(row0 + lr0);
        size_t r1 = (size_t)(row0 + lr1);
#pragma unroll
        for (int ni = 0; ni < 4; ni++) {
            int col = n0 + wn + ni * 8 + 2 * tg;
            float bi0 = b2[col], bi1 = b2[col + 1];
            float2 h0 = *(const float2*)(embed + (size_t)srow[lr0] + col);
            float2 h1 = *(const float2*)(embed + (size_t)srow[lr1] + col);
            float2 o0, o1;
            o0.x = acc[mi][ni][0] + bi0 + h0.x;
            o0.y = acc[mi][ni][1] + bi1 + h0.y;
            o1.x = acc[mi][ni][2] + bi0 + h1.x;
            o1.y = acc[mi][ni][3] + bi1 + h1.y;
            *(float2*)(g_x + r0 * DD + col) = o0;
            *(float2*)(g_x + r1 * DD + col) = o1;
        }
    }
#undef G2_ISSUE
}

// ---------------- K3: LayerNorm + slot_imp + query extraction ----------------
__global__ __launch_bounds__(256) void ln_kernel(
    const float* __restrict__ ln_g, const float* __restrict__ ln_b) {
    const int token = blockIdx.x;
    const int tid = threadIdx.x;
    const float4 x4 = *(const float4*)(g_x + (size_t)token * DD + tid * 4);
    float s = x4.x + x4.y + x4.z + x4.w;
    float sq = x4.x * x4.x + x4.y * x4.y + x4.z * x4.z + x4.w * x4.w;
    __shared__ float sh1[8], sh2[8];
    const int w = tid >> 5, l = tid & 31;
    s = warp_sum(s);
    sq = warp_sum(sq);
    if (l == 0) { sh1[w] = s; sh2[w] = sq; }
    __syncthreads();
    float ts = 0.f, tq = 0.f;
#pragma unroll
    for (int i = 0; i < 8; i++) { ts += sh1[i]; tq += sh2[i]; }
    const float mu = ts * (1.f / 1024.f);
    const float var = tq * (1.f / 1024.f) - mu * mu;
    const float rstd = rsqrtf(var + 1e-5f);
    const float4 g4 = *(const float4*)(ln_g + tid * 4);
    const float4 b4 = *(const float4*)(ln_b + tid * 4);
    float4 h4;
    h4.x = (x4.x - mu) * rstd * g4.x + b4.x;
    h4.y = (x4.y - mu) * rstd * g4.y + b4.y;
    h4.z = (x4.z - mu) * rstd * g4.z + b4.z;
    h4.w = (x4.w - mu) * rstd * g4.w + b4.w;
    *(float4*)(g_hidden + (size_t)token * DD + tid * 4) = h4;
    const float4 wb = *(const float4*)(g_wbar + tid * 4);
    float wd = h4.x * wb.x + h4.y * wb.y + h4.z * wb.z + h4.w * wb.w;
    wd = warp_sum(wd);
    __syncthreads();
    if (l == 0) sh1[w] = wd;
    __syncthreads();
    if (tid == 0) {
        float t2 = 0.f;
#pragma unroll
        for (int i = 0; i < 8; i++) t2 += sh1[i];
        g_slot[token] = t2;   // constant offset (mean wg_b) omitted: rank-invariant
    }
    if ((token & (TT - 1)) == TT - 1) {
        int bidx = token >> 9;
        *(float4*)(g_query + bidx * DD + tid * 4) = h4;
    }
}

// ---------------- K4: top-k selection + memory assembly ----------------
__global__ __launch_bounds__(256) void select_kernel(const float* __restrict__ memory) {
    const int b = blockIdx.x, tid = threadIdx.x;
    __shared__ float imp[512];
    __shared__ int idx[6];
    for (int t = tid; t < TT - 1; t += 256) imp[t] = g_slot[b * TT + t];
    __syncthreads();
    if (tid == 0) {
#pragma unroll
        for (int r = 0; r < 4; r++) {       // fwd top-4 (desc, stable)
            float best = -1e30f; int bi = 0;
            for (int t = 0; t < TT - 1; t++)
                if (imp[t] > best) { best = imp[t]; bi = t; }
            idx[r] = bi;
            imp[bi] = -3.0e38f;
        }
#pragma unroll
        for (int r = 0; r < 2; r++) {       // rev top-2 over first 8, masked
            float best = -1e30f; int bi = 0;
            for (int t = 0; t < 8; t++)
                if (imp[t] > best) { best = imp[t]; bi = t; }
            idx[4 + r] = bi;
            imp[bi] = -3.0e38f;
        }
    }
    __syncthreads();
    for (int s = 0; s < SS; s++) {
        const float* src = (s < 6)
            ? (g_hidden + (size_t)(b * TT + idx[s]) * DD)
            : (memory + (size_t)s * DD);
        *(float4*)(g_mem + (size_t)(b * SS + s) * DD + tid * 4) =
            *(const float4*)(src + tid * 4);
    }
}

// ---------------- conf-side vocab GEMM (tf32 mma): g_dl = Q @ out_w + out_b ----------------
// Output feeds ONLY the conf decision (margin ~0.8 vs ~2e-4): tf32 rounding is safe.
// Tail: v0 clamped to VOCAB-128; overlap cols written twice with identical values.
__global__ __launch_bounds__(256) void conf_logits_kernel(
    const float* __restrict__ W, const float* __restrict__ bias) {
    __shared__ unsigned As[2][32 * APAD];
    __shared__ unsigned Bs[2][32 * BPAD];
    const int tid = threadIdx.x, warp = tid >> 5, lane = tid & 31;
    const int gid = lane >> 2, tg = lane & 3;
    const int wn = warp * 16;
    int v0 = blockIdx.x * 128;
    if (v0 > VOCAB - 128) v0 = VOCAB - 128;

    const int ar = tid >> 3, akq = tid & 7;   // A: row 0..31, k-quad 0..7
    const int bkr = warp, bc4 = lane * 4;     // B: base k-row 0..7, col*4

    float4 aR;
    float bR[16];

#define CLQ_LOAD(kt) do {                                                       \
        const int k0q = (kt) * 32;                                              \
        aR = *(const float4*)(g_query + ar * DD + k0q + akq * 4);               \
        _Pragma("unroll")                                                       \
        for (int o = 0; o < 4; o++) {                                           \
            const float* wp = W + (size_t)(k0q + bkr + o * 8) * VOCAB + v0 + bc4; \
            bR[o * 4 + 0] = wp[0]; bR[o * 4 + 1] = wp[1];                       \
            bR[o * 4 + 2] = wp[2]; bR[o * 4 + 3] = wp[3];                       \
        }                                                                       \
    } while (0)
#define CLQ_STORE(buf) do {                                                     \
        unsigned* Ad = As[buf]; unsigned* Bd = Bs[buf];                         \
        uint4 ta;                                                               \
        ta.x = __float_as_uint(aR.x); ta.y = __float_as_uint(aR.y);             \
        ta.z = __float_as_uint(aR.z); ta.w = __float_as_uint(aR.w);             \
        *(uint4*)&Ad[ar * APAD + akq * 4] = ta;                                 \
        _Pragma("unroll")                                                       \
        for (int o = 0; o < 4; o++) {                                           \
            uint4 tb;                                                           \
            tb.x = __float_as_uint(bR[o * 4 + 0]);                              \
            tb.y = __float_as_uint(bR[o * 4 + 1]);                              \
            tb.z = __float_as_uint(bR[o * 4 + 2]);                              \
            tb.w = __float_as_uint(bR[o * 4 + 3]);                              \
            *(uint4*)&Bd[(bkr + o * 8) * BPAD + bc4] = tb;                      \
        }                                                                       \
    } while (0)

    float acc[2][2][4];
#pragma unroll
    for (int mi = 0; mi < 2; mi++)
#pragma unroll
        for (int ni = 0; ni < 2; ni++)
#pragma unroll
            for (int r = 0; r < 4; r++) acc[mi][ni][r] = 0.f;

    CLQ_LOAD(0);
    CLQ_STORE(0);
    for (int kt = 0; kt < 32; kt++) {
        __syncthreads();
        if (kt + 1 < 32) CLQ_LOAD(kt + 1);
        const unsigned* Ab = As[kt & 1];
        const unsigned* Bb = Bs[kt & 1];
#pragma unroll
        for (int ks = 0; ks < 32; ks += 8) {
            unsigned a[2][4], b[2][2];
#pragma unroll
            for (int mi = 0; mi < 2; mi++) {
                int mb = (mi * 16 + gid) * APAD;
                a[mi][0] = f2tf(__uint_as_float(Ab[mb + ks + tg]));
                a[mi][1] = f2tf(__uint_as_float(Ab[mb + 8 * APAD + ks + tg]));
                a[mi][2] = f2tf(__uint_as_float(Ab[mb + ks + tg + 4]));
                a[mi][3] = f2tf(__uint_as_float(Ab[mb + 8 * APAD + ks + tg + 4]));
            }
#pragma unroll
            for (int ni = 0; ni < 2; ni++) {
                int c = wn + ni * 8 + gid;
                b[ni][0] = f2tf(__uint_as_float(Bb[(ks + tg) * BPAD + c]));
                b[ni][1] = f2tf(__uint_as_float(Bb[(ks + tg + 4) * BPAD + c]));
            }
#pragma unroll
            for (int mi = 0; mi < 2; mi++)
#pragma unroll
                for (int ni = 0; ni < 2; ni++)
                    mma_tf32(acc[mi][ni], a[mi][0], a[mi][1], a[mi][2], a[mi][3],
                             b[ni][0], b[ni][1]);
        }
        if (kt + 1 < 32) CLQ_STORE((kt + 1) & 1);
    }
#pragma unroll
    for (int mi = 0; mi < 2; mi++) {
        int m0 = mi * 16 + gid;
#pragma unroll
        for (int ni = 0; ni < 2; ni++) {
            int vc = v0 + wn + ni * 8 + 2 * tg;
            float bi0 = bias[vc], bi1 = bias[vc + 1];
            g_dl[(size_t)m0 * VOCAB + vc]           = acc[mi][ni][0] + bi0;
            g_dl[(size_t)m0 * VOCAB + vc + 1]       = acc[mi][ni][1] + bi1;
            g_dl[(size_t)(m0 + 8) * VOCAB + vc]     = acc[mi][ni][2] + bi0;
            g_dl[(size_t)(m0 + 8) * VOCAB + vc + 1] = acc[mi][ni][3] + bi1;
        }
    }
#undef CLQ_LOAD
#undef CLQ_STORE
}

// ---------------- K9: final vocab GEMM (fp32, feeds OUTPUT -> keep full precision) ----------------
__global__ __launch_bounds__(256) void logits_kernel(
    const float* __restrict__ W, const float* __restrict__ bias,
    float* __restrict__ out) {
    const float* __restrict__ Q = g_ctx;
    const int tid = threadIdx.x;
    const int tv = tid & 31, bg = tid >> 5;
    const int v0 = blockIdx.x * 128 + tv * 4;
    __shared__ float Qs[32][128];
    float acc[4][4];
#pragma unroll
    for (int u = 0; u < 4; u++)
#pragma unroll
        for (int j = 0; j < 4; j++) acc[u][j] = 0.f;
    const bool full = (v0 + 4 <= VOCAB);

    for (int k0 = 0; k0 < DD; k0 += 128) {
#pragma unroll
        for (int l2 = 0; l2 < 4; l2++) {
            int f4 = tid + l2 * 256;
            int bb = f4 >> 5, dq = f4 & 31;
            *(float4*)&Qs[bb][dq * 4] =
                *(const float4*)(Q + bb * DD + k0 + dq * 4);
        }
        __syncthreads();
        if (full) {
            const float* wp = W + (size_t)k0 * VOCAB + v0;
#pragma unroll 2
            for (int d = 0; d < 128; d++) {
                const float w0 = wp[0], w1 = wp[1], w2 = wp[2], w3 = wp[3];
#pragma unroll
                for (int u = 0; u < 4; u++) {
                    const float q = Qs[bg * 4 + u][d];
                    acc[u][0] += q * w0; acc[u][1] += q * w1;
                    acc[u][2] += q * w2; acc[u][3] += q * w3;
                }
                wp += VOCAB;
            }
        } else if (v0 < VOCAB) {
            for (int d = 0; d < 128; d++) {
                const float* wp = W + (size_t)(k0 + d) * VOCAB;
#pragma unroll
                for (int j = 0; j < 4; j++) {
                    int v = v0 + j;
                    if (v < VOCAB) {
                        const float wv = wp[v];
#pragma unroll
                        for (int u = 0; u < 4; u++)
                            acc[u][j] += Qs[bg * 4 + u][d] * wv;
                    }
                }
            }
        }
        __syncthreads();
    }
#pragma unroll
    for (int u = 0; u < 4; u++) {
        const int bidx = bg * 4 + u;
#pragma unroll
        for (int j = 0; j < 4; j++) {
            int v = v0 + j;
            if (v < VOCAB) out[(size_t)bidx * VOCAB + v] = acc[u][j] + bias[v];
        }
    }
}

// ---------------- K6: conf = 1/sumexp(direct_logits - max) -> use_mem flag ----------------
__global__ __launch_bounds__(256) void conf_kernel() {
    const int b = blockIdx.x, tid = threadIdx.x;
    const float* row = g_dl + (size_t)b * VOCAB;
    float m = -3.0e38f;
    for (int v = tid; v < VOCAB; v += 256) m = fmaxf(m, row[v]);
    __shared__ float sh[8];
#pragma unroll
    for (int o = 16; o > 0; o >>= 1) m = fmaxf(m, __shfl_xor_sync(0xffffffffu, m, o));
    if ((tid & 31) == 0) sh[tid >> 5] = m;
    __syncthreads();
    float bm = sh[0];
#pragma unroll
    for (int i = 1; i < 8; i++) bm = fmaxf(bm, sh[i]);
    float ssum = 0.f;
    for (int v = tid; v < VOCAB; v += 256) ssum += expf(row[v] - bm);
    ssum = warp_sum(ssum);
    __syncthreads();
    if ((tid & 31) == 0) sh[tid >> 5] = ssum;
    __syncthreads();
    if (tid == 0) {
        float t = 0.f;
#pragma unroll
        for (int i = 0; i < 8; i++) t += sh[i];
        const float conf = 1.f / t;
        g_use[b] = (conf < 0.8f) ? 1.f : 0.f;
    }
}

// ---------------- K7: q = query @ rp_w + rp_b ----------------
__global__ __launch_bounds__(256) void rp_kernel(
    const float* __restrict__ rp_w, const float* __restrict__ rp_b) {
    const int b = blockIdx.x, tid = threadIdx.x;
    __shared__ __align__(16) float qs[DD];
    *(float4*)&qs[tid * 4] = *(const float4*)(g_query + b * DD + tid * 4);
    __syncthreads();
    float acc0 = 0.f, acc1 = 0.f, acc2 = 0.f, acc3 = 0.f;
    for (int d = 0; d < DD; d++) {
        const float q = qs[d];
        const float* wr = rp_w + (size_t)d * DD + tid;
        acc0 += q * wr[0];
        acc1 += q * wr[256];
        acc2 += q * wr[512];
        acc3 += q * wr[768];
    }
    g_q[b * DD + tid +   0] = acc0 + rp_b[tid +   0];
    g_q[b * DD + tid + 256] = acc1 + rp_b[tid + 256];
    g_q[b * DD + tid + 512] = acc2 + rp_b[tid + 512];
    g_q[b * DD + tid + 768] = acc3 + rp_b[tid + 768];
}

// ---------------- K8: scores -> softmax -> ctx -> blend ----------------
__global__ __launch_bounds__(256) void attn_kernel() {
    const int b = blockIdx.x, tid = threadIdx.x;
    __shared__ __align__(16) float qs[DD];
    __shared__ float sh[8];
    __shared__ float scores[SS];
    __shared__ float attn[SS];
    *(float4*)&qs[tid * 4] = *(const float4*)(g_q + b * DD + tid * 4);
    __syncthreads();
    for (int s = 0; s < SS; s++) {
        const float4 m4 = *(const float4*)(g_mem + (size_t)(b * SS + s) * DD + tid * 4);
        const float4 q4 = *(const float4*)&qs[tid * 4];
        float p = m4.x * q4.x + m4.y * q4.y + m4.z * q4.z + m4.w * q4.w;
        p = warp_sum(p);
        if ((tid & 31) == 0) sh[tid >> 5] = p;
        __syncthreads();
        if (tid == 0) {
            float t = 0.f;
#pragma unroll
            for (int i = 0; i < 8; i++) t += sh[i];
            scores[s] = t;
        }
        __syncthreads();
    }
    if (tid == 0) {
        float m = scores[0];
        for (int s = 1; s < SS; s++) m = fmaxf(m, scores[s]);
        float sum = 0.f;
        for (int s = 0; s < SS; s++) { float e = expf(scores[s] - m); attn[s] = e; sum += e; }
        const float inv = 1.f / sum;
        for (int s = 0; s < SS; s++) attn[s] *= inv;
    }
    __syncthreads();
    float c0 = 0.f, c1 = 0.f, c2 = 0.f, c3 = 0.f;
#pragma unroll
    for (int s = 0; s < SS; s++) {
        const float a = attn[s];
        const float4 m4 = *(const float4*)(g_mem + (size_t)(b * SS + s) * DD + tid * 4);
        c0 += a * m4.x; c1 += a * m4.y; c2 += a * m4.z; c3 += a * m4.w;
    }
    const float use = g_use[b];
    const float4 qv = *(const float4*)(g_query + b * DD + tid * 4);
    float4 o;
    o.x = c0 * use + qv.x * (1.f - use);
    o.y = c1 * use + qv.y * (1.f - use);
    o.z = c2 * use + qv.z * (1.f - use);
    o.w = c3 * use + qv.w * (1.f - use);
    *(float4*)(g_ctx + b * DD + tid * 4) = o;
}

// ---------------- launch ----------------
extern "C" void kernel_launch(void* const* d_in, const int* in_sizes, int n_in,
                              void* d_out, int out_size) {
    const int*   seq    = (const int*)  d_in[0];
    const float* embed  = (const float*)d_in[1];
    const float* ff_w1  = (const float*)d_in[2];
    const float* ff_b1  = (const float*)d_in[3];
    const float* ff_w2  = (const float*)d_in[4];
    const float* ff_b2  = (const float*)d_in[5];
    const float* ln_g   = (const float*)d_in[6];
    const float* ln_b   = (const float*)d_in[7];
    const float* wg_w   = (const float*)d_in[8];
    // d_in[9] = wg_b: constant shift of slot_imp, rank-invariant -> unused
    const float* rp_w   = (const float*)d_in[10];
    const float* rp_b   = (const float*)d_in[11];
    const float* out_w  = (const float*)d_in[12];
    const float* out_b  = (const float*)d_in[13];
    const float* memory = (const float*)d_in[14];
    float* out = (float*)d_out;

    cudaFuncSetAttribute(gemm1_kernel, cudaFuncAttributeMaxDynamicSharedMemorySize, GEMM_SMEM);
    cudaFuncSetAttribute(gemm2_kernel, cudaFuncAttributeMaxDynamicSharedMemorySize, GEMM_SMEM);

    wbar_kernel<<<4, 256>>>(wg_w);
    round_w1<<<(DD * H2 / 4) / 256, 256>>>(ff_w1);
    round_w2<<<(DD * H2 / 4) / 256, 256>>>(ff_w2);
    htf_kernel<<<BT, 256>>>(seq, embed);
    gemm1_kernel<<<dim3(16, 128), 256, GEMM_SMEM>>>(ff_b1);
    gemm2_kernel<<<dim3(8, 128), 256, GEMM_SMEM>>>(seq, embed, ff_b2);
    ln_kernel<<<BT, 256>>>(ln_g, ln_b);
    select_kernel<<<BB, 256>>>(memory);
    conf_logits_kernel<<<(VOCAB + 127) / 128, 256>>>(out_w, out_b);
    conf_kernel<<<BB, 256>>>();
    rp_kernel<<<BB, 256>>>(rp_w, rp_b);
    attn_kernel<<<BB, 256>>>();
    logits_kernel<<<(VOCAB + 127) / 128, 256>>>(out_w, out_b, out);
}

// round 12
// speedup vs baseline: 3.3511x; 1.3440x over previous
#include <cuda_runtime.h>
#include <math.h>

#define BB 32
#define TT 512
#define DD 1024
#define VOCAB 50257
#define SS 16
#define BT (BB*TT)
#define H2 2048

// ---------------- scratch (static device globals; no allocation) ----------------
// NOTE: device globals are ONLY referenced inside device code (never passed as
// kernel arguments from host — host shadow address + GB300 ATS silently breaks that).
__device__ unsigned g_act[(size_t)BT * H2];    // relu(h@W1+b1) tf32 bits 128 MB
__device__ unsigned g_htf[(size_t)BT * DD];    // rna(embed[seq]) bits     64 MB
__device__ unsigned g_w1r[(size_t)DD * H2];    // rna(W1) bits              8 MB
__device__ unsigned g_w2r[(size_t)H2 * DD];    // rna(W2) bits              8 MB
__device__ float g_x[(size_t)BT * DD];         // h + ff                   64 MB
__device__ float g_hidden[(size_t)BT * DD];    // LN output                64 MB
__device__ float g_slot[BT];
__device__ float g_wbar[DD];
__device__ float g_query[BB * DD];
__device__ float g_mem[BB * SS * DD];
__device__ float g_dl[(size_t)BB * VOCAB];
__device__ float g_use[BB];
__device__ float g_q[BB * DD];
__device__ float g_ctx[BB * DD];

__device__ __forceinline__ float warp_sum(float v) {
#pragma unroll
    for (int o = 16; o > 0; o >>= 1) v += __shfl_xor_sync(0xffffffffu, v, o);
    return v;
}
__device__ __forceinline__ unsigned f2tf(float x) {
    unsigned u;
    asm("cvt.rna.tf32.f32 %0, %1;" : "=r"(u) : "f"(x));
    return u;
}
__device__ __forceinline__ void mma_tf32(float* c,
    unsigned a0, unsigned a1, unsigned a2, unsigned a3,
    unsigned b0, unsigned b1) {
    asm volatile(
        "mma.sync.aligned.m16n8k8.row.col.f32.tf32.tf32.f32 "
        "{%0,%1,%2,%3}, {%4,%5,%6,%7}, {%8,%9}, {%0,%1,%2,%3};"
        : "+f"(c[0]), "+f"(c[1]), "+f"(c[2]), "+f"(c[3])
        : "r"(a0), "r"(a1), "r"(a2), "r"(a3), "r"(b0), "r"(b1));
}
__device__ __forceinline__ unsigned sptr(const void* p) {
    return (unsigned)__cvta_generic_to_shared(p);
}
#define CPA16(dst_u32, src_ptr) \
    asm volatile("cp.async.cg.shared.global [%0], [%1], 16;" :: "r"(dst_u32), "l"(src_ptr))
#define CPA_COMMIT() asm volatile("cp.async.commit_group;")
#define CPA_WAIT1()  asm volatile("cp.async.wait_group 1;")
#define CPA_WAIT0()  asm volatile("cp.async.wait_group 0;")

// A smem: [128 rows][36 words]  (pad 36 ≡ 4 mod 32 -> conflict-free, 16B rows)
// B smem: [32 k][136 words]     (pad 136 ≡ 8 mod 32 -> conflict-free, 16B rows)
#define APAD 36
#define BPAD 136
#define ASZ (128 * APAD)
#define BSZ (32 * BPAD)
#define NSTAGE 3
#define GEMM_SMEM (NSTAGE * (ASZ + BSZ) * 4)

// ---------------- K0: wbar = mean_s wg_w ----------------
__global__ void wbar_kernel(const float* __restrict__ wg_w) {
    int d = blockIdx.x * blockDim.x + threadIdx.x;
    if (d < DD) {
        float s = 0.f;
#pragma unroll
        for (int j = 0; j < SS; j++) s += wg_w[d * SS + j];
        g_wbar[d] = s * (1.f / 16.f);
    }
}

// ---------------- prep: RNA round weights to tf32 bits ----------------
__global__ __launch_bounds__(256) void round_w1(const float* __restrict__ src) {
    size_t i = ((size_t)blockIdx.x * 256 + threadIdx.x) * 4;
    float4 v = *(const float4*)(src + i);
    uint4 o;
    o.x = f2tf(v.x); o.y = f2tf(v.y); o.z = f2tf(v.z); o.w = f2tf(v.w);
    *(uint4*)(g_w1r + i) = o;
}
__global__ __launch_bounds__(256) void round_w2(const float* __restrict__ src) {
    size_t i = ((size_t)blockIdx.x * 256 + threadIdx.x) * 4;
    float4 v = *(const float4*)(src + i);
    uint4 o;
    o.x = f2tf(v.x); o.y = f2tf(v.y); o.z = f2tf(v.z); o.w = f2tf(v.w);
    *(uint4*)(g_w2r + i) = o;
}

// ---------------- prep: g_htf = rna(embed[seq]) ----------------
__global__ __launch_bounds__(256) void htf_kernel(const int* __restrict__ seq,
                                                  const float* __restrict__ embed) {
    const int t = blockIdx.x;
    const int off = threadIdx.x * 4;
    const size_t erow = (size_t)seq[t] * DD;
    float4 v = *(const float4*)(embed + erow + off);
    uint4 o;
    o.x = f2tf(v.x); o.y = f2tf(v.y); o.z = f2tf(v.z); o.w = f2tf(v.w);
    *(uint4*)(g_htf + (size_t)t * DD + off) = o;
}

// fragment load / mma step macros (shared layout between gemm1/gemm2)
#define LOADF(buf, ks) do {                                                     \
        _Pragma("unroll")                                                       \
        for (int mi = 0; mi < 4; mi++) {                                        \
            int mb = (wm + mi * 16 + gid) * APAD;                               \
            af[buf][mi][0] = Ab[mb + (ks) * 8 + tg];                            \
            af[buf][mi][1] = Ab[mb + 8 * APAD + (ks) * 8 + tg];                 \
            af[buf][mi][2] = Ab[mb + (ks) * 8 + tg + 4];                        \
            af[buf][mi][3] = Ab[mb + 8 * APAD + (ks) * 8 + tg + 4];             \
        }                                                                       \
        _Pragma("unroll")                                                       \
        for (int ni = 0; ni < 4; ni++) {                                        \
            int c = wn + ni * 8 + gid;                                          \
            bf[buf][ni][0] = Bb[((ks) * 8 + tg) * BPAD + c];                    \
            bf[buf][ni][1] = Bb[((ks) * 8 + tg + 4) * BPAD + c];                \
        }                                                                       \
    } while (0)
#define MMAS(buf) do {                                                          \
        _Pragma("unroll")                                                       \
        for (int mi = 0; mi < 4; mi++)                                          \
        _Pragma("unroll")                                                       \
        for (int ni = 0; ni < 4; ni++)                                          \
            mma_tf32(acc[mi][ni],                                               \
                     af[buf][mi][0], af[buf][mi][1], af[buf][mi][2], af[buf][mi][3], \
                     bf[buf][ni][0], bf[buf][ni][1]);                           \
    } while (0)

// ---------------- K1: g_act = tf32bits(relu(h @ W1 + b1))  M=16384 N=2048 K=1024 ----------------
__global__ __launch_bounds__(256) void gemm1_kernel(const float* __restrict__ b1) {
    extern __shared__ unsigned dsm[];
    unsigned* Asm = dsm;                    // [NSTAGE][ASZ]
    unsigned* Bsm = dsm + NSTAGE * ASZ;     // [NSTAGE][BSZ]
    const int tid = threadIdx.x;
    const int n0 = blockIdx.x * 128;
    const size_t row0 = (size_t)blockIdx.y * 128;
    const int lane = tid & 31, warp = tid >> 5;
    const int wm = (warp & 1) * 64, wn = (warp >> 1) * 32;
    const int gid = lane >> 2, tg = lane & 3;
    const int NT = DD / 32;

#define G1_ISSUE(kt, st) do {                                                   \
        const int k0 = (kt) * 32;                                               \
        unsigned* Ad = Asm + (st) * ASZ;                                        \
        unsigned* Bd = Bsm + (st) * BSZ;                                        \
        _Pragma("unroll")                                                       \
        for (int l = 0; l < 4; l++) {                                           \
            int f4 = tid + l * 256;                                             \
            int r = f4 >> 3, kq = f4 & 7;                                       \
            CPA16(sptr(Ad + r * APAD + kq * 4),                                 \
                  g_htf + (row0 + r) * DD + k0 + kq * 4);                       \
        }                                                                       \
        _Pragma("unroll")                                                       \
        for (int l = 0; l < 4; l++) {                                           \
            int f4 = tid + l * 256;                                             \
            int kr = f4 >> 5, c4 = (f4 & 31) * 4;                               \
            CPA16(sptr(Bd + kr * BPAD + c4),                                    \
                  g_w1r + (size_t)(k0 + kr) * H2 + n0 + c4);                    \
        }                                                                       \
        CPA_COMMIT();                                                           \
    } while (0)

    float acc[4][4][4];
#pragma unroll
    for (int mi = 0; mi < 4; mi++)
#pragma unroll
        for (int ni = 0; ni < 4; ni++)
#pragma unroll
            for (int r = 0; r < 4; r++) acc[mi][ni][r] = 0.f;

    unsigned af[2][4][4], bf[2][4][2];

    G1_ISSUE(0, 0);
    G1_ISSUE(1, 1);

    for (int kt = 0; kt < NT; kt++) {
        if (kt + 1 < NT) { CPA_WAIT1(); } else { CPA_WAIT0(); }
        __syncthreads();
        const unsigned* Ab = Asm + (kt % NSTAGE) * ASZ;
        const unsigned* Bb = Bsm + (kt % NSTAGE) * BSZ;
        LOADF(0, 0);                               // start LDS before cp.async burst
        if (kt + 2 < NT) G1_ISSUE(kt + 2, (kt + 2) % NSTAGE);
#pragma unroll
        for (int ks = 0; ks < 4; ks++) {
            if (ks < 3) LOADF((ks + 1) & 1, ks + 1);   // prefetch next step's frags
            MMAS(ks & 1);
        }
        __syncthreads();
    }
    // epilogue: bias + relu -> tf32 bits (gemm2's A path then needs no CVT)
#pragma unroll
    for (int mi = 0; mi < 4; mi++) {
        size_t r0 = row0 + wm + mi * 16 + gid;
        size_t r1 = r0 + 8;
#pragma unroll
        for (int ni = 0; ni < 4; ni++) {
            int col = n0 + wn + ni * 8 + 2 * tg;
            float bi0 = b1[col], bi1 = b1[col + 1];
            uint2 o0, o1;
            o0.x = f2tf(fmaxf(acc[mi][ni][0] + bi0, 0.f));
            o0.y = f2tf(fmaxf(acc[mi][ni][1] + bi1, 0.f));
            o1.x = f2tf(fmaxf(acc[mi][ni][2] + bi0, 0.f));
            o1.y = f2tf(fmaxf(acc[mi][ni][3] + bi1, 0.f));
            *(uint2*)(g_act + r0 * H2 + col) = o0;
            *(uint2*)(g_act + r1 * H2 + col) = o1;
        }
    }
#undef G1_ISSUE
}

// ---------------- K2: x = act @ W2 + b2 + embed[seq]   M=16384 N=1024 K=2048 ----------------
__global__ __launch_bounds__(256) void gemm2_kernel(const int* __restrict__ seq,
                                                    const float* __restrict__ embed,
                                                    const float* __restrict__ b2) {
    extern __shared__ unsigned dsm[];
    unsigned* Asm = dsm;
    unsigned* Bsm = dsm + NSTAGE * ASZ;
    __shared__ int srow[128];
    const int tid = threadIdx.x;
    const int n0 = blockIdx.x * 128;
    const int row0 = blockIdx.y * 128;
    if (tid < 128) srow[tid] = seq[row0 + tid] * DD;
    __syncthreads();
    const int lane = tid & 31, warp = tid >> 5;
    const int wm = (warp & 1) * 64, wn = (warp >> 1) * 32;
    const int gid = lane >> 2, tg = lane & 3;
    const int NT = H2 / 32;

#define G2_ISSUE(kt, st) do {                                                   \
        const int k0 = (kt) * 32;                                               \
        unsigned* Ad = Asm + (st) * ASZ;                                        \
        unsigned* Bd = Bsm + (st) * BSZ;                                        \
        _Pragma("unroll")                                                       \
        for (int l = 0; l < 4; l++) {                                           \
            int f4 = tid + l * 256;                                             \
            int r = f4 >> 3, kq = f4 & 7;                                       \
            CPA16(sptr(Ad + r * APAD + kq * 4),                                 \
                  g_act + (size_t)(row0 + r) * H2 + k0 + kq * 4);               \
        }                                                                       \
        _Pragma("unroll")                                                       \
        for (int l = 0; l < 4; l++) {                                           \
            int f4 = tid + l * 256;                                             \
            int kr = f4 >> 5, c4 = (f4 & 31) * 4;                               \
            CPA16(sptr(Bd + kr * BPAD + c4),                                    \
                  g_w2r + (size_t)(k0 + kr) * DD + n0 + c4);                    \
        }                                                                       \
        CPA_COMMIT();                                                           \
    } while (0)

    float acc[4][4][4];
#pragma unroll
    for (int mi = 0; mi < 4; mi++)
#pragma unroll
        for (int ni = 0; ni < 4; ni++)
#pragma unroll
            for (int r = 0; r < 4; r++) acc[mi][ni][r] = 0.f;

    unsigned af[2][4][4], bf[2][4][2];

    G2_ISSUE(0, 0);
    G2_ISSUE(1, 1);

    for (int kt = 0; kt < NT; kt++) {
        if (kt + 1 < NT) { CPA_WAIT1(); } else { CPA_WAIT0(); }
        __syncthreads();
        const unsigned* Ab = Asm + (kt % NSTAGE) * ASZ;
        const unsigned* Bb = Bsm + (kt % NSTAGE) * BSZ;
        LOADF(0, 0);
        if (kt + 2 < NT) G2_ISSUE(kt + 2, (kt + 2) % NSTAGE);
#pragma unroll
        for (int ks = 0; ks < 4; ks++) {
            if (ks < 3) LOADF((ks + 1) & 1, ks + 1);
            MMAS(ks & 1);
        }
        __syncthreads();
    }
    // epilogue: bias + gathered embedding residual (fp32)
#pragma unroll
    for (int mi = 0; mi < 4; mi++) {
        int lr0 = wm + mi * 16 + gid;
        int lr1 = lr0 + 8;
        size_t r0 = (size_t)(row0 + lr0);
        size_t r1 = (size_t)(row0 + lr1);
#pragma unroll
        for (int ni = 0; ni < 4; ni++) {
            int col = n0 + wn + ni * 8 + 2 * tg;
            float bi0 = b2[col], bi1 = b2[col + 1];
            float2 h0 = *(const float2*)(embed + (size_t)srow[lr0] + col);
            float2 h1 = *(const float2*)(embed + (size_t)srow[lr1] + col);
            float2 o0, o1;
            o0.x = acc[mi][ni][0] + bi0 + h0.x;
            o0.y = acc[mi][ni][1] + bi1 + h0.y;
            o1.x = acc[mi][ni][2] + bi0 + h1.x;
            o1.y = acc[mi][ni][3] + bi1 + h1.y;
            *(float2*)(g_x + r0 * DD + col) = o0;
            *(float2*)(g_x + r1 * DD + col) = o1;
        }
    }
#undef G2_ISSUE
}

// ---------------- K3: LayerNorm + slot_imp + query extraction ----------------
__global__ __launch_bounds__(256) void ln_kernel(
    const float* __restrict__ ln_g, const float* __restrict__ ln_b) {
    const int token = blockIdx.x;
    const int tid = threadIdx.x;
    const float4 x4 = *(const float4*)(g_x + (size_t)token * DD + tid * 4);
    float s = x4.x + x4.y + x4.z + x4.w;
    float sq = x4.x * x4.x + x4.y * x4.y + x4.z * x4.z + x4.w * x4.w;
    __shared__ float sh1[8], sh2[8];
    const int w = tid >> 5, l = tid & 31;
    s = warp_sum(s);
    sq = warp_sum(sq);
    if (l == 0) { sh1[w] = s; sh2[w] = sq; }
    __syncthreads();
    float ts = 0.f, tq = 0.f;
#pragma unroll
    for (int i = 0; i < 8; i++) { ts += sh1[i]; tq += sh2[i]; }
    const float mu = ts * (1.f / 1024.f);
    const float var = tq * (1.f / 1024.f) - mu * mu;
    const float rstd = rsqrtf(var + 1e-5f);
    const float4 g4 = *(const float4*)(ln_g + tid * 4);
    const float4 b4 = *(const float4*)(ln_b + tid * 4);
    float4 h4;
    h4.x = (x4.x - mu) * rstd * g4.x + b4.x;
    h4.y = (x4.y - mu) * rstd * g4.y + b4.y;
    h4.z = (x4.z - mu) * rstd * g4.z + b4.z;
    h4.w = (x4.w - mu) * rstd * g4.w + b4.w;
    *(float4*)(g_hidden + (size_t)token * DD + tid * 4) = h4;
    const float4 wb = *(const float4*)(g_wbar + tid * 4);
    float wd = h4.x * wb.x + h4.y * wb.y + h4.z * wb.z + h4.w * wb.w;
    wd = warp_sum(wd);
    __syncthreads();
    if (l == 0) sh1[w] = wd;
    __syncthreads();
    if (tid == 0) {
        float t2 = 0.f;
#pragma unroll
        for (int i = 0; i < 8; i++) t2 += sh1[i];
        g_slot[token] = t2;   // constant offset (mean wg_b) omitted: rank-invariant
    }
    if ((token & (TT - 1)) == TT - 1) {
        int bidx = token >> 9;
        *(float4*)(g_query + bidx * DD + tid * 4) = h4;
    }
}

// ---------------- K4: top-k selection + memory assembly ----------------
__global__ __launch_bounds__(256) void select_kernel(const float* __restrict__ memory) {
    const int b = blockIdx.x, tid = threadIdx.x;
    __shared__ float imp[512];
    __shared__ int idx[6];
    for (int t = tid; t < TT - 1; t += 256) imp[t] = g_slot[b * TT + t];
    __syncthreads();
    if (tid == 0) {
#pragma unroll
        for (int r = 0; r < 4; r++) {       // fwd top-4 (desc, stable)
            float best = -1e30f; int bi = 0;
            for (int t = 0; t < TT - 1; t++)
                if (imp[t] > best) { best = imp[t]; bi = t; }
            idx[r] = bi;
            imp[bi] = -3.0e38f;
        }
#pragma unroll
        for (int r = 0; r < 2; r++) {       // rev top-2 over first 8, masked
            float best = -1e30f; int bi = 0;
            for (int t = 0; t < 8; t++)
                if (imp[t] > best) { best = imp[t]; bi = t; }
            idx[4 + r] = bi;
            imp[bi] = -3.0e38f;
        }
    }
    __syncthreads();
    for (int s = 0; s < SS; s++) {
        const float* src = (s < 6)
            ? (g_hidden + (size_t)(b * TT + idx[s]) * DD)
            : (memory + (size_t)s * DD);
        *(float4*)(g_mem + (size_t)(b * SS + s) * DD + tid * 4) =
            *(const float4*)(src + tid * 4);
    }
}

// ---------------- vocab GEMM (tf32 mma): logits = Q @ out_w + out_b ----------------
// mode 0: Q=g_query -> g_dl (conf side; margin ~0.8 vs ~2e-4 => tf32 safe)
// mode 1: Q=g_ctx   -> extout (final output; tf32 adds ~3e-4, combined ~6.5e-4 < 1e-3)
// Tail: v0 clamped to VOCAB-128; overlap cols written twice with identical values.
__global__ __launch_bounds__(256) void vlogits_kernel(
    const float* __restrict__ W, const float* __restrict__ bias,
    float* __restrict__ extout, int mode) {
    __shared__ unsigned As[2][32 * APAD];
    __shared__ unsigned Bs[2][32 * BPAD];
    const float* __restrict__ Q = mode ? g_ctx : g_query;
    float* __restrict__ out = mode ? extout : g_dl;
    const int tid = threadIdx.x, warp = tid >> 5, lane = tid & 31;
    const int gid = lane >> 2, tg = lane & 3;
    const int wn = warp * 16;
    int v0 = blockIdx.x * 128;
    if (v0 > VOCAB - 128) v0 = VOCAB - 128;

    const int ar = tid >> 3, akq = tid & 7;   // A: row 0..31, k-quad 0..7
    const int bkr = warp, bc4 = lane * 4;     // B: base k-row 0..7, col*4

    float4 aR;
    float bR[16];

#define CLQ_LOAD(kt) do {                                                       \
        const int k0q = (kt) * 32;                                              \
        aR = *(const float4*)(Q + ar * DD + k0q + akq * 4);                     \
        _Pragma("unroll")                                                       \
        for (int o = 0; o < 4; o++) {                                           \
            const float* wp = W + (size_t)(k0q + bkr + o * 8) * VOCAB + v0 + bc4; \
            bR[o * 4 + 0] = wp[0]; bR[o * 4 + 1] = wp[1];                       \
            bR[o * 4 + 2] = wp[2]; bR[o * 4 + 3] = wp[3];                       \
        }                                                                       \
    } while (0)
#define CLQ_STORE(buf) do {                                                     \
        unsigned* Ad = As[buf]; unsigned* Bd = Bs[buf];                         \
        uint4 ta;                                                               \
        ta.x = __float_as_uint(aR.x); ta.y = __float_as_uint(aR.y);             \
        ta.z = __float_as_uint(aR.z); ta.w = __float_as_uint(aR.w);             \
        *(uint4*)&Ad[ar * APAD + akq * 4] = ta;                                 \
        _Pragma("unroll")                                                       \
        for (int o = 0; o < 4; o++) {                                           \
            uint4 tb;                                                           \
            tb.x = __float_as_uint(bR[o * 4 + 0]);                              \
            tb.y = __float_as_uint(bR[o * 4 + 1]);                              \
            tb.z = __float_as_uint(bR[o * 4 + 2]);                              \
            tb.w = __float_as_uint(bR[o * 4 + 3]);                              \
            *(uint4*)&Bd[(bkr + o * 8) * BPAD + bc4] = tb;                      \
        }                                                                       \
    } while (0)

    float acc[2][2][4];
#pragma unroll
    for (int mi = 0; mi < 2; mi++)
#pragma unroll
        for (int ni = 0; ni < 2; ni++)
#pragma unroll
            for (int r = 0; r < 4; r++) acc[mi][ni][r] = 0.f;

    CLQ_LOAD(0);
    CLQ_STORE(0);
    for (int kt = 0; kt < 32; kt++) {
        __syncthreads();
        if (kt + 1 < 32) CLQ_LOAD(kt + 1);
        const unsigned* Ab = As[kt & 1];
        const unsigned* Bb = Bs[kt & 1];
#pragma unroll
        for (int ks = 0; ks < 32; ks += 8) {
            unsigned a[2][4], b[2][2];
#pragma unroll
            for (int mi = 0; mi < 2; mi++) {
                int mb = (mi * 16 + gid) * APAD;
                a[mi][0] = f2tf(__uint_as_float(Ab[mb + ks + tg]));
                a[mi][1] = f2tf(__uint_as_float(Ab[mb + 8 * APAD + ks + tg]));
                a[mi][2] = f2tf(__uint_as_float(Ab[mb + ks + tg + 4]));
                a[mi][3] = f2tf(__uint_as_float(Ab[mb + 8 * APAD + ks + tg + 4]));
            }
#pragma unroll
            for (int ni = 0; ni < 2; ni++) {
                int c = wn + ni * 8 + gid;
                b[ni][0] = f2tf(__uint_as_float(Bb[(ks + tg) * BPAD + c]));
                b[ni][1] = f2tf(__uint_as_float(Bb[(ks + tg + 4) * BPAD + c]));
            }
#pragma unroll
            for (int mi = 0; mi < 2; mi++)
#pragma unroll
                for (int ni = 0; ni < 2; ni++)
                    mma_tf32(acc[mi][ni], a[mi][0], a[mi][1], a[mi][2], a[mi][3],
                             b[ni][0], b[ni][1]);
        }
        if (kt + 1 < 32) CLQ_STORE((kt + 1) & 1);
    }
#pragma unroll
    for (int mi = 0; mi < 2; mi++) {
        int m0 = mi * 16 + gid;
#pragma unroll
        for (int ni = 0; ni < 2; ni++) {
            int vc = v0 + wn + ni * 8 + 2 * tg;
            float bi0 = bias[vc], bi1 = bias[vc + 1];
            out[(size_t)m0 * VOCAB + vc]           = acc[mi][ni][0] + bi0;
            out[(size_t)m0 * VOCAB + vc + 1]       = acc[mi][ni][1] + bi1;
            out[(size_t)(m0 + 8) * VOCAB + vc]     = acc[mi][ni][2] + bi0;
            out[(size_t)(m0 + 8) * VOCAB + vc + 1] = acc[mi][ni][3] + bi1;
        }
    }
#undef CLQ_LOAD
#undef CLQ_STORE
}

// ---------------- K6: conf = 1/sumexp(direct_logits - max) -> use_mem flag ----------------
__global__ __launch_bounds__(256) void conf_kernel() {
    const int b = blockIdx.x, tid = threadIdx.x;
    const float* row = g_dl + (size_t)b * VOCAB;
    float m = -3.0e38f;
    for (int v = tid; v < VOCAB; v += 256) m = fmaxf(m, row[v]);
    __shared__ float sh[8];
#pragma unroll
    for (int o = 16; o > 0; o >>= 1) m = fmaxf(m, __shfl_xor_sync(0xffffffffu, m, o));
    if ((tid & 31) == 0) sh[tid >> 5] = m;
    __syncthreads();
    float bm = sh[0];
#pragma unroll
    for (int i = 1; i < 8; i++) bm = fmaxf(bm, sh[i]);
    float ssum = 0.f;
    for (int v = tid; v < VOCAB; v += 256) ssum += expf(row[v] - bm);
    ssum = warp_sum(ssum);
    __syncthreads();
    if ((tid & 31) == 0) sh[tid >> 5] = ssum;
    __syncthreads();
    if (tid == 0) {
        float t = 0.f;
#pragma unroll
        for (int i = 0; i < 8; i++) t += sh[i];
        const float conf = 1.f / t;
        g_use[b] = (conf < 0.8f) ? 1.f : 0.f;
    }
}

// ---------------- K7: q = query @ rp_w + rp_b ----------------
__global__ __launch_bounds__(256) void rp_kernel(
    const float* __restrict__ rp_w, const float* __restrict__ rp_b) {
    const int b = blockIdx.x, tid = threadIdx.x;
    __shared__ __align__(16) float qs[DD];
    *(float4*)&qs[tid * 4] = *(const float4*)(g_query + b * DD + tid * 4);
    __syncthreads();
    float acc0 = 0.f, acc1 = 0.f, acc2 = 0.f, acc3 = 0.f;
    for (int d = 0; d < DD; d++) {
        const float q = qs[d];
        const float* wr = rp_w + (size_t)d * DD + tid;
        acc0 += q * wr[0];
        acc1 += q * wr[256];
        acc2 += q * wr[512];
        acc3 += q * wr[768];
    }
    g_q[b * DD + tid +   0] = acc0 + rp_b[tid +   0];
    g_q[b * DD + tid + 256] = acc1 + rp_b[tid + 256];
    g_q[b * DD + tid + 512] = acc2 + rp_b[tid + 512];
    g_q[b * DD + tid + 768] = acc3 + rp_b[tid + 768];
}

// ---------------- K8: scores -> softmax -> ctx -> blend ----------------
__global__ __launch_bounds__(256) void attn_kernel() {
    const int b = blockIdx.x, tid = threadIdx.x;
    __shared__ __align__(16) float qs[DD];
    __shared__ float sh[8];
    __shared__ float scores[SS];
    __shared__ float attn[SS];
    *(float4*)&qs[tid * 4] = *(const float4*)(g_q + b * DD + tid * 4);
    __syncthreads();
    for (int s = 0; s < SS; s++) {
        const float4 m4 = *(const float4*)(g_mem + (size_t)(b * SS + s) * DD + tid * 4);
        const float4 q4 = *(const float4*)&qs[tid * 4];
        float p = m4.x * q4.x + m4.y * q4.y + m4.z * q4.z + m4.w * q4.w;
        p = warp_sum(p);
        if ((tid & 31) == 0) sh[tid >> 5] = p;
        __syncthreads();
        if (tid == 0) {
            float t = 0.f;
#pragma unroll
            for (int i = 0; i < 8; i++) t += sh[i];
            scores[s] = t;
        }
        __syncthreads();
    }
    if (tid == 0) {
        float m = scores[0];
        for (int s = 1; s < SS; s++) m = fmaxf(m, scores[s]);
        float sum = 0.f;
        for (int s = 0; s < SS; s++) { float e = expf(scores[s] - m); attn[s] = e; sum += e; }
        const float inv = 1.f / sum;
        for (int s = 0; s < SS; s++) attn[s] *= inv;
    }
    __syncthreads();
    float c0 = 0.f, c1 = 0.f, c2 = 0.f, c3 = 0.f;
#pragma unroll
    for (int s = 0; s < SS; s++) {
        const float a = attn[s];
        const float4 m4 = *(const float4*)(g_mem + (size_t)(b * SS + s) * DD + tid * 4);
        c0 += a * m4.x; c1 += a * m4.y; c2 += a * m4.z; c3 += a * m4.w;
    }
    const float use = g_use[b];
    const float4 qv = *(const float4*)(g_query + b * DD + tid * 4);
    float4 o;
    o.x = c0 * use + qv.x * (1.f - use);
    o.y = c1 * use + qv.y * (1.f - use);
    o.z = c2 * use + qv.z * (1.f - use);
    o.w = c3 * use + qv.w * (1.f - use);
    *(float4*)(g_ctx + b * DD + tid * 4) = o;
}

// ---------------- launch ----------------
extern "C" void kernel_launch(void* const* d_in, const int* in_sizes, int n_in,
                              void* d_out, int out_size) {
    const int*   seq    = (const int*)  d_in[0];
    const float* embed  = (const float*)d_in[1];
    const float* ff_w1  = (const float*)d_in[2];
    const float* ff_b1  = (const float*)d_in[3];
    const float* ff_w2  = (const float*)d_in[4];
    const float* ff_b2  = (const float*)d_in[5];
    const float* ln_g   = (const float*)d_in[6];
    const float* ln_b   = (const float*)d_in[7];
    const float* wg_w   = (const float*)d_in[8];
    // d_in[9] = wg_b: constant shift of slot_imp, rank-invariant -> unused
    const float* rp_w   = (const float*)d_in[10];
    const float* rp_b   = (const float*)d_in[11];
    const float* out_w  = (const float*)d_in[12];
    const float* out_b  = (const float*)d_in[13];
    const float* memory = (const float*)d_in[14];
    float* out = (float*)d_out;

    cudaFuncSetAttribute(gemm1_kernel, cudaFuncAttributeMaxDynamicSharedMemorySize, GEMM_SMEM);
    cudaFuncSetAttribute(gemm2_kernel, cudaFuncAttributeMaxDynamicSharedMemorySize, GEMM_SMEM);

    wbar_kernel<<<4, 256>>>(wg_w);
    round_w1<<<(DD * H2 / 4) / 256, 256>>>(ff_w1);
    round_w2<<<(DD * H2 / 4) / 256, 256>>>(ff_w2);
    htf_kernel<<<BT, 256>>>(seq, embed);
    gemm1_kernel<<<dim3(16, 128), 256, GEMM_SMEM>>>(ff_b1);
    gemm2_kernel<<<dim3(8, 128), 256, GEMM_SMEM>>>(seq, embed, ff_b2);
    ln_kernel<<<BT, 256>>>(ln_g, ln_b);
    select_kernel<<<BB, 256>>>(memory);
    vlogits_kernel<<<(VOCAB + 127) / 128, 256>>>(out_w, out_b, nullptr, 0);
    conf_kernel<<<BB, 256>>>();
    rp_kernel<<<BB, 256>>>(rp_w, rp_b);
    attn_kernel<<<BB, 256>>>();
    vlogits_kernel<<<(VOCAB + 127) / 128, 256>>>(out_w, out_b, out, 1);
}

// round 13
// speedup vs baseline: 3.5144x; 1.0487x over previous
#include <cuda_runtime.h>
#include <math.h>

#define BB 32
#define TT 512
#define DD 1024
#define VOCAB 50257
#define SS 16
#define BT (BB*TT)
#define H2 2048

// ---------------- scratch (static device globals; no allocation) ----------------
// RULE: device globals are ONLY referenced inside device code. Passing them as
// kernel arguments from host code silently breaks on GB300 (ATS host-shadow).
__device__ unsigned g_aF[(size_t)BT * DD];      // embed[seq] A-fragments (tf32)  64 MB
__device__ unsigned g_actF[(size_t)BT * H2];    // relu(ff1) A-fragments (tf32)  128 MB
__device__ unsigned g_w1F[(size_t)H2 * DD];     // W1 B-fragments (tf32)           8 MB
__device__ unsigned g_w2F[(size_t)DD * H2];     // W2 B-fragments (tf32)           8 MB
__device__ float g_x[(size_t)BT * DD];          // h + ff                         64 MB
__device__ float g_hidden[(size_t)BT * DD];     // LN output                      64 MB
__device__ float g_slot[BT];
__device__ float g_wbar[DD];
__device__ float g_query[BB * DD];
__device__ float g_mem[BB * SS * DD];
__device__ float g_dl[(size_t)BB * VOCAB];
__device__ float g_use[BB];
__device__ float g_q[BB * DD];
__device__ float g_ctx[BB * DD];

__device__ __forceinline__ float warp_sum(float v) {
#pragma unroll
    for (int o = 16; o > 0; o >>= 1) v += __shfl_xor_sync(0xffffffffu, v, o);
    return v;
}
__device__ __forceinline__ unsigned f2tf(float x) {
    unsigned u;
    asm("cvt.rna.tf32.f32 %0, %1;" : "=r"(u) : "f"(x));
    return u;
}
__device__ __forceinline__ void mma_tf32(float* c,
    unsigned a0, unsigned a1, unsigned a2, unsigned a3,
    unsigned b0, unsigned b1) {
    asm volatile(
        "mma.sync.aligned.m16n8k8.row.col.f32.tf32.tf32.f32 "
        "{%0,%1,%2,%3}, {%4,%5,%6,%7}, {%8,%9}, {%0,%1,%2,%3};"
        : "+f"(c[0]), "+f"(c[1]), "+f"(c[2]), "+f"(c[3])
        : "r"(a0), "r"(a1), "r"(a2), "r"(a3), "r"(b0), "r"(b1));
}
__device__ __forceinline__ unsigned sptr(const void* p) {
    return (unsigned)__cvta_generic_to_shared(p);
}
#define CPA16(dst_u32, src_ptr) \
    asm volatile("cp.async.cg.shared.global [%0], [%1], 16;" :: "r"(dst_u32), "l"(src_ptr))
#define CPA_COMMIT() asm volatile("cp.async.commit_group;")
#define CPA_WAIT1()  asm volatile("cp.async.wait_group 1;")
#define CPA_WAIT0()  asm volatile("cp.async.wait_group 0;")

// fragment-major stages: A 128 rows x 32 k = 16 KB, B 128 cols x 32 k = 16 KB
#define ASTG 16384
#define BSTG 16384
#define STGB (ASTG + BSTG)
#define NSTAGE 3
#define GSMEM (NSTAGE * STGB)

// vlogits smem layout constants (kept from R12's passing kernel)
#define APAD 36
#define BPAD 136

// ---------------- K0: wbar = mean_s wg_w ----------------
__global__ void wbar_kernel(const float* __restrict__ wg_w) {
    int d = blockIdx.x * blockDim.x + threadIdx.x;
    if (d < DD) {
        float s = 0.f;
#pragma unroll
        for (int j = 0; j < SS; j++) s += wg_w[d * SS + j];
        g_wbar[d] = s * (1.f / 16.f);
    }
}

// ---------------- prep: W1 [DD][H2] -> B-fragment layout (KB=128) ----------------
// dst[((nblk*KB + kblk)*32 + lane)*2 + {0,1}] = tf32(W[kblk*8+tg+{0,4}][nblk*8+gid])
__global__ __launch_bounds__(256) void prep_w1(const float* __restrict__ W) {
    const int gtid = blockIdx.x * 256 + threadIdx.x;
    const int lane = gtid & 31;
    const int kblk = (gtid >> 5) & 127;      // KB = DD/8 = 128
    const int nblk = gtid >> 12;
    const int gid = lane >> 2, tg = lane & 3;
    const int k = kblk * 8 + tg;
    const int n = nblk * 8 + gid;
    uint2 o;
    o.x = f2tf(W[(size_t)k * H2 + n]);
    o.y = f2tf(W[(size_t)(k + 4) * H2 + n]);
    *(uint2*)(g_w1F + (size_t)gtid * 2) = o;
}
// ---------------- prep: W2 [H2][DD] -> B-fragment layout (KB=256) ----------------
__global__ __launch_bounds__(256) void prep_w2(const float* __restrict__ W) {
    const int gtid = blockIdx.x * 256 + threadIdx.x;
    const int lane = gtid & 31;
    const int kblk = (gtid >> 5) & 255;      // KB = H2/8 = 256
    const int nblk = gtid >> 13;
    const int gid = lane >> 2, tg = lane & 3;
    const int k = kblk * 8 + tg;
    const int n = nblk * 8 + gid;
    uint2 o;
    o.x = f2tf(W[(size_t)k * DD + n]);
    o.y = f2tf(W[(size_t)(k + 4) * DD + n]);
    *(uint2*)(g_w2F + (size_t)gtid * 2) = o;
}

// ---------------- prep: embed[seq] -> A-fragment layout (tf32) ----------------
__global__ __launch_bounds__(256) void prep_a(const int* __restrict__ seq,
                                              const float* __restrict__ embed) {
    extern __shared__ unsigned sA[];   // [16][1028]
    __shared__ int srow[16];
    const int tid = threadIdx.x;
    const int mblk = blockIdx.x;
    if (tid < 16) srow[tid] = seq[mblk * 16 + tid] * DD;
    __syncthreads();
#pragma unroll
    for (int l = 0; l < 16; l++) {
        int idx = tid + l * 256;
        int r = idx >> 8, c4 = idx & 255;
        float4 v = *(const float4*)(embed + (size_t)srow[r] + c4 * 4);
        unsigned* p = sA + r * 1028 + c4 * 4;
        p[0] = f2tf(v.x); p[1] = f2tf(v.y); p[2] = f2tf(v.z); p[3] = f2tf(v.w);
    }
    __syncthreads();
#pragma unroll
    for (int l = 0; l < 16; l++) {
        int c = tid + l * 256;
        int kblk = c >> 5, lane = c & 31;
        int gid = lane >> 2, tg = lane & 3;
        int col = kblk * 8 + tg;
        uint4 o;
        o.x = sA[gid * 1028 + col];
        o.y = sA[(gid + 8) * 1028 + col];
        o.z = sA[gid * 1028 + col + 4];
        o.w = sA[(gid + 8) * 1028 + col + 4];
        *(uint4*)(g_aF + (((size_t)mblk * 128 + kblk) * 32 + lane) * 4) = o;
    }
}

// fragment load (vectorized) + mma step macros
#define LOADF(buf, ks) do {                                                     \
        _Pragma("unroll")                                                       \
        for (int mi = 0; mi < 4; mi++)                                          \
            af[buf][mi] = *(const uint4*)(stg + ((am + mi) * 4 + (ks)) * 512 + lane * 16); \
        _Pragma("unroll")                                                       \
        for (int ni = 0; ni < 4; ni++)                                          \
            bf[buf][ni] = *(const uint2*)(stg + ASTG + ((bn + ni) * 4 + (ks)) * 256 + lane * 8); \
    } while (0)
#define MMAS(buf) do {                                                          \
        _Pragma("unroll")                                                       \
        for (int mi = 0; mi < 4; mi++)                                          \
        _Pragma("unroll")                                                       \
        for (int ni = 0; ni < 4; ni++)                                          \
            mma_tf32(acc[mi][ni],                                               \
                     af[buf][mi].x, af[buf][mi].y, af[buf][mi].z, af[buf][mi].w, \
                     bf[buf][ni].x, bf[buf][ni].y);                             \
    } while (0)

// ---------------- gemm1: g_actF = Afrag(tf32(relu(h @ W1 + b1)))  M=16384 N=2048 K=1024 ----------------
__global__ __launch_bounds__(256) void gemm1_kernel(const float* __restrict__ b1) {
    extern __shared__ unsigned char dsm[];
    __shared__ float sbias[128];
    const int tid = threadIdx.x, warp = tid >> 5, lane = tid & 31;
    const int gid = lane >> 2, tg = lane & 3;
    const int wm = (warp & 1) * 64, wn = (warp >> 1) * 32;
    const int am = (warp & 1) * 4, bn = (warp >> 1) * 4;
    const int n0 = blockIdx.x * 128;
    const size_t mb0 = (size_t)blockIdx.y * 8;
    const size_t nb0 = (size_t)(n0 >> 3);
    if (tid < 128) sbias[tid] = b1[n0 + tid];
    __syncthreads();
    const unsigned sb = sptr(dsm);
    const int NTk = DD / 32;   // 32 k-tiles, A KB = 128

#define ISS1(kt, st) do {                                                       \
        const unsigned ab = sb + (st) * STGB;                                   \
        const unsigned bb = ab + ASTG;                                          \
        const size_t kb0 = (size_t)(kt) * 4;                                    \
        _Pragma("unroll")                                                       \
        for (int l = 0; l < 4; l++) {                                           \
            int c = tid + l * 256;                                              \
            int mb = c >> 7, kb = (c >> 5) & 3, ln = c & 31;                    \
            CPA16(ab + c * 16,                                                  \
                  g_aF + (((mb0 + mb) * 128 + kb0 + kb) * 32 + ln) * 4);        \
        }                                                                       \
        _Pragma("unroll")                                                       \
        for (int l = 0; l < 4; l++) {                                           \
            int c = tid + l * 256;                                              \
            int nb = c >> 6, rm = c & 63, kb = rm >> 4, ch = rm & 15;           \
            CPA16(bb + c * 16,                                                  \
                  g_w1F + (((nb0 + nb) * 128 + kb0 + kb) * 64 + ch * 4));       \
        }                                                                       \
        CPA_COMMIT();                                                           \
    } while (0)

    float acc[4][4][4];
#pragma unroll
    for (int mi = 0; mi < 4; mi++)
#pragma unroll
        for (int ni = 0; ni < 4; ni++)
#pragma unroll
            for (int r = 0; r < 4; r++) acc[mi][ni][r] = 0.f;

    uint4 af[2][4]; uint2 bf[2][4];

    ISS1(0, 0); ISS1(1, 1);
    for (int kt = 0; kt < NTk; kt++) {
        if (kt + 1 < NTk) { CPA_WAIT1(); } else { CPA_WAIT0(); }
        __syncthreads();
        const unsigned char* stg = dsm + (kt % NSTAGE) * STGB;
        LOADF(0, 0);                                   // LDS before cp.async burst
        if (kt + 2 < NTk) ISS1(kt + 2, (kt + 2) % NSTAGE);
#pragma unroll
        for (int ks = 0; ks < 4; ks++) {
            if (ks < 3) LOADF((ks + 1) & 1, ks + 1);
            MMAS(ks & 1);
        }
        __syncthreads();
    }
    // epilogue: bias + relu -> tf32 bits, stage [col][row], scatter to A-frag layout
    unsigned* Ts = (unsigned*)dsm;
#pragma unroll
    for (int mi = 0; mi < 4; mi++) {
        const int row = wm + mi * 16 + gid;
#pragma unroll
        for (int ni = 0; ni < 4; ni++) {
            const int col = wn + ni * 8 + 2 * tg;
            Ts[col * 132 + row]           = f2tf(fmaxf(acc[mi][ni][0] + sbias[col], 0.f));
            Ts[(col + 1) * 132 + row]     = f2tf(fmaxf(acc[mi][ni][1] + sbias[col + 1], 0.f));
            Ts[col * 132 + row + 8]       = f2tf(fmaxf(acc[mi][ni][2] + sbias[col], 0.f));
            Ts[(col + 1) * 132 + row + 8] = f2tf(fmaxf(acc[mi][ni][3] + sbias[col + 1], 0.f));
        }
    }
    __syncthreads();
#pragma unroll
    for (int i = 0; i < 16; i++) {
        const int col = i * 8 + tg;
        const int row = warp * 16 + gid;
        uint4 o;
        o.x = Ts[col * 132 + row];
        o.y = Ts[col * 132 + row + 8];
        o.z = Ts[(col + 4) * 132 + row];
        o.w = Ts[(col + 4) * 132 + row + 8];
        *(uint4*)(g_actF + (((mb0 + warp) * 256 + (n0 >> 3) + i) * 32 + lane) * 4) = o;
    }
#undef ISS1
}

// ---------------- gemm2: g_x = act @ W2 + b2 + embed[seq]  M=16384 N=1024 K=2048 ----------------
__global__ __launch_bounds__(256) void gemm2_kernel(const int* __restrict__ seq,
                                                    const float* __restrict__ embed,
                                                    const float* __restrict__ b2) {
    extern __shared__ unsigned char dsm[];
    __shared__ float sbias[128];
    __shared__ int srow[128];
    const int tid = threadIdx.x, warp = tid >> 5, lane = tid & 31;
    const int gid = lane >> 2, tg = lane & 3;
    const int wm = (warp & 1) * 64, wn = (warp >> 1) * 32;
    const int am = (warp & 1) * 4, bn = (warp >> 1) * 4;
    const int n0 = blockIdx.x * 128;
    const int row0 = blockIdx.y * 128;
    const size_t mb0 = (size_t)blockIdx.y * 8;
    const size_t nb0 = (size_t)(n0 >> 3);
    if (tid < 128) { sbias[tid] = b2[n0 + tid]; srow[tid] = seq[row0 + tid] * DD; }
    __syncthreads();
    const unsigned sb = sptr(dsm);
    const int NTk = H2 / 32;   // 64 k-tiles, A KB = 256

#define ISS2(kt, st) do {                                                       \
        const unsigned ab = sb + (st) * STGB;                                   \
        const unsigned bb = ab + ASTG;                                          \
        const size_t kb0 = (size_t)(kt) * 4;                                    \
        _Pragma("unroll")                                                       \
        for (int l = 0; l < 4; l++) {                                           \
            int c = tid + l * 256;                                              \
            int mb = c >> 7, kb = (c >> 5) & 3, ln = c & 31;                    \
            CPA16(ab + c * 16,                                                  \
                  g_actF + (((mb0 + mb) * 256 + kb0 + kb) * 32 + ln) * 4);      \
        }                                                                       \
        _Pragma("unroll")                                                       \
        for (int l = 0; l < 4; l++) {                                           \
            int c = tid + l * 256;                                              \
            int nb = c >> 6, rm = c & 63, kb = rm >> 4, ch = rm & 15;           \
            CPA16(bb + c * 16,                                                  \
                  g_w2F + (((nb0 + nb) * 256 + kb0 + kb) * 64 + ch * 4));       \
        }                                                                       \
        CPA_COMMIT();                                                           \
    } while (0)

    float acc[4][4][4];
#pragma unroll
    for (int mi = 0; mi < 4; mi++)
#pragma unroll
        for (int ni = 0; ni < 4; ni++)
#pragma unroll
            for (int r = 0; r < 4; r++) acc[mi][ni][r] = 0.f;

    uint4 af[2][4]; uint2 bf[2][4];

    ISS2(0, 0); ISS2(1, 1);
    for (int kt = 0; kt < NTk; kt++) {
        if (kt + 1 < NTk) { CPA_WAIT1(); } else { CPA_WAIT0(); }
        __syncthreads();
        const unsigned char* stg = dsm + (kt % NSTAGE) * STGB;
        LOADF(0, 0);
        if (kt + 2 < NTk) ISS2(kt + 2, (kt + 2) % NSTAGE);
#pragma unroll
        for (int ks = 0; ks < 4; ks++) {
            if (ks < 3) LOADF((ks + 1) & 1, ks + 1);
            MMAS(ks & 1);
        }
        __syncthreads();
    }
    // epilogue: stage fp32 + bias [col][row], then +embed residual, row-major out
    float* Tf = (float*)dsm;
#pragma unroll
    for (int mi = 0; mi < 4; mi++) {
        const int row = wm + mi * 16 + gid;
#pragma unroll
        for (int ni = 0; ni < 4; ni++) {
            const int col = wn + ni * 8 + 2 * tg;
            Tf[col * 132 + row]           = acc[mi][ni][0] + sbias[col];
            Tf[(col + 1) * 132 + row]     = acc[mi][ni][1] + sbias[col + 1];
            Tf[col * 132 + row + 8]       = acc[mi][ni][2] + sbias[col];
            Tf[(col + 1) * 132 + row + 8] = acc[mi][ni][3] + sbias[col + 1];
        }
    }
    __syncthreads();
    {
        const int rr = tid >> 1, half = (tid & 1) * 64;
        const size_t gr = (size_t)(row0 + rr) * DD + n0;
        const float* ep = embed + (size_t)srow[rr] + n0;
#pragma unroll
        for (int j = 0; j < 16; j++) {
            const int c0 = half + j * 4;
            float4 e = *(const float4*)(ep + c0);
            float4 o;
            o.x = Tf[(c0 + 0) * 132 + rr] + e.x;
            o.y = Tf[(c0 + 1) * 132 + rr] + e.y;
            o.z = Tf[(c0 + 2) * 132 + rr] + e.z;
            o.w = Tf[(c0 + 3) * 132 + rr] + e.w;
            *(float4*)(g_x + gr + c0) = o;
        }
    }
#undef ISS2
}

// ---------------- K3: LayerNorm + slot_imp + query extraction ----------------
__global__ __launch_bounds__(256) void ln_kernel(
    const float* __restrict__ ln_g, const float* __restrict__ ln_b) {
    const int token = blockIdx.x;
    const int tid = threadIdx.x;
    const float4 x4 = *(const float4*)(g_x + (size_t)token * DD + tid * 4);
    float s = x4.x + x4.y + x4.z + x4.w;
    float sq = x4.x * x4.x + x4.y * x4.y + x4.z * x4.z + x4.w * x4.w;
    __shared__ float sh1[8], sh2[8];
    const int w = tid >> 5, l = tid & 31;
    s = warp_sum(s);
    sq = warp_sum(sq);
    if (l == 0) { sh1[w] = s; sh2[w] = sq; }
    __syncthreads();
    float ts = 0.f, tq = 0.f;
#pragma unroll
    for (int i = 0; i < 8; i++) { ts += sh1[i]; tq += sh2[i]; }
    const float mu = ts * (1.f / 1024.f);
    const float var = tq * (1.f / 1024.f) - mu * mu;
    const float rstd = rsqrtf(var + 1e-5f);
    const float4 g4 = *(const float4*)(ln_g + tid * 4);
    const float4 b4 = *(const float4*)(ln_b + tid * 4);
    float4 h4;
    h4.x = (x4.x - mu) * rstd * g4.x + b4.x;
    h4.y = (x4.y - mu) * rstd * g4.y + b4.y;
    h4.z = (x4.z - mu) * rstd * g4.z + b4.z;
    h4.w = (x4.w - mu) * rstd * g4.w + b4.w;
    *(float4*)(g_hidden + (size_t)token * DD + tid * 4) = h4;
    const float4 wb = *(const float4*)(g_wbar + tid * 4);
    float wd = h4.x * wb.x + h4.y * wb.y + h4.z * wb.z + h4.w * wb.w;
    wd = warp_sum(wd);
    __syncthreads();
    if (l == 0) sh1[w] = wd;
    __syncthreads();
    if (tid == 0) {
        float t2 = 0.f;
#pragma unroll
        for (int i = 0; i < 8; i++) t2 += sh1[i];
        g_slot[token] = t2;   // constant offset (mean wg_b) omitted: rank-invariant
    }
    if ((token & (TT - 1)) == TT - 1) {
        int bidx = token >> 9;
        *(float4*)(g_query + bidx * DD + tid * 4) = h4;
    }
}

// ---------------- K4: top-k selection + memory assembly ----------------
__global__ __launch_bounds__(256) void select_kernel(const float* __restrict__ memory) {
    const int b = blockIdx.x, tid = threadIdx.x;
    __shared__ float imp[512];
    __shared__ int idx[6];
    for (int t = tid; t < TT - 1; t += 256) imp[t] = g_slot[b * TT + t];
    __syncthreads();
    if (tid == 0) {
#pragma unroll
        for (int r = 0; r < 4; r++) {       // fwd top-4 (desc, stable)
            float best = -1e30f; int bi = 0;
            for (int t = 0; t < TT - 1; t++)
                if (imp[t] > best) { best = imp[t]; bi = t; }
            idx[r] = bi;
            imp[bi] = -3.0e38f;
        }
#pragma unroll
        for (int r = 0; r < 2; r++) {       // rev top-2 over first 8, masked
            float best = -1e30f; int bi = 0;
            for (int t = 0; t < 8; t++)
                if (imp[t] > best) { best = imp[t]; bi = t; }
            idx[4 + r] = bi;
            imp[bi] = -3.0e38f;
        }
    }
    __syncthreads();
    for (int s = 0; s < SS; s++) {
        const float* src = (s < 6)
            ? (g_hidden + (size_t)(b * TT + idx[s]) * DD)
            : (memory + (size_t)s * DD);
        *(float4*)(g_mem + (size_t)(b * SS + s) * DD + tid * 4) =
            *(const float4*)(src + tid * 4);
    }
}

// ---------------- vocab GEMM (tf32 mma): logits = Q @ out_w + out_b ----------------
// mode 0: Q=g_query -> g_dl ; mode 1: Q=g_ctx -> extout
// Tail: v0 clamped to VOCAB-128; overlap cols written twice with identical values.
__global__ __launch_bounds__(256) void vlogits_kernel(
    const float* __restrict__ W, const float* __restrict__ bias,
    float* __restrict__ extout, int mode) {
    __shared__ unsigned As[2][32 * APAD];
    __shared__ unsigned Bs[2][32 * BPAD];
    const float* __restrict__ Q = mode ? g_ctx : g_query;
    float* __restrict__ out = mode ? extout : g_dl;
    const int tid = threadIdx.x, warp = tid >> 5, lane = tid & 31;
    const int gid = lane >> 2, tg = lane & 3;
    const int wn = warp * 16;
    int v0 = blockIdx.x * 128;
    if (v0 > VOCAB - 128) v0 = VOCAB - 128;

    const int ar = tid >> 3, akq = tid & 7;
    const int bkr = warp, bc4 = lane * 4;

    float4 aR;
    float bR[16];

#define CLQ_LOAD(kt) do {                                                       \
        const int k0q = (kt) * 32;                                              \
        aR = *(const float4*)(Q + ar * DD + k0q + akq * 4);                     \
        _Pragma("unroll")                                                       \
        for (int o = 0; o < 4; o++) {                                           \
            const float* wp = W + (size_t)(k0q + bkr + o * 8) * VOCAB + v0 + bc4; \
            bR[o * 4 + 0] = wp[0]; bR[o * 4 + 1] = wp[1];                       \
            bR[o * 4 + 2] = wp[2]; bR[o * 4 + 3] = wp[3];                       \
        }                                                                       \
    } while (0)
#define CLQ_STORE(buf) do {                                                     \
        unsigned* Ad = As[buf]; unsigned* Bd = Bs[buf];                         \
        uint4 ta;                                                               \
        ta.x = __float_as_uint(aR.x); ta.y = __float_as_uint(aR.y);             \
        ta.z = __float_as_uint(aR.z); ta.w = __float_as_uint(aR.w);             \
        *(uint4*)&Ad[ar * APAD + akq * 4] = ta;                                 \
        _Pragma("unroll")                                                       \
        for (int o = 0; o < 4; o++) {                                           \
            uint4 tb;                                                           \
            tb.x = __float_as_uint(bR[o * 4 + 0]);                              \
            tb.y = __float_as_uint(bR[o * 4 + 1]);                              \
            tb.z = __float_as_uint(bR[o * 4 + 2]);                              \
            tb.w = __float_as_uint(bR[o * 4 + 3]);                              \
            *(uint4*)&Bd[(bkr + o * 8) * BPAD + bc4] = tb;                      \
        }                                                                       \
    } while (0)

    float acc[2][2][4];
#pragma unroll
    for (int mi = 0; mi < 2; mi++)
#pragma unroll
        for (int ni = 0; ni < 2; ni++)
#pragma unroll
            for (int r = 0; r < 4; r++) acc[mi][ni][r] = 0.f;

    CLQ_LOAD(0);
    CLQ_STORE(0);
    for (int kt = 0; kt < 32; kt++) {
        __syncthreads();
        if (kt + 1 < 32) CLQ_LOAD(kt + 1);
        const unsigned* Ab = As[kt & 1];
        const unsigned* Bb = Bs[kt & 1];
#pragma unroll
        for (int ks = 0; ks < 32; ks += 8) {
            unsigned a[2][4], b[2][2];
#pragma unroll
            for (int mi = 0; mi < 2; mi++) {
                int mb = (mi * 16 + gid) * APAD;
                a[mi][0] = f2tf(__uint_as_float(Ab[mb + ks + tg]));
                a[mi][1] = f2tf(__uint_as_float(Ab[mb + 8 * APAD + ks + tg]));
                a[mi][2] = f2tf(__uint_as_float(Ab[mb + ks + tg + 4]));
                a[mi][3] = f2tf(__uint_as_float(Ab[mb + 8 * APAD + ks + tg + 4]));
            }
#pragma unroll
            for (int ni = 0; ni < 2; ni++) {
                int c = wn + ni * 8 + gid;
                b[ni][0] = f2tf(__uint_as_float(Bb[(ks + tg) * BPAD + c]));
                b[ni][1] = f2tf(__uint_as_float(Bb[(ks + tg + 4) * BPAD + c]));
            }
#pragma unroll
            for (int mi = 0; mi < 2; mi++)
#pragma unroll
                for (int ni = 0; ni < 2; ni++)
                    mma_tf32(acc[mi][ni], a[mi][0], a[mi][1], a[mi][2], a[mi][3],
                             b[ni][0], b[ni][1]);
        }
        if (kt + 1 < 32) CLQ_STORE((kt + 1) & 1);
    }
#pragma unroll
    for (int mi = 0; mi < 2; mi++) {
        int m0 = mi * 16 + gid;
#pragma unroll
        for (int ni = 0; ni < 2; ni++) {
            int vc = v0 + wn + ni * 8 + 2 * tg;
            float bi0 = bias[vc], bi1 = bias[vc + 1];
            out[(size_t)m0 * VOCAB + vc]           = acc[mi][ni][0] + bi0;
            out[(size_t)m0 * VOCAB + vc + 1]       = acc[mi][ni][1] + bi1;
            out[(size_t)(m0 + 8) * VOCAB + vc]     = acc[mi][ni][2] + bi0;
            out[(size_t)(m0 + 8) * VOCAB + vc + 1] = acc[mi][ni][3] + bi1;
        }
    }
#undef CLQ_LOAD
#undef CLQ_STORE
}

// ---------------- K6: conf = 1/sumexp(direct_logits - max) -> use_mem flag ----------------
__global__ __launch_bounds__(256) void conf_kernel() {
    const int b = blockIdx.x, tid = threadIdx.x;
    const float* row = g_dl + (size_t)b * VOCAB;
    float m = -3.0e38f;
    for (int v = tid; v < VOCAB; v += 256) m = fmaxf(m, row[v]);
    __shared__ float sh[8];
#pragma unroll
    for (int o = 16; o > 0; o >>= 1) m = fmaxf(m, __shfl_xor_sync(0xffffffffu, m, o));
    if ((tid & 31) == 0) sh[tid >> 5] = m;
    __syncthreads();
    float bm = sh[0];
#pragma unroll
    for (int i = 1; i < 8; i++) bm = fmaxf(bm, sh[i]);
    float ssum = 0.f;
    for (int v = tid; v < VOCAB; v += 256) ssum += expf(row[v] - bm);
    ssum = warp_sum(ssum);
    __syncthreads();
    if ((tid & 31) == 0) sh[tid >> 5] = ssum;
    __syncthreads();
    if (tid == 0) {
        float t = 0.f;
#pragma unroll
        for (int i = 0; i < 8; i++) t += sh[i];
        const float conf = 1.f / t;
        g_use[b] = (conf < 0.8f) ? 1.f : 0.f;
    }
}

// ---------------- K7: q = query @ rp_w + rp_b ----------------
__global__ __launch_bounds__(256) void rp_kernel(
    const float* __restrict__ rp_w, const float* __restrict__ rp_b) {
    const int b = blockIdx.x, tid = threadIdx.x;
    __shared__ __align__(16) float qs[DD];
    *(float4*)&qs[tid * 4] = *(const float4*)(g_query + b * DD + tid * 4);
    __syncthreads();
    float acc0 = 0.f, acc1 = 0.f, acc2 = 0.f, acc3 = 0.f;
    for (int d = 0; d < DD; d++) {
        const float q = qs[d];
        const float* wr = rp_w + (size_t)d * DD + tid;
        acc0 += q * wr[0];
        acc1 += q * wr[256];
        acc2 += q * wr[512];
        acc3 += q * wr[768];
    }
    g_q[b * DD + tid +   0] = acc0 + rp_b[tid +   0];
    g_q[b * DD + tid + 256] = acc1 + rp_b[tid + 256];
    g_q[b * DD + tid + 512] = acc2 + rp_b[tid + 512];
    g_q[b * DD + tid + 768] = acc3 + rp_b[tid + 768];
}

// ---------------- K8: scores -> softmax -> ctx -> blend ----------------
__global__ __launch_bounds__(256) void attn_kernel() {
    const int b = blockIdx.x, tid = threadIdx.x;
    __shared__ __align__(16) float qs[DD];
    __shared__ float sh[8];
    __shared__ float scores[SS];
    __shared__ float attn[SS];
    *(float4*)&qs[tid * 4] = *(const float4*)(g_q + b * DD + tid * 4);
    __syncthreads();
    for (int s = 0; s < SS; s++) {
        const float4 m4 = *(const float4*)(g_mem + (size_t)(b * SS + s) * DD + tid * 4);
        const float4 q4 = *(const float4*)&qs[tid * 4];
        float p = m4.x * q4.x + m4.y * q4.y + m4.z * q4.z + m4.w * q4.w;
        p = warp_sum(p);
        if ((tid & 31) == 0) sh[tid >> 5] = p;
        __syncthreads();
        if (tid == 0) {
            float t = 0.f;
#pragma unroll
            for (int i = 0; i < 8; i++) t += sh[i];
            scores[s] = t;
        }
        __syncthreads();
    }
    if (tid == 0) {
        float m = scores[0];
        for (int s = 1; s < SS; s++) m = fmaxf(m, scores[s]);
        float sum = 0.f;
        for (int s = 0; s < SS; s++) { float e = expf(scores[s] - m); attn[s] = e; sum += e; }
        const float inv = 1.f / sum;
        for (int s = 0; s < SS; s++) attn[s] *= inv;
    }
    __syncthreads();
    float c0 = 0.f, c1 = 0.f, c2 = 0.f, c3 = 0.f;
#pragma unroll
    for (int s = 0; s < SS; s++) {
        const float a = attn[s];
        const float4 m4 = *(const float4*)(g_mem + (size_t)(b * SS + s) * DD + tid * 4);
        c0 += a * m4.x; c1 += a * m4.y; c2 += a * m4.z; c3 += a * m4.w;
    }
    const float use = g_use[b];
    const float4 qv = *(const float4*)(g_query + b * DD + tid * 4);
    float4 o;
    o.x = c0 * use + qv.x * (1.f - use);
    o.y = c1 * use + qv.y * (1.f - use);
    o.z = c2 * use + qv.z * (1.f - use);
    o.w = c3 * use + qv.w * (1.f - use);
    *(float4*)(g_ctx + b * DD + tid * 4) = o;
}

// ---------------- launch ----------------
extern "C" void kernel_launch(void* const* d_in, const int* in_sizes, int n_in,
                              void* d_out, int out_size) {
    const int*   seq    = (const int*)  d_in[0];
    const float* embed  = (const float*)d_in[1];
    const float* ff_w1  = (const float*)d_in[2];
    const float* ff_b1  = (const float*)d_in[3];
    const float* ff_w2  = (const float*)d_in[4];
    const float* ff_b2  = (const float*)d_in[5];
    const float* ln_g   = (const float*)d_in[6];
    const float* ln_b   = (const float*)d_in[7];
    const float* wg_w   = (const float*)d_in[8];
    // d_in[9] = wg_b: constant shift of slot_imp, rank-invariant -> unused
    const float* rp_w   = (const float*)d_in[10];
    const float* rp_b   = (const float*)d_in[11];
    const float* out_w  = (const float*)d_in[12];
    const float* out_b  = (const float*)d_in[13];
    const float* memory = (const float*)d_in[14];
    float* out = (float*)d_out;

    cudaFuncSetAttribute(gemm1_kernel, cudaFuncAttributeMaxDynamicSharedMemorySize, GSMEM);
    cudaFuncSetAttribute(gemm2_kernel, cudaFuncAttributeMaxDynamicSharedMemorySize, GSMEM);
    cudaFuncSetAttribute(prep_a, cudaFuncAttributeMaxDynamicSharedMemorySize, 16 * 1028 * 4);

    wbar_kernel<<<4, 256>>>(wg_w);
    prep_w1<<<(H2 / 8) * (DD / 8) * 32 / 256, 256>>>(ff_w1);
    prep_w2<<<(DD / 8) * (H2 / 8) * 32 / 256, 256>>>(ff_w2);
    prep_a<<<BT / 16, 256, 16 * 1028 * 4>>>(seq, embed);
    gemm1_kernel<<<dim3(H2 / 128, BT / 128), 256, GSMEM>>>(ff_b1);
    gemm2_kernel<<<dim3(DD / 128, BT / 128), 256, GSMEM>>>(seq, embed, ff_b2);
    ln_kernel<<<BT, 256>>>(ln_g, ln_b);
    select_kernel<<<BB, 256>>>(memory);
    vlogits_kernel<<<(VOCAB + 127) / 128, 256>>>(out_w, out_b, nullptr, 0);
    conf_kernel<<<BB, 256>>>();
    rp_kernel<<<BB, 256>>>(rp_w, rp_b);
    attn_kernel<<<BB, 256>>>();
    vlogits_kernel<<<(VOCAB + 127) / 128, 256>>>(out_w, out_b, out, 1);
}

// round 14
// speedup vs baseline: 4.8944x; 1.3927x over previous
#include <cuda_runtime.h>
#include <cuda_fp16.h>
#include <math.h>

#define BB 32
#define TT 512
#define DD 1024
#define VOCAB 50257
#define SS 16
#define BT (BB*TT)
#define H2 2048

// ---------------- scratch (static device globals; no allocation) ----------------
// RULE: device globals are ONLY referenced inside device code. Passing them as
// kernel arguments from host code silently breaks on GB300 (ATS host-shadow).
__device__ unsigned g_aF16[(size_t)BT * DD / 2];    // embed[seq] fp16 A-frags  32 MB
__device__ unsigned g_actF16[(size_t)BT * H2 / 2];  // relu(ff1) fp16 A-frags   64 MB
__device__ unsigned g_w1F16[(size_t)DD * H2 / 2];   // W1 fp16 B-frags           4 MB
__device__ unsigned g_w2F16[(size_t)H2 * DD / 2];   // W2 fp16 B-frags           4 MB
__device__ float g_x[(size_t)BT * DD];              // h + ff                   64 MB
__device__ float g_hidden[(size_t)BT * DD];         // LN output                64 MB
__device__ float g_slot[BT];
__device__ float g_wbar[DD];
__device__ float g_query[BB * DD];
__device__ float g_mem[BB * SS * DD];
__device__ float g_dl[(size_t)BB * VOCAB];
__device__ float g_use[BB];
__device__ float g_q[BB * DD];
__device__ float g_ctx[BB * DD];

__device__ __forceinline__ float warp_sum(float v) {
#pragma unroll
    for (int o = 16; o > 0; o >>= 1) v += __shfl_xor_sync(0xffffffffu, v, o);
    return v;
}
__device__ __forceinline__ unsigned f2tf(float x) {
    unsigned u;
    asm("cvt.rna.tf32.f32 %0, %1;" : "=r"(u) : "f"(x));
    return u;
}
// pack two floats -> half2 bits (elem0 in low 16 bits, per PTX f16x2 convention)
__device__ __forceinline__ unsigned pkf(float lo, float hi) {
    return ((unsigned)__half_as_ushort(__float2half_rn(hi)) << 16) |
           (unsigned)__half_as_ushort(__float2half_rn(lo));
}
__device__ __forceinline__ unsigned pkh(__half lo, __half hi) {
    return ((unsigned)__half_as_ushort(hi) << 16) | (unsigned)__half_as_ushort(lo);
}
__device__ __forceinline__ void mma_f16(float* c,
    unsigned a0, unsigned a1, unsigned a2, unsigned a3,
    unsigned b0, unsigned b1) {
    asm volatile(
        "mma.sync.aligned.m16n8k16.row.col.f32.f16.f16.f32 "
        "{%0,%1,%2,%3}, {%4,%5,%6,%7}, {%8,%9}, {%0,%1,%2,%3};"
        : "+f"(c[0]), "+f"(c[1]), "+f"(c[2]), "+f"(c[3])
        : "r"(a0), "r"(a1), "r"(a2), "r"(a3), "r"(b0), "r"(b1));
}
__device__ __forceinline__ void mma_tf32(float* c,
    unsigned a0, unsigned a1, unsigned a2, unsigned a3,
    unsigned b0, unsigned b1) {
    asm volatile(
        "mma.sync.aligned.m16n8k8.row.col.f32.tf32.tf32.f32 "
        "{%0,%1,%2,%3}, {%4,%5,%6,%7}, {%8,%9}, {%0,%1,%2,%3};"
        : "+f"(c[0]), "+f"(c[1]), "+f"(c[2]), "+f"(c[3])
        : "r"(a0), "r"(a1), "r"(a2), "r"(a3), "r"(b0), "r"(b1));
}
__device__ __forceinline__ unsigned sptr(const void* p) {
    return (unsigned)__cvta_generic_to_shared(p);
}
#define CPA16(dst_u32, src_ptr) \
    asm volatile("cp.async.cg.shared.global [%0], [%1], 16;" :: "r"(dst_u32), "l"(src_ptr))
#define CPA_COMMIT() asm volatile("cp.async.commit_group;")
#define CPA_WAIT1()  asm volatile("cp.async.wait_group 1;")
#define CPA_WAIT0()  asm volatile("cp.async.wait_group 0;")

// fp16 fragment-major stages: A 128 rows x 32 k x 2B = 8 KB, B 128 cols x 32 k = 8 KB
#define ASTG 8192
#define BSTG 8192
#define STGB (ASTG + BSTG)
#define NSTAGE 3
#define GSMEM_G 67584           // max(3*STGB=48K, gemm2 epilogue 128*132*4B=67.6K)

// vlogits tf32 smem constants (R12 proven)
#define APAD 36
#define BPAD 136

// ---------------- K0: wbar = mean_s wg_w ----------------
__global__ void wbar_kernel(const float* __restrict__ wg_w) {
    int d = blockIdx.x * blockDim.x + threadIdx.x;
    if (d < DD) {
        float s = 0.f;
#pragma unroll
        for (int j = 0; j < SS; j++) s += wg_w[d * SS + j];
        g_wbar[d] = s * (1.f / 16.f);
    }
}

// ---------------- prep: W1 [DD][H2] -> fp16 B-fragments (KB1 = DD/16 = 64) ----------------
// entry (nblk,kblk,lane): reg0={W[16k+2tg][n],W[16k+2tg+1][n]}, reg1=rows+8; n=8nblk+gid
__global__ __launch_bounds__(256) void prep_w1(const float* __restrict__ W) {
    const int gtid = blockIdx.x * 256 + threadIdx.x;
    const int lane = gtid & 31;
    const int kblk = (gtid >> 5) & 63;
    const int nblk = gtid >> 11;
    const int gid = lane >> 2, tg = lane & 3;
    const int k = kblk * 16 + 2 * tg;
    const int n = nblk * 8 + gid;
    uint2 o;
    o.x = pkf(W[(size_t)k * H2 + n],       W[(size_t)(k + 1) * H2 + n]);
    o.y = pkf(W[(size_t)(k + 8) * H2 + n], W[(size_t)(k + 9) * H2 + n]);
    *(uint2*)(g_w1F16 + (size_t)gtid * 2) = o;
}
// ---------------- prep: W2 [H2][DD] -> fp16 B-fragments (KB2 = H2/16 = 128) ----------------
__global__ __launch_bounds__(256) void prep_w2(const float* __restrict__ W) {
    const int gtid = blockIdx.x * 256 + threadIdx.x;
    const int lane = gtid & 31;
    const int kblk = (gtid >> 5) & 127;
    const int nblk = gtid >> 12;
    const int gid = lane >> 2, tg = lane & 3;
    const int k = kblk * 16 + 2 * tg;
    const int n = nblk * 8 + gid;
    uint2 o;
    o.x = pkf(W[(size_t)k * DD + n],       W[(size_t)(k + 1) * DD + n]);
    o.y = pkf(W[(size_t)(k + 8) * DD + n], W[(size_t)(k + 9) * DD + n]);
    *(uint2*)(g_w2F16 + (size_t)gtid * 2) = o;
}

// ---------------- prep: embed[seq] -> fp16 A-fragments (KB = DD/16 = 64) ----------------
#define PADW 1032
__global__ __launch_bounds__(256) void prep_a(const int* __restrict__ seq,
                                              const float* __restrict__ embed) {
    extern __shared__ __half sA[];   // [16][PADW]
    __shared__ int srow[16];
    const int tid = threadIdx.x;
    const int mblk = blockIdx.x;
    if (tid < 16) srow[tid] = seq[mblk * 16 + tid] * DD;
    __syncthreads();
#pragma unroll
    for (int l = 0; l < 16; l++) {
        int idx = tid + l * 256;
        int r = idx >> 8, c4 = idx & 255;
        float4 v = *(const float4*)(embed + (size_t)srow[r] + c4 * 4);
        __half* p = sA + r * PADW + c4 * 4;
        p[0] = __float2half_rn(v.x); p[1] = __float2half_rn(v.y);
        p[2] = __float2half_rn(v.z); p[3] = __float2half_rn(v.w);
    }
    __syncthreads();
#pragma unroll
    for (int l = 0; l < 8; l++) {
        int c = tid + l * 256;               // 64 kblk * 32 lanes = 2048
        int kblk = c >> 5, lane = c & 31;
        int gid = lane >> 2, tg = lane & 3;
        int col = kblk * 16 + 2 * tg;
        uint4 o;
        o.x = pkh(sA[gid * PADW + col],           sA[gid * PADW + col + 1]);
        o.y = pkh(sA[(gid + 8) * PADW + col],     sA[(gid + 8) * PADW + col + 1]);
        o.z = pkh(sA[gid * PADW + col + 8],       sA[gid * PADW + col + 9]);
        o.w = pkh(sA[(gid + 8) * PADW + col + 8], sA[(gid + 8) * PADW + col + 9]);
        *(uint4*)(g_aF16 + (((size_t)mblk * 64 + kblk) * 32 + lane) * 4) = o;
    }
}

// fragment load (vectorized) + fp16 mma step macros
#define LOADF(buf, ks) do {                                                     \
        _Pragma("unroll")                                                       \
        for (int mi = 0; mi < 4; mi++)                                          \
            af[buf][mi] = *(const uint4*)(stg + ((am + mi) * 2 + (ks)) * 512 + lane * 16); \
        _Pragma("unroll")                                                       \
        for (int ni = 0; ni < 4; ni++)                                          \
            bf[buf][ni] = *(const uint2*)(stg + ASTG + ((bn + ni) * 2 + (ks)) * 256 + lane * 8); \
    } while (0)
#define MMAS(buf) do {                                                          \
        _Pragma("unroll")                                                       \
        for (int mi = 0; mi < 4; mi++)                                          \
        _Pragma("unroll")                                                       \
        for (int ni = 0; ni < 4; ni++)                                          \
            mma_f16(acc[mi][ni],                                                \
                    af[buf][mi].x, af[buf][mi].y, af[buf][mi].z, af[buf][mi].w, \
                    bf[buf][ni].x, bf[buf][ni].y);                              \
    } while (0)

// ---------------- gemm1: g_actF16 = Afrag(fp16(relu(h @ W1 + b1)))  M=16384 N=2048 K=1024 ----------------
__global__ __launch_bounds__(256) void gemm1_kernel(const float* __restrict__ b1) {
    extern __shared__ unsigned char dsm[];
    __shared__ float sbias[128];
    const int tid = threadIdx.x, warp = tid >> 5, lane = tid & 31;
    const int gid = lane >> 2, tg = lane & 3;
    const int wm = (warp & 1) * 64, wn = (warp >> 1) * 32;
    const int am = (warp & 1) * 4, bn = (warp >> 1) * 4;
    const int n0 = blockIdx.x * 128;
    const size_t mb0 = (size_t)blockIdx.y * 8;
    const size_t nb0 = (size_t)(n0 >> 3);
    if (tid < 128) sbias[tid] = b1[n0 + tid];
    __syncthreads();
    const unsigned sb = sptr(dsm);
    const int NTk = DD / 32;   // 32 k-tiles; A/B kblk = kt*2 + {0,1}, KB1 = 64

#define ISS1(kt, st) do {                                                       \
        const unsigned ab = sb + (st) * STGB;                                   \
        const unsigned bb = ab + ASTG;                                          \
        const size_t kb0 = (size_t)(kt) * 2;                                    \
        _Pragma("unroll")                                                       \
        for (int l = 0; l < 2; l++) {                                           \
            int c = tid + l * 256;                                              \
            int mb = c >> 6, kb = (c >> 5) & 1, ln = c & 31;                    \
            CPA16(ab + c * 16,                                                  \
                  g_aF16 + (((mb0 + mb) * 64 + kb0 + kb) * 32 + ln) * 4);       \
        }                                                                       \
        _Pragma("unroll")                                                       \
        for (int l = 0; l < 2; l++) {                                           \
            int c = tid + l * 256;                                              \
            int nb = c >> 5, rm = c & 31, kb = rm >> 4, ch = rm & 15;           \
            CPA16(bb + c * 16,                                                  \
                  g_w1F16 + (((nb0 + nb) * 64 + kb0 + kb) * 32 + ch * 2) * 2);  \
        }                                                                       \
        CPA_COMMIT();                                                           \
    } while (0)

    float acc[4][4][4];
#pragma unroll
    for (int mi = 0; mi < 4; mi++)
#pragma unroll
        for (int ni = 0; ni < 4; ni++)
#pragma unroll
            for (int r = 0; r < 4; r++) acc[mi][ni][r] = 0.f;

    uint4 af[2][4]; uint2 bf[2][4];

    ISS1(0, 0); ISS1(1, 1);
    for (int kt = 0; kt < NTk; kt++) {
        if (kt + 1 < NTk) { CPA_WAIT1(); } else { CPA_WAIT0(); }
        __syncthreads();
        const unsigned char* stg = dsm + (kt % NSTAGE) * STGB;
        LOADF(0, 0);
        if (kt + 2 < NTk) ISS1(kt + 2, (kt + 2) % NSTAGE);
        LOADF(1, 1);
        MMAS(0);
        MMAS(1);
        __syncthreads();
    }
    // epilogue: bias + relu -> fp16, stage [col][row], scatter to fp16 A-frag layout
    __half* Ts = (__half*)dsm;
#pragma unroll
    for (int mi = 0; mi < 4; mi++) {
        const int row = wm + mi * 16 + gid;
#pragma unroll
        for (int ni = 0; ni < 4; ni++) {
            const int col = wn + ni * 8 + 2 * tg;
            Ts[col * 132 + row]           = __float2half_rn(fmaxf(acc[mi][ni][0] + sbias[col], 0.f));
            Ts[(col + 1) * 132 + row]     = __float2half_rn(fmaxf(acc[mi][ni][1] + sbias[col + 1], 0.f));
            Ts[col * 132 + row + 8]       = __float2half_rn(fmaxf(acc[mi][ni][2] + sbias[col], 0.f));
            Ts[(col + 1) * 132 + row + 8] = __float2half_rn(fmaxf(acc[mi][ni][3] + sbias[col + 1], 0.f));
        }
    }
    __syncthreads();
    // scatter: each warp owns mblk mb0+warp; 8 kblks (16 cols each) per block
#pragma unroll
    for (int i = 0; i < 8; i++) {
        const int col = i * 16 + 2 * tg;
        const int row = warp * 16 + gid;
        uint4 o;
        o.x = pkh(Ts[col * 132 + row],           Ts[(col + 1) * 132 + row]);
        o.y = pkh(Ts[col * 132 + row + 8],       Ts[(col + 1) * 132 + row + 8]);
        o.z = pkh(Ts[(col + 8) * 132 + row],     Ts[(col + 9) * 132 + row]);
        o.w = pkh(Ts[(col + 8) * 132 + row + 8], Ts[(col + 9) * 132 + row + 8]);
        *(uint4*)(g_actF16 + (((mb0 + warp) * 128 + (n0 >> 4) + i) * 32 + lane) * 4) = o;
    }
#undef ISS1
}

// ---------------- gemm2: g_x = act @ W2 + b2 + embed[seq]  M=16384 N=1024 K=2048 ----------------
__global__ __launch_bounds__(256) void gemm2_kernel(const int* __restrict__ seq,
                                                    const float* __restrict__ embed,
                                                    const float* __restrict__ b2) {
    extern __shared__ unsigned char dsm[];
    __shared__ float sbias[128];
    __shared__ int srow[128];
    const int tid = threadIdx.x, warp = tid >> 5, lane = tid & 31;
    const int gid = lane >> 2, tg = lane & 3;
    const int wm = (warp & 1) * 64, wn = (warp >> 1) * 32;
    const int am = (warp & 1) * 4, bn = (warp >> 1) * 4;
    const int n0 = blockIdx.x * 128;
    const int row0 = blockIdx.y * 128;
    const size_t mb0 = (size_t)blockIdx.y * 8;
    const size_t nb0 = (size_t)(n0 >> 3);
    if (tid < 128) { sbias[tid] = b2[n0 + tid]; srow[tid] = seq[row0 + tid] * DD; }
    __syncthreads();
    const unsigned sb = sptr(dsm);
    const int NTk = H2 / 32;   // 64 k-tiles; kblk = kt*2 + {0,1}, KB2 = 128

#define ISS2(kt, st) do {                                                       \
        const unsigned ab = sb + (st) * STGB;                                   \
        const unsigned bb = ab + ASTG;                                          \
        const size_t kb0 = (size_t)(kt) * 2;                                    \
        _Pragma("unroll")                                                       \
        for (int l = 0; l < 2; l++) {                                           \
            int c = tid + l * 256;                                              \
            int mb = c >> 6, kb = (c >> 5) & 1, ln = c & 31;                    \
            CPA16(ab + c * 16,                                                  \
                  g_actF16 + (((mb0 + mb) * 128 + kb0 + kb) * 32 + ln) * 4);    \
        }                                                                       \
        _Pragma("unroll")                                                       \
        for (int l = 0; l < 2; l++) {                                           \
            int c = tid + l * 256;                                              \
            int nb = c >> 5, rm = c & 31, kb = rm >> 4, ch = rm & 15;           \
            CPA16(bb + c * 16,                                                  \
                  g_w2F16 + (((nb0 + nb) * 128 + kb0 + kb) * 32 + ch * 2) * 2); \
        }                                                                       \
        CPA_COMMIT();                                                           \
    } while (0)

    float acc[4][4][4];
#pragma unroll
    for (int mi = 0; mi < 4; mi++)
#pragma unroll
        for (int ni = 0; ni < 4; ni++)
#pragma unroll
            for (int r = 0; r < 4; r++) acc[mi][ni][r] = 0.f;

    uint4 af[2][4]; uint2 bf[2][4];

    ISS2(0, 0); ISS2(1, 1);
    for (int kt = 0; kt < NTk; kt++) {
        if (kt + 1 < NTk) { CPA_WAIT1(); } else { CPA_WAIT0(); }
        __syncthreads();
        const unsigned char* stg = dsm + (kt % NSTAGE) * STGB;
        LOADF(0, 0);
        if (kt + 2 < NTk) ISS2(kt + 2, (kt + 2) % NSTAGE);
        LOADF(1, 1);
        MMAS(0);
        MMAS(1);
        __syncthreads();
    }
    // epilogue: stage fp32 + bias [col][row], then +embed residual, row-major out
    float* Tf = (float*)dsm;
#pragma unroll
    for (int mi = 0; mi < 4; mi++) {
        const int row = wm + mi * 16 + gid;
#pragma unroll
        for (int ni = 0; ni < 4; ni++) {
            const int col = wn + ni * 8 + 2 * tg;
            Tf[col * 132 + row]           = acc[mi][ni][0] + sbias[col];
            Tf[(col + 1) * 132 + row]     = acc[mi][ni][1] + sbias[col + 1];
            Tf[col * 132 + row + 8]       = acc[mi][ni][2] + sbias[col];
            Tf[(col + 1) * 132 + row + 8] = acc[mi][ni][3] + sbias[col + 1];
        }
    }
    __syncthreads();
    {
        const int rr = tid >> 1, half = (tid & 1) * 64;
        const size_t gr = (size_t)(row0 + rr) * DD + n0;
        const float* ep = embed + (size_t)srow[rr] + n0;
#pragma unroll
        for (int j = 0; j < 16; j++) {
            const int c0 = half + j * 4;
            float4 e = *(const float4*)(ep + c0);
            float4 o;
            o.x = Tf[(c0 + 0) * 132 + rr] + e.x;
            o.y = Tf[(c0 + 1) * 132 + rr] + e.y;
            o.z = Tf[(c0 + 2) * 132 + rr] + e.z;
            o.w = Tf[(c0 + 3) * 132 + rr] + e.w;
            *(float4*)(g_x + gr + c0) = o;
        }
    }
#undef ISS2
}

// ---------------- K3: LayerNorm + slot_imp + query extraction ----------------
__global__ __launch_bounds__(256) void ln_kernel(
    const float* __restrict__ ln_g, const float* __restrict__ ln_b) {
    const int token = blockIdx.x;
    const int tid = threadIdx.x;
    const float4 x4 = *(const float4*)(g_x + (size_t)token * DD + tid * 4);
    float s = x4.x + x4.y + x4.z + x4.w;
    float sq = x4.x * x4.x + x4.y * x4.y + x4.z * x4.z + x4.w * x4.w;
    __shared__ float sh1[8], sh2[8];
    const int w = tid >> 5, l = tid & 31;
    s = warp_sum(s);
    sq = warp_sum(sq);
    if (l == 0) { sh1[w] = s; sh2[w] = sq; }
    __syncthreads();
    float ts = 0.f, tq = 0.f;
#pragma unroll
    for (int i = 0; i < 8; i++) { ts += sh1[i]; tq += sh2[i]; }
    const float mu = ts * (1.f / 1024.f);
    const float var = tq * (1.f / 1024.f) - mu * mu;
    const float rstd = rsqrtf(var + 1e-5f);
    const float4 g4 = *(const float4*)(ln_g + tid * 4);
    const float4 b4 = *(const float4*)(ln_b + tid * 4);
    float4 h4;
    h4.x = (x4.x - mu) * rstd * g4.x + b4.x;
    h4.y = (x4.y - mu) * rstd * g4.y + b4.y;
    h4.z = (x4.z - mu) * rstd * g4.z + b4.z;
    h4.w = (x4.w - mu) * rstd * g4.w + b4.w;
    *(float4*)(g_hidden + (size_t)token * DD + tid * 4) = h4;
    const float4 wb = *(const float4*)(g_wbar + tid * 4);
    float wd = h4.x * wb.x + h4.y * wb.y + h4.z * wb.z + h4.w * wb.w;
    wd = warp_sum(wd);
    __syncthreads();
    if (l == 0) sh1[w] = wd;
    __syncthreads();
    if (tid == 0) {
        float t2 = 0.f;
#pragma unroll
        for (int i = 0; i < 8; i++) t2 += sh1[i];
        g_slot[token] = t2;   // constant offset (mean wg_b) omitted: rank-invariant
    }
    if ((token & (TT - 1)) == TT - 1) {
        int bidx = token >> 9;
        *(float4*)(g_query + bidx * DD + tid * 4) = h4;
    }
}

// ---------------- K4: top-k selection + memory assembly ----------------
__global__ __launch_bounds__(256) void select_kernel(const float* __restrict__ memory) {
    const int b = blockIdx.x, tid = threadIdx.x;
    __shared__ float imp[512];
    __shared__ int idx[6];
    for (int t = tid; t < TT - 1; t += 256) imp[t] = g_slot[b * TT + t];
    __syncthreads();
    if (tid == 0) {
#pragma unroll
        for (int r = 0; r < 4; r++) {       // fwd top-4 (desc, stable)
            float best = -1e30f; int bi = 0;
            for (int t = 0; t < TT - 1; t++)
                if (imp[t] > best) { best = imp[t]; bi = t; }
            idx[r] = bi;
            imp[bi] = -3.0e38f;
        }
#pragma unroll
        for (int r = 0; r < 2; r++) {       // rev top-2 over first 8, masked
            float best = -1e30f; int bi = 0;
            for (int t = 0; t < 8; t++)
                if (imp[t] > best) { best = imp[t]; bi = t; }
            idx[4 + r] = bi;
            imp[bi] = -3.0e38f;
        }
    }
    __syncthreads();
    for (int s = 0; s < SS; s++) {
        const float* src = (s < 6)
            ? (g_hidden + (size_t)(b * TT + idx[s]) * DD)
            : (memory + (size_t)s * DD);
        *(float4*)(g_mem + (size_t)(b * SS + s) * DD + tid * 4) =
            *(const float4*)(src + tid * 4);
    }
}

// ---------------- vocab GEMM (tf32 mma): logits = Q @ out_w + out_b ----------------
// mode 0: Q=g_query -> g_dl ; mode 1: Q=g_ctx -> extout
// Tail: v0 clamped to VOCAB-128; overlap cols written twice with identical values.
__global__ __launch_bounds__(256) void vlogits_kernel(
    const float* __restrict__ W, const float* __restrict__ bias,
    float* __restrict__ extout, int mode) {
    __shared__ unsigned As[2][32 * APAD];
    __shared__ unsigned Bs[2][32 * BPAD];
    const float* __restrict__ Q = mode ? g_ctx : g_query;
    float* __restrict__ out = mode ? extout : g_dl;
    const int tid = threadIdx.x, warp = tid >> 5, lane = tid & 31;
    const int gid = lane >> 2, tg = lane & 3;
    const int wn = warp * 16;
    int v0 = blockIdx.x * 128;
    if (v0 > VOCAB - 128) v0 = VOCAB - 128;

    const int ar = tid >> 3, akq = tid & 7;
    const int bkr = warp, bc4 = lane * 4;

    float4 aR;
    float bR[16];

#define CLQ_LOAD(kt) do {                                                       \
        const int k0q = (kt) * 32;                                              \
        aR = *(const float4*)(Q + ar * DD + k0q + akq * 4);                     \
        _Pragma("unroll")                                                       \
        for (int o = 0; o < 4; o++) {                                           \
            const float* wp = W + (size_t)(k0q + bkr + o * 8) * VOCAB + v0 + bc4; \
            bR[o * 4 + 0] = wp[0]; bR[o * 4 + 1] = wp[1];                       \
            bR[o * 4 + 2] = wp[2]; bR[o * 4 + 3] = wp[3];                       \
        }                                                                       \
    } while (0)
#define CLQ_STORE(buf) do {                                                     \
        unsigned* Ad = As[buf]; unsigned* Bd = Bs[buf];                         \
        uint4 ta;                                                               \
        ta.x = __float_as_uint(aR.x); ta.y = __float_as_uint(aR.y);             \
        ta.z = __float_as_uint(aR.z); ta.w = __float_as_uint(aR.w);             \
        *(uint4*)&Ad[ar * APAD + akq * 4] = ta;                                 \
        _Pragma("unroll")                                                       \
        for (int o = 0; o < 4; o++) {                                           \
            uint4 tb;                                                           \
            tb.x = __float_as_uint(bR[o * 4 + 0]);                              \
            tb.y = __float_as_uint(bR[o * 4 + 1]);                              \
            tb.z = __float_as_uint(bR[o * 4 + 2]);                              \
            tb.w = __float_as_uint(bR[o * 4 + 3]);                              \
            *(uint4*)&Bd[(bkr + o * 8) * BPAD + bc4] = tb;                      \
        }                                                                       \
    } while (0)

    float acc[2][2][4];
#pragma unroll
    for (int mi = 0; mi < 2; mi++)
#pragma unroll
        for (int ni = 0; ni < 2; ni++)
#pragma unroll
            for (int r = 0; r < 4; r++) acc[mi][ni][r] = 0.f;

    CLQ_LOAD(0);
    CLQ_STORE(0);
    for (int kt = 0; kt < 32; kt++) {
        __syncthreads();
        if (kt + 1 < 32) CLQ_LOAD(kt + 1);
        const unsigned* Ab = As[kt & 1];
        const unsigned* Bb = Bs[kt & 1];
#pragma unroll
        for (int ks = 0; ks < 32; ks += 8) {
            unsigned a[2][4], b[2][2];
#pragma unroll
            for (int mi = 0; mi < 2; mi++) {
                int mb = (mi * 16 + gid) * APAD;
                a[mi][0] = f2tf(__uint_as_float(Ab[mb + ks + tg]));
                a[mi][1] = f2tf(__uint_as_float(Ab[mb + 8 * APAD + ks + tg]));
                a[mi][2] = f2tf(__uint_as_float(Ab[mb + ks + tg + 4]));
                a[mi][3] = f2tf(__uint_as_float(Ab[mb + 8 * APAD + ks + tg + 4]));
            }
#pragma unroll
            for (int ni = 0; ni < 2; ni++) {
                int c = wn + ni * 8 + gid;
                b[ni][0] = f2tf(__uint_as_float(Bb[(ks + tg) * BPAD + c]));
                b[ni][1] = f2tf(__uint_as_float(Bb[(ks + tg + 4) * BPAD + c]));
            }
#pragma unroll
            for (int mi = 0; mi < 2; mi++)
#pragma unroll
                for (int ni = 0; ni < 2; ni++)
                    mma_tf32(acc[mi][ni], a[mi][0], a[mi][1], a[mi][2], a[mi][3],
                             b[ni][0], b[ni][1]);
        }
        if (kt + 1 < 32) CLQ_STORE((kt + 1) & 1);
    }
#pragma unroll
    for (int mi = 0; mi < 2; mi++) {
        int m0 = mi * 16 + gid;
#pragma unroll
        for (int ni = 0; ni < 2; ni++) {
            int vc = v0 + wn + ni * 8 + 2 * tg;
            float bi0 = bias[vc], bi1 = bias[vc + 1];
            out[(size_t)m0 * VOCAB + vc]           = acc[mi][ni][0] + bi0;
            out[(size_t)m0 * VOCAB + vc + 1]       = acc[mi][ni][1] + bi1;
            out[(size_t)(m0 + 8) * VOCAB + vc]     = acc[mi][ni][2] + bi0;
            out[(size_t)(m0 + 8) * VOCAB + vc + 1] = acc[mi][ni][3] + bi1;
        }
    }
#undef CLQ_LOAD
#undef CLQ_STORE
}

// ---------------- K6: conf = 1/sumexp(direct_logits - max) -> use_mem flag ----------------
__global__ __launch_bounds__(256) void conf_kernel() {
    const int b = blockIdx.x, tid = threadIdx.x;
    const float* row = g_dl + (size_t)b * VOCAB;
    float m = -3.0e38f;
    for (int v = tid; v < VOCAB; v += 256) m = fmaxf(m, row[v]);
    __shared__ float sh[8];
#pragma unroll
    for (int o = 16; o > 0; o >>= 1) m = fmaxf(m, __shfl_xor_sync(0xffffffffu, m, o));
    if ((tid & 31) == 0) sh[tid >> 5] = m;
    __syncthreads();
    float bm = sh[0];
#pragma unroll
    for (int i = 1; i < 8; i++) bm = fmaxf(bm, sh[i]);
    float ssum = 0.f;
    for (int v = tid; v < VOCAB; v += 256) ssum += expf(row[v] - bm);
    ssum = warp_sum(ssum);
    __syncthreads();
    if ((tid & 31) == 0) sh[tid >> 5] = ssum;
    __syncthreads();
    if (tid == 0) {
        float t = 0.f;
#pragma unroll
        for (int i = 0; i < 8; i++) t += sh[i];
        const float conf = 1.f / t;
        g_use[b] = (conf < 0.8f) ? 1.f : 0.f;
    }
}

// ---------------- K7: q = query @ rp_w + rp_b ----------------
__global__ __launch_bounds__(256) void rp_kernel(
    const float* __restrict__ rp_w, const float* __restrict__ rp_b) {
    const int b = blockIdx.x, tid = threadIdx.x;
    __shared__ __align__(16) float qs[DD];
    *(float4*)&qs[tid * 4] = *(const float4*)(g_query + b * DD + tid * 4);
    __syncthreads();
    float acc0 = 0.f, acc1 = 0.f, acc2 = 0.f, acc3 = 0.f;
    for (int d = 0; d < DD; d++) {
        const float q = qs[d];
        const float* wr = rp_w + (size_t)d * DD + tid;
        acc0 += q * wr[0];
        acc1 += q * wr[256];
        acc2 += q * wr[512];
        acc3 += q * wr[768];
    }
    g_q[b * DD + tid +   0] = acc0 + rp_b[tid +   0];
    g_q[b * DD + tid + 256] = acc1 + rp_b[tid + 256];
    g_q[b * DD + tid + 512] = acc2 + rp_b[tid + 512];
    g_q[b * DD + tid + 768] = acc3 + rp_b[tid + 768];
}

// ---------------- K8: scores -> softmax -> ctx -> blend ----------------
__global__ __launch_bounds__(256) void attn_kernel() {
    const int b = blockIdx.x, tid = threadIdx.x;
    __shared__ __align__(16) float qs[DD];
    __shared__ float sh[8];
    __shared__ float scores[SS];
    __shared__ float attn[SS];
    *(float4*)&qs[tid * 4] = *(const float4*)(g_q + b * DD + tid * 4);
    __syncthreads();
    for (int s = 0; s < SS; s++) {
        const float4 m4 = *(const float4*)(g_mem + (size_t)(b * SS + s) * DD + tid * 4);
        const float4 q4 = *(const float4*)&qs[tid * 4];
        float p = m4.x * q4.x + m4.y * q4.y + m4.z * q4.z + m4.w * q4.w;
        p = warp_sum(p);
        if ((tid & 31) == 0) sh[tid >> 5] = p;
        __syncthreads();
        if (tid == 0) {
            float t = 0.f;
#pragma unroll
            for (int i = 0; i < 8; i++) t += sh[i];
            scores[s] = t;
        }
        __syncthreads();
    }
    if (tid == 0) {
        float m = scores[0];
        for (int s = 1; s < SS; s++) m = fmaxf(m, scores[s]);
        float sum = 0.f;
        for (int s = 0; s < SS; s++) { float e = expf(scores[s] - m); attn[s] = e; sum += e; }
        const float inv = 1.f / sum;
        for (int s = 0; s < SS; s++) attn[s] *= inv;
    }
    __syncthreads();
    float c0 = 0.f, c1 = 0.f, c2 = 0.f, c3 = 0.f;
#pragma unroll
    for (int s = 0; s < SS; s++) {
        const float a = attn[s];
        const float4 m4 = *(const float4*)(g_mem + (size_t)(b * SS + s) * DD + tid * 4);
        c0 += a * m4.x; c1 += a * m4.y; c2 += a * m4.z; c3 += a * m4.w;
    }
    const float use = g_use[b];
    const float4 qv = *(const float4*)(g_query + b * DD + tid * 4);
    float4 o;
    o.x = c0 * use + qv.x * (1.f - use);
    o.y = c1 * use + qv.y * (1.f - use);
    o.z = c2 * use + qv.z * (1.f - use);
    o.w = c3 * use + qv.w * (1.f - use);
    *(float4*)(g_ctx + b * DD + tid * 4) = o;
}

// ---------------- launch ----------------
extern "C" void kernel_launch(void* const* d_in, const int* in_sizes, int n_in,
                              void* d_out, int out_size) {
    const int*   seq    = (const int*)  d_in[0];
    const float* embed  = (const float*)d_in[1];
    const float* ff_w1  = (const float*)d_in[2];
    const float* ff_b1  = (const float*)d_in[3];
    const float* ff_w2  = (const float*)d_in[4];
    const float* ff_b2  = (const float*)d_in[5];
    const float* ln_g   = (const float*)d_in[6];
    const float* ln_b   = (const float*)d_in[7];
    const float* wg_w   = (const float*)d_in[8];
    // d_in[9] = wg_b: constant shift of slot_imp, rank-invariant -> unused
    const float* rp_w   = (const float*)d_in[10];
    const float* rp_b   = (const float*)d_in[11];
    const float* out_w  = (const float*)d_in[12];
    const float* out_b  = (const float*)d_in[13];
    const float* memory = (const float*)d_in[14];
    float* out = (float*)d_out;

    cudaFuncSetAttribute(gemm1_kernel, cudaFuncAttributeMaxDynamicSharedMemorySize, GSMEM_G);
    cudaFuncSetAttribute(gemm2_kernel, cudaFuncAttributeMaxDynamicSharedMemorySize, GSMEM_G);

    wbar_kernel<<<4, 256>>>(wg_w);
    prep_w1<<<(H2 / 8) * (DD / 16) * 32 / 256, 256>>>(ff_w1);   // 2048 blocks
    prep_w2<<<(DD / 8) * (H2 / 16) * 32 / 256, 256>>>(ff_w2);   // 2048 blocks
    prep_a<<<BT / 16, 256, 16 * PADW * 2>>>(seq, embed);
    gemm1_kernel<<<dim3(H2 / 128, BT / 128), 256, GSMEM_G>>>(ff_b1);
    gemm2_kernel<<<dim3(DD / 128, BT / 128), 256, GSMEM_G>>>(seq, embed, ff_b2);
    ln_kernel<<<BT, 256>>>(ln_g, ln_b);
    select_kernel<<<BB, 256>>>(memory);
    vlogits_kernel<<<(VOCAB + 127) / 128, 256>>>(out_w, out_b, nullptr, 0);
    conf_kernel<<<BB, 256>>>();
    rp_kernel<<<BB, 256>>>(rp_w, rp_b);
    attn_kernel<<<BB, 256>>>();
    vlogits_kernel<<<(VOCAB + 127) / 128, 256>>>(out_w, out_b, out, 1);
}